// round 4
// baseline (speedup 1.0000x reference)
#include <cuda_runtime.h>
#include <cuda_bf16.h>

#define N_NODES 100000
#define N_EDGES 3200000
#define K1 512      // in_dim * n_seq
#define H1 256
#define H2 128
#define ENDD 64

static_assert(N_NODES == 100000, "");

// ---------------- scratch (device globals; no allocation allowed) -----------
__device__ float g_H[(size_t)N_NODES * H1];   // GEMM outputs (256 wide L1, 128 wide L2)
__device__ float g_X[(size_t)N_NODES * H1];   // aggregated activations
__device__ int   g_deg_out[N_NODES];
__device__ int   g_deg_in[N_NODES];
__device__ float g_sout[N_NODES];
__device__ float g_sin[N_NODES];
__device__ int   g_rowptr[N_NODES + 1];
__device__ int   g_cursor[N_NODES];
__device__ int   g_colsrc[N_EDGES];
#define SCAN_BLOCKS ((N_NODES + 1023) / 1024)   // 98
__device__ int   g_part[128];
__device__ int   g_poff[128];

// ---------------- graph preprocessing ---------------------------------------
__global__ void zero_deg_kernel() {
    int i = blockIdx.x * blockDim.x + threadIdx.x;
    if (i < N_NODES) { g_deg_out[i] = 0; g_deg_in[i] = 0; }
}

__global__ void degree_kernel(const int* __restrict__ src, const int* __restrict__ dst) {
    for (int e = blockIdx.x * blockDim.x + threadIdx.x; e < N_EDGES;
         e += gridDim.x * blockDim.x) {
        atomicAdd(&g_deg_out[src[e]], 1);
        atomicAdd(&g_deg_in[dst[e]], 1);
    }
}

__global__ void scales_kernel() {
    int i = blockIdx.x * blockDim.x + threadIdx.x;
    if (i < N_NODES) {
        g_sout[i] = rsqrtf((float)max(g_deg_out[i], 1));
        g_sin[i]  = rsqrtf((float)max(g_deg_in[i], 1));
    }
}

__global__ void scan_block_kernel() {
    __shared__ int sh[1024];
    int t = threadIdx.x;
    int i = blockIdx.x * 1024 + t;
    int v = (i < N_NODES) ? g_deg_in[i] : 0;
    sh[t] = v;
    __syncthreads();
    for (int off = 1; off < 1024; off <<= 1) {
        int x = sh[t];
        int y = (t >= off) ? sh[t - off] : 0;
        __syncthreads();
        sh[t] = x + y;
        __syncthreads();
    }
    if (i < N_NODES) g_rowptr[i] = sh[t] - v;    // block-local exclusive
    if (t == 1023) g_part[blockIdx.x] = sh[1023];
}

__global__ void scan_part_kernel() {  // 1 block, 128 threads
    __shared__ int sh[128];
    int t = threadIdx.x;
    int v = (t < SCAN_BLOCKS) ? g_part[t] : 0;
    sh[t] = v;
    __syncthreads();
    for (int off = 1; off < 128; off <<= 1) {
        int x = sh[t];
        int y = (t >= off) ? sh[t - off] : 0;
        __syncthreads();
        sh[t] = x + y;
        __syncthreads();
    }
    g_poff[t] = sh[t] - v;   // exclusive
}

__global__ void scan_finish_kernel() {
    int i = blockIdx.x * blockDim.x + threadIdx.x;
    if (i < N_NODES) {
        int r = g_rowptr[i] + g_poff[i >> 10];
        g_rowptr[i] = r;
        g_cursor[i] = r;
    }
    if (i == 0) g_rowptr[N_NODES] = N_EDGES;
}

__global__ void csr_fill_kernel(const int* __restrict__ src, const int* __restrict__ dst) {
    for (int e = blockIdx.x * blockDim.x + threadIdx.x; e < N_EDGES;
         e += gridDim.x * blockDim.x) {
        int d = dst[e];
        int pos = atomicAdd(&g_cursor[d], 1);
        g_colsrc[pos] = src[e];
    }
}

// ---------------- row-scaled SGEMM: C = diag(rowscale) * A @ B --------------
// BM=128, BN=128, BK=8, TM=8, TN=8, 256 threads.  C is always g_H.
// If A_GLOBAL, A is g_X; otherwise the Aparam pointer.
template <bool A_GLOBAL>
__global__ __launch_bounds__(256)
void sgemm_rowscale(int M, int N, int K, const float* __restrict__ Aparam,
                    const float* __restrict__ B) {
    constexpr int BM = 128, BN = 128, BK = 8, TM = 8, TN = 8;
    __shared__ __align__(16) float As[BK][BM];
    __shared__ __align__(16) float Bs[BK][BN];

    const float* __restrict__ A = A_GLOBAL ? g_X : Aparam;
    float* __restrict__ C = g_H;

    const int tid = threadIdx.x;
    const int bm = blockIdx.y, bn = blockIdx.x;
    const int tr = tid / (BN / TN);   // 0..15
    const int tc = tid % (BN / TN);   // 0..15

    const int aRow = tid / (BK / 4);  // 0..127
    const int aC4  = tid % (BK / 4);  // 0..1
    const int bRow = tid / (BN / 4);  // 0..7
    const int bC4  = tid % (BN / 4);  // 0..31

    const int grow = bm * BM + aRow;
    const bool arow_ok = (grow < M);
    const float sc = arow_ok ? g_sout[grow] : 0.f;
    const float4* __restrict__ Av =
        (const float4*)(A + (size_t)grow * K);

    float acc[TM][TN];
#pragma unroll
    for (int i = 0; i < TM; i++)
#pragma unroll
        for (int j = 0; j < TN; j++) acc[i][j] = 0.f;

    for (int k0 = 0; k0 < K; k0 += BK) {
        float4 av = make_float4(0.f, 0.f, 0.f, 0.f);
        if (arow_ok) av = Av[k0 / 4 + aC4];
        As[aC4 * 4 + 0][aRow] = av.x * sc;
        As[aC4 * 4 + 1][aRow] = av.y * sc;
        As[aC4 * 4 + 2][aRow] = av.z * sc;
        As[aC4 * 4 + 3][aRow] = av.w * sc;

        float4 bv = *(const float4*)(B + (size_t)(k0 + bRow) * N + bn * BN + bC4 * 4);
        *(float4*)&Bs[bRow][bC4 * 4] = bv;
        __syncthreads();

#pragma unroll
        for (int k = 0; k < BK; k++) {
            float ra[TM], rb[TN];
            *(float4*)&ra[0] = *(const float4*)&As[k][tr * TM];
            *(float4*)&ra[4] = *(const float4*)&As[k][tr * TM + 4];
            *(float4*)&rb[0] = *(const float4*)&Bs[k][tc * TN];
            *(float4*)&rb[4] = *(const float4*)&Bs[k][tc * TN + 4];
#pragma unroll
            for (int i = 0; i < TM; i++)
#pragma unroll
                for (int j = 0; j < TN; j++)
                    acc[i][j] = fmaf(ra[i], rb[j], acc[i][j]);
        }
        __syncthreads();
    }

#pragma unroll
    for (int i = 0; i < TM; i++) {
        int r = bm * BM + tr * TM + i;
        if (r < M) {
            float* cp = C + (size_t)r * N + bn * BN + tc * TN;
            *(float4*)cp       = make_float4(acc[i][0], acc[i][1], acc[i][2], acc[i][3]);
            *(float4*)(cp + 4) = make_float4(acc[i][4], acc[i][5], acc[i][6], acc[i][7]);
        }
    }
}

// ---------------- pull-based aggregation (atomic-free) ----------------------
// one block (128 threads) per destination node; reads g_H, writes g_X.
template <int COLS, bool RELU>
__global__ __launch_bounds__(128)
void aggregate_kernel(const float* __restrict__ bias) {
    const int v = blockIdx.x;
    const int t = threadIdx.x;
    constexpr int CP = COLS / 128;

    float acc[CP];
#pragma unroll
    for (int c = 0; c < CP; c++) acc[c] = 0.f;

    const int beg = g_rowptr[v];
    const int end = g_rowptr[v + 1];
    const float* __restrict__ Hm = g_H;

    int e = beg;
    for (; e + 3 < end; e += 4) {
        int s0 = g_colsrc[e + 0], s1 = g_colsrc[e + 1];
        int s2 = g_colsrc[e + 2], s3 = g_colsrc[e + 3];
        const float* r0 = Hm + (size_t)s0 * COLS;
        const float* r1 = Hm + (size_t)s1 * COLS;
        const float* r2 = Hm + (size_t)s2 * COLS;
        const float* r3 = Hm + (size_t)s3 * COLS;
#pragma unroll
        for (int c = 0; c < CP; c++) {
            acc[c] += r0[t + 128 * c];
            acc[c] += r1[t + 128 * c];
            acc[c] += r2[t + 128 * c];
            acc[c] += r3[t + 128 * c];
        }
    }
    for (; e < end; e++) {
        int s = g_colsrc[e];
        const float* r = Hm + (size_t)s * COLS;
#pragma unroll
        for (int c = 0; c < CP; c++) acc[c] += r[t + 128 * c];
    }

    const float si = g_sin[v];
#pragma unroll
    for (int c = 0; c < CP; c++) {
        float val = fmaf(acc[c], si, bias[t + 128 * c]);
        if (RELU) val = fmaxf(val, 0.f);
        g_X[(size_t)v * COLS + t + 128 * c] = val;
    }
}

// ---------------- output head: relu(x@Wo1+bo1)@Wo2+bo2 ----------------------
__global__ __launch_bounds__(256)
void head_kernel(const float* __restrict__ Wo1, const float* __restrict__ bo1,
                 const float* __restrict__ Wo2, const float* __restrict__ bo2,
                 float* __restrict__ out) {
    __shared__ __align__(16) float sW1[H2 * ENDD];   // 32 KB
    __shared__ float sb1[ENDD], sW2[ENDD];
    __shared__ float sx[8][H2];

    const int tid = threadIdx.x;
    for (int i = tid; i < H2 * ENDD; i += 256) sW1[i] = Wo1[i];
    if (tid < ENDD) { sb1[tid] = bo1[tid]; sW2[tid] = Wo2[tid]; }
    __syncthreads();

    const float bout = bo2[0];
    const int warp = tid >> 5, lane = tid & 31;

    for (int v = blockIdx.x * 8 + warp; v < N_NODES; v += gridDim.x * 8) {
        const float* xr = g_X + (size_t)v * H2;
#pragma unroll
        for (int q = 0; q < 4; q++) sx[warp][lane + 32 * q] = xr[lane + 32 * q];
        __syncwarp();

        float h0 = sb1[lane], h1 = sb1[lane + 32];
#pragma unroll 8
        for (int k = 0; k < H2; k++) {
            float xk = sx[warp][k];
            h0 = fmaf(xk, sW1[k * ENDD + lane], h0);
            h1 = fmaf(xk, sW1[k * ENDD + lane + 32], h1);
        }
        h0 = fmaxf(h0, 0.f);
        h1 = fmaxf(h1, 0.f);
        float p = h0 * sW2[lane] + h1 * sW2[lane + 32];
#pragma unroll
        for (int off = 16; off; off >>= 1) p += __shfl_down_sync(0xffffffffu, p, off);
        if (lane == 0) out[v] = p + bout;
        __syncwarp();
    }
}

// ---------------- launch -----------------------------------------------------
extern "C" void kernel_launch(void* const* d_in, const int* in_sizes, int n_in,
                              void* d_out, int out_size) {
    const float* feat = (const float*)d_in[0];   // [N, 64, 8] -> [N, 512]
    const int*   src  = (const int*)d_in[1];
    const int*   dst  = (const int*)d_in[2];
    const float* W1   = (const float*)d_in[3];
    const float* b1   = (const float*)d_in[4];
    const float* W2   = (const float*)d_in[5];
    const float* b2   = (const float*)d_in[6];
    const float* Wo1  = (const float*)d_in[7];
    const float* bo1  = (const float*)d_in[8];
    const float* Wo2  = (const float*)d_in[9];
    const float* bo2  = (const float*)d_in[10];
    float* out = (float*)d_out;

    const int nb_nodes = (N_NODES + 255) / 256;

    // graph preprocessing: degrees, scales, CSR-by-dst
    zero_deg_kernel<<<nb_nodes, 256>>>();
    degree_kernel<<<2048, 256>>>(src, dst);
    scales_kernel<<<nb_nodes, 256>>>();
    scan_block_kernel<<<SCAN_BLOCKS, 1024>>>();
    scan_part_kernel<<<1, 128>>>();
    scan_finish_kernel<<<nb_nodes, 256>>>();
    csr_fill_kernel<<<2048, 256>>>(src, dst);

    // layer 1: H = (sout * X) @ W1 ; X2 = relu(sin * agg(H) + b1)
    {
        dim3 grid(H1 / 128, (N_NODES + 127) / 128);
        sgemm_rowscale<false><<<grid, 256>>>(N_NODES, H1, K1, feat, W1);
    }
    aggregate_kernel<H1, true><<<N_NODES, 128>>>(b1);

    // layer 2: H = (sout * X2) @ W2 ; X3 = sin * agg(H) + b2
    {
        dim3 grid(H2 / 128, (N_NODES + 127) / 128);
        sgemm_rowscale<true><<<grid, 256>>>(N_NODES, H2, H1, nullptr, W2);
    }
    aggregate_kernel<H2, false><<<N_NODES, 128>>>(b2);

    // head
    head_kernel<<<296, 256>>>(Wo1, bo1, Wo2, bo2, out);
}

// round 6
// speedup vs baseline: 1.4913x; 1.4913x over previous
#include <cuda_runtime.h>
#include <cuda_bf16.h>
#include <cstdint>

#define N_NODES 100000
#define N_EDGES 3200000
#define K1 512      // in_dim * n_seq
#define H1 256
#define H2 128
#define ENDD 64

// ---------------- scratch (device globals; no allocation allowed) -----------
__device__ float g_H[(size_t)N_NODES * H1];   // GEMM outputs
__device__ float g_X[(size_t)N_NODES * H1];   // aggregated activations
__device__ int   g_deg_out[N_NODES];
__device__ int   g_deg_in[N_NODES];
__device__ float g_sout[N_NODES];
__device__ float g_sin[N_NODES];
__device__ int   g_rowptr[N_NODES + 1];
__device__ int   g_cursor[N_NODES];
__device__ int   g_colsrc[N_EDGES];
#define SCAN_BLOCKS ((N_NODES + 1023) / 1024)   // 98
__device__ int   g_part[128];
__device__ int   g_poff[128];
// transposed + bf16-split weights: Wt[n][k]
__device__ __nv_bfloat16 g_W1t_hi[H1 * K1];
__device__ __nv_bfloat16 g_W1t_lo[H1 * K1];
__device__ __nv_bfloat16 g_W2t_hi[H2 * H1];
__device__ __nv_bfloat16 g_W2t_lo[H2 * H1];

// ---------------- PTX helpers ------------------------------------------------
__device__ __forceinline__ uint32_t smem_u32(const void* p) {
    uint32_t a;
    asm("{ .reg .u64 t; cvta.to.shared.u64 t, %1; cvt.u32.u64 %0, t; }"
        : "=r"(a) : "l"(p));
    return a;
}

__device__ __forceinline__ void ldsm_x4(uint32_t (&r)[4], uint32_t a) {
    asm volatile("ldmatrix.sync.aligned.m8n8.x4.shared.b16 {%0,%1,%2,%3}, [%4];"
                 : "=r"(r[0]), "=r"(r[1]), "=r"(r[2]), "=r"(r[3]) : "r"(a));
}

__device__ __forceinline__ void ldsm_x2(uint32_t (&r)[2], uint32_t a) {
    asm volatile("ldmatrix.sync.aligned.m8n8.x2.shared.b16 {%0,%1}, [%2];"
                 : "=r"(r[0]), "=r"(r[1]) : "r"(a));
}

__device__ __forceinline__ void mma_bf16(float (&d)[4], const uint32_t (&a)[4],
                                         const uint32_t (&b)[2]) {
    asm volatile(
        "mma.sync.aligned.m16n8k16.row.col.f32.bf16.bf16.f32 "
        "{%0,%1,%2,%3}, {%4,%5,%6,%7}, {%8,%9}, {%0,%1,%2,%3};"
        : "+f"(d[0]), "+f"(d[1]), "+f"(d[2]), "+f"(d[3])
        : "r"(a[0]), "r"(a[1]), "r"(a[2]), "r"(a[3]), "r"(b[0]), "r"(b[1]));
}

// ---------------- graph preprocessing ---------------------------------------
__global__ void zero_deg_kernel() {
    int i = blockIdx.x * blockDim.x + threadIdx.x;
    if (i < N_NODES) { g_deg_out[i] = 0; g_deg_in[i] = 0; }
}

__global__ void degree_kernel(const int* __restrict__ src, const int* __restrict__ dst) {
    for (int e = blockIdx.x * blockDim.x + threadIdx.x; e < N_EDGES;
         e += gridDim.x * blockDim.x) {
        atomicAdd(&g_deg_out[src[e]], 1);
        atomicAdd(&g_deg_in[dst[e]], 1);
    }
}

__global__ void scales_kernel() {
    int i = blockIdx.x * blockDim.x + threadIdx.x;
    if (i < N_NODES) {
        g_sout[i] = rsqrtf((float)max(g_deg_out[i], 1));
        g_sin[i]  = rsqrtf((float)max(g_deg_in[i], 1));
    }
}

__global__ void scan_block_kernel() {
    __shared__ int sh[1024];
    int t = threadIdx.x;
    int i = blockIdx.x * 1024 + t;
    int v = (i < N_NODES) ? g_deg_in[i] : 0;
    sh[t] = v;
    __syncthreads();
    for (int off = 1; off < 1024; off <<= 1) {
        int x = sh[t];
        int y = (t >= off) ? sh[t - off] : 0;
        __syncthreads();
        sh[t] = x + y;
        __syncthreads();
    }
    if (i < N_NODES) g_rowptr[i] = sh[t] - v;
    if (t == 1023) g_part[blockIdx.x] = sh[1023];
}

__global__ void scan_part_kernel() {
    __shared__ int sh[128];
    int t = threadIdx.x;
    int v = (t < SCAN_BLOCKS) ? g_part[t] : 0;
    sh[t] = v;
    __syncthreads();
    for (int off = 1; off < 128; off <<= 1) {
        int x = sh[t];
        int y = (t >= off) ? sh[t - off] : 0;
        __syncthreads();
        sh[t] = x + y;
        __syncthreads();
    }
    g_poff[t] = sh[t] - v;
}

__global__ void scan_finish_kernel() {
    int i = blockIdx.x * blockDim.x + threadIdx.x;
    if (i < N_NODES) {
        int r = g_rowptr[i] + g_poff[i >> 10];
        g_rowptr[i] = r;
        g_cursor[i] = r;
    }
    if (i == 0) g_rowptr[N_NODES] = N_EDGES;
}

__global__ void csr_fill_kernel(const int* __restrict__ src, const int* __restrict__ dst) {
    for (int e = blockIdx.x * blockDim.x + threadIdx.x; e < N_EDGES;
         e += gridDim.x * blockDim.x) {
        int d = dst[e];
        int pos = atomicAdd(&g_cursor[d], 1);
        g_colsrc[pos] = src[e];
    }
}

// ------- weight transpose + bf16 split: W[K][N] -> Wt_hi/lo[N][K] -----------
__global__ void wsplit_kernel(const float* __restrict__ W, __nv_bfloat16* __restrict__ Th,
                              __nv_bfloat16* __restrict__ Tl, int K, int N) {
    int i = blockIdx.x * blockDim.x + threadIdx.x;
    if (i < K * N) {
        int k = i / N, n = i % N;
        float v = W[i];
        __nv_bfloat16 h = __float2bfloat16(v);
        __nv_bfloat16 l = __float2bfloat16(v - __bfloat162float(h));
        Th[(size_t)n * K + k] = h;
        Tl[(size_t)n * K + k] = l;
    }
}

// ---------------- bf16x3 tensor-core GEMM -----------------------------------
// g_H = diag(g_sout) * A @ Wt^T   with D = Ahi*Bhi + Ahi*Blo + Alo*Bhi.
// BM=128, BN=128, BK=32, 8 warps (2m x 4n), warp tile 64x32, mma.m16n8k16 bf16.
template <int NC, int KT, bool A_GLOBAL>
__global__ __launch_bounds__(256, 2)
void gemm_bf16x3(const float* __restrict__ Aparam,
                 const __nv_bfloat16* __restrict__ Bh,
                 const __nv_bfloat16* __restrict__ Bl, int M) {
    constexpr int BK = 32, PAD = 40;   // 40*2=80B row stride: conflict-free ldmatrix
    __shared__ __align__(16) __nv_bfloat16 Ah[128 * PAD];
    __shared__ __align__(16) __nv_bfloat16 Al[128 * PAD];
    __shared__ __align__(16) __nv_bfloat16 Bhs[128 * PAD];
    __shared__ __align__(16) __nv_bfloat16 Bls[128 * PAD];

    const int tid = threadIdx.x;
    const int lane = tid & 31, warp = tid >> 5;
    const int wm = warp >> 2, wn = warp & 3;     // 2 x 4 warp grid
    const int bn = blockIdx.x, bm = blockIdx.y;
    const float* __restrict__ A = A_GLOBAL ? g_X : Aparam;

    float c[4][4][4];
#pragma unroll
    for (int mi = 0; mi < 4; mi++)
#pragma unroll
        for (int ni = 0; ni < 4; ni++)
#pragma unroll
            for (int q = 0; q < 4; q++) c[mi][ni][q] = 0.f;

    const uint32_t sAh = smem_u32(Ah), sAl = smem_u32(Al);
    const uint32_t sBh = smem_u32(Bhs), sBl = smem_u32(Bls);

    const int kiters = KT / BK;
    for (int kt = 0; kt < kiters; kt++) {
        const int k0 = kt * BK;

        // ---- A tile: 128x32 fp32, rowscale + bf16 hi/lo split ----
#pragma unroll
        for (int q = 0; q < 4; q++) {
            const int idx = q * 256 + tid;
            const int row = idx >> 3, f4 = idx & 7;
            const int grow = bm * 128 + row;
            float4 v = make_float4(0.f, 0.f, 0.f, 0.f);
            float sc = 0.f;
            if (grow < M) {
                sc = g_sout[grow];
                v = *(const float4*)(A + (size_t)grow * KT + k0 + f4 * 4);
            }
            v.x *= sc; v.y *= sc; v.z *= sc; v.w *= sc;
            __nv_bfloat16 h0 = __float2bfloat16(v.x), h1 = __float2bfloat16(v.y);
            __nv_bfloat16 h2 = __float2bfloat16(v.z), h3 = __float2bfloat16(v.w);
            __nv_bfloat16 l0 = __float2bfloat16(v.x - __bfloat162float(h0));
            __nv_bfloat16 l1 = __float2bfloat16(v.y - __bfloat162float(h1));
            __nv_bfloat16 l2 = __float2bfloat16(v.z - __bfloat162float(h2));
            __nv_bfloat16 l3 = __float2bfloat16(v.w - __bfloat162float(h3));
            const int off = row * PAD + f4 * 4;
            *(__nv_bfloat162*)&Ah[off]     = __halves2bfloat162(h0, h1);
            *(__nv_bfloat162*)&Ah[off + 2] = __halves2bfloat162(h2, h3);
            *(__nv_bfloat162*)&Al[off]     = __halves2bfloat162(l0, l1);
            *(__nv_bfloat162*)&Al[off + 2] = __halves2bfloat162(l2, l3);
        }

        // ---- B tile: 128x32 bf16 hi/lo straight copy (pre-split weights) ----
#pragma unroll
        for (int q = 0; q < 2; q++) {
            const int idx = q * 256 + tid;
            const int row = idx >> 2, c16 = idx & 3;
            const int gn = bn * 128 + row;          // NC is a multiple of 128
            const uint4 vh = *(const uint4*)(Bh + (size_t)gn * KT + k0 + c16 * 8);
            const uint4 vl = *(const uint4*)(Bl + (size_t)gn * KT + k0 + c16 * 8);
            *(uint4*)&Bhs[row * PAD + c16 * 8] = vh;
            *(uint4*)&Bls[row * PAD + c16 * 8] = vl;
        }
        __syncthreads();

        // ---- compute: 2 k-steps of 16, 3 MMA combos each ----
#pragma unroll
        for (int kk = 0; kk < 2; kk++) {
            const int kc = kk * 16;
            const int l16 = lane & 15;
            uint32_t bhf[4][2], blf[4][2];
#pragma unroll
            for (int ni = 0; ni < 4; ni++) {
                const uint32_t boff =
                    (uint32_t)((wn * 32 + ni * 8 + (l16 & 7)) * PAD + kc + (l16 >> 3) * 8) * 2u;
                ldsm_x2(bhf[ni], sBh + boff);
                ldsm_x2(blf[ni], sBl + boff);
            }
#pragma unroll
            for (int mi = 0; mi < 4; mi++) {
                const uint32_t aoff =
                    (uint32_t)((wm * 64 + mi * 16 + (lane & 15)) * PAD + kc + (lane >> 4) * 8) * 2u;
                uint32_t ahf[4], alf[4];
                ldsm_x4(ahf, sAh + aoff);
                ldsm_x4(alf, sAl + aoff);
#pragma unroll
                for (int ni = 0; ni < 4; ni++) {
                    mma_bf16(c[mi][ni], ahf, bhf[ni]);
                    mma_bf16(c[mi][ni], ahf, blf[ni]);
                    mma_bf16(c[mi][ni], alf, bhf[ni]);
                }
            }
        }
        __syncthreads();
    }

    // ---- epilogue ----
#pragma unroll
    for (int mi = 0; mi < 4; mi++) {
        const int r0 = bm * 128 + wm * 64 + mi * 16 + (lane >> 2);
#pragma unroll
        for (int ni = 0; ni < 4; ni++) {
            const int col = bn * 128 + wn * 32 + ni * 8 + 2 * (lane & 3);
            if (r0 < M)
                *(float2*)(g_H + (size_t)r0 * NC + col) = make_float2(c[mi][ni][0], c[mi][ni][1]);
            if (r0 + 8 < M)
                *(float2*)(g_H + (size_t)(r0 + 8) * NC + col) = make_float2(c[mi][ni][2], c[mi][ni][3]);
        }
    }
}

// ---------------- pull-based aggregation (atomic-free) ----------------------
template <int COLS, bool RELU>
__global__ __launch_bounds__(128)
void aggregate_kernel(const float* __restrict__ bias) {
    const int v = blockIdx.x;
    const int t = threadIdx.x;
    constexpr int CP = COLS / 128;

    float acc[CP];
#pragma unroll
    for (int c = 0; c < CP; c++) acc[c] = 0.f;

    const int beg = g_rowptr[v];
    const int end = g_rowptr[v + 1];
    const float* __restrict__ Hm = g_H;

    int e = beg;
    for (; e + 3 < end; e += 4) {
        int s0 = g_colsrc[e + 0], s1 = g_colsrc[e + 1];
        int s2 = g_colsrc[e + 2], s3 = g_colsrc[e + 3];
        const float* r0 = Hm + (size_t)s0 * COLS;
        const float* r1 = Hm + (size_t)s1 * COLS;
        const float* r2 = Hm + (size_t)s2 * COLS;
        const float* r3 = Hm + (size_t)s3 * COLS;
#pragma unroll
        for (int c = 0; c < CP; c++) {
            acc[c] += r0[t + 128 * c];
            acc[c] += r1[t + 128 * c];
            acc[c] += r2[t + 128 * c];
            acc[c] += r3[t + 128 * c];
        }
    }
    for (; e < end; e++) {
        int s = g_colsrc[e];
        const float* r = Hm + (size_t)s * COLS;
#pragma unroll
        for (int c = 0; c < CP; c++) acc[c] += r[t + 128 * c];
    }

    const float si = g_sin[v];
#pragma unroll
    for (int c = 0; c < CP; c++) {
        float val = fmaf(acc[c], si, bias[t + 128 * c]);
        if (RELU) val = fmaxf(val, 0.f);
        g_X[(size_t)v * COLS + t + 128 * c] = val;
    }
}

// ---------------- output head: relu(x@Wo1+bo1)@Wo2+bo2 ----------------------
__global__ __launch_bounds__(256)
void head_kernel(const float* __restrict__ Wo1, const float* __restrict__ bo1,
                 const float* __restrict__ Wo2, const float* __restrict__ bo2,
                 float* __restrict__ out) {
    __shared__ __align__(16) float sW1[H2 * ENDD];
    __shared__ float sb1[ENDD], sW2[ENDD];
    __shared__ float sx[8][H2];

    const int tid = threadIdx.x;
    for (int i = tid; i < H2 * ENDD; i += 256) sW1[i] = Wo1[i];
    if (tid < ENDD) { sb1[tid] = bo1[tid]; sW2[tid] = Wo2[tid]; }
    __syncthreads();

    const float bout = bo2[0];
    const int warp = tid >> 5, lane = tid & 31;

    for (int v = blockIdx.x * 8 + warp; v < N_NODES; v += gridDim.x * 8) {
        const float* xr = g_X + (size_t)v * H2;
#pragma unroll
        for (int q = 0; q < 4; q++) sx[warp][lane + 32 * q] = xr[lane + 32 * q];
        __syncwarp();

        float h0 = sb1[lane], h1 = sb1[lane + 32];
#pragma unroll 8
        for (int k = 0; k < H2; k++) {
            float xk = sx[warp][k];
            h0 = fmaf(xk, sW1[k * ENDD + lane], h0);
            h1 = fmaf(xk, sW1[k * ENDD + lane + 32], h1);
        }
        h0 = fmaxf(h0, 0.f);
        h1 = fmaxf(h1, 0.f);
        float p = h0 * sW2[lane] + h1 * sW2[lane + 32];
#pragma unroll
        for (int off = 16; off; off >>= 1) p += __shfl_down_sync(0xffffffffu, p, off);
        if (lane == 0) out[v] = p + bout;
        __syncwarp();
    }
}

// ---------------- launch -----------------------------------------------------
extern "C" void kernel_launch(void* const* d_in, const int* in_sizes, int n_in,
                              void* d_out, int out_size) {
    const float* feat = (const float*)d_in[0];   // [N, 64, 8] -> [N, 512]
    const int*   src  = (const int*)d_in[1];
    const int*   dst  = (const int*)d_in[2];
    const float* W1   = (const float*)d_in[3];
    const float* b1   = (const float*)d_in[4];
    const float* W2   = (const float*)d_in[5];
    const float* b2   = (const float*)d_in[6];
    const float* Wo1  = (const float*)d_in[7];
    const float* bo1  = (const float*)d_in[8];
    const float* Wo2  = (const float*)d_in[9];
    const float* bo2  = (const float*)d_in[10];
    float* out = (float*)d_out;

    const int nb_nodes = (N_NODES + 255) / 256;
    const int mtiles = (N_NODES + 127) / 128;   // 782

    __nv_bfloat16 *t1h, *t1l, *t2h, *t2l;
    cudaGetSymbolAddress((void**)&t1h, g_W1t_hi);
    cudaGetSymbolAddress((void**)&t1l, g_W1t_lo);
    cudaGetSymbolAddress((void**)&t2h, g_W2t_hi);
    cudaGetSymbolAddress((void**)&t2l, g_W2t_lo);

    // graph preprocessing: degrees, scales, CSR-by-dst; weight transpose/split
    zero_deg_kernel<<<nb_nodes, 256>>>();
    degree_kernel<<<2048, 256>>>(src, dst);
    scales_kernel<<<nb_nodes, 256>>>();
    scan_block_kernel<<<SCAN_BLOCKS, 1024>>>();
    scan_part_kernel<<<1, 128>>>();
    scan_finish_kernel<<<nb_nodes, 256>>>();
    csr_fill_kernel<<<2048, 256>>>(src, dst);
    wsplit_kernel<<<(K1 * H1 + 255) / 256, 256>>>(W1, t1h, t1l, K1, H1);
    wsplit_kernel<<<(H1 * H2 + 255) / 256, 256>>>(W2, t2h, t2l, H1, H2);

    // layer 1: H = (sout * X) @ W1 ; X2 = relu(sin * agg(H) + b1)
    {
        dim3 grid(H1 / 128, mtiles);
        gemm_bf16x3<H1, K1, false><<<grid, 256>>>(feat, t1h, t1l, N_NODES);
    }
    aggregate_kernel<H1, true><<<N_NODES, 128>>>(b1);

    // layer 2: H = (sout * X2) @ W2 ; X3 = sin * agg(H) + b2
    {
        dim3 grid(H2 / 128, mtiles);
        gemm_bf16x3<H2, H1, true><<<grid, 256>>>(nullptr, t2h, t2l, N_NODES);
    }
    aggregate_kernel<H2, false><<<N_NODES, 128>>>(b2);

    // head
    head_kernel<<<296, 256>>>(Wo1, bo1, Wo2, bo2, out);
}

// round 7
// speedup vs baseline: 1.7298x; 1.1599x over previous
#include <cuda_runtime.h>
#include <cuda_bf16.h>
#include <cuda_fp16.h>
#include <cstdint>

#define N_NODES 100000
#define N_EDGES 3200000
#define K1 512      // in_dim * n_seq
#define H1 256
#define H2 128
#define ENDD 64

// ---------------- scratch (device globals; no allocation allowed) -----------
__device__ __half g_Hh[(size_t)N_NODES * H1];  // GEMM outputs, fp16 (agg input)
__device__ float g_X[(size_t)N_NODES * H1];    // aggregated activations (fp32)
__device__ int   g_deg_out[N_NODES];
__device__ int   g_deg_in[N_NODES];
__device__ float g_sout[N_NODES];
__device__ float g_sin[N_NODES];
__device__ int   g_rowptr[N_NODES + 1];
__device__ int   g_cursor[N_NODES];
__device__ int   g_colsrc[N_EDGES];
#define SCAN_BLOCKS ((N_NODES + 1023) / 1024)   // 98
__device__ int   g_part[128];
__device__ int   g_poff[128];
// transposed + bf16-split weights: Wt[n][k]
__device__ __nv_bfloat16 g_W1t_hi[H1 * K1];
__device__ __nv_bfloat16 g_W1t_lo[H1 * K1];
__device__ __nv_bfloat16 g_W2t_hi[H2 * H1];
__device__ __nv_bfloat16 g_W2t_lo[H2 * H1];

// ---------------- PTX helpers ------------------------------------------------
__device__ __forceinline__ uint32_t smem_u32(const void* p) {
    uint32_t a;
    asm("{ .reg .u64 t; cvta.to.shared.u64 t, %1; cvt.u32.u64 %0, t; }"
        : "=r"(a) : "l"(p));
    return a;
}

__device__ __forceinline__ void ldsm_x4(uint32_t (&r)[4], uint32_t a) {
    asm volatile("ldmatrix.sync.aligned.m8n8.x4.shared.b16 {%0,%1,%2,%3}, [%4];"
                 : "=r"(r[0]), "=r"(r[1]), "=r"(r[2]), "=r"(r[3]) : "r"(a));
}

__device__ __forceinline__ void ldsm_x2(uint32_t (&r)[2], uint32_t a) {
    asm volatile("ldmatrix.sync.aligned.m8n8.x2.shared.b16 {%0,%1}, [%2];"
                 : "=r"(r[0]), "=r"(r[1]) : "r"(a));
}

__device__ __forceinline__ void mma_bf16(float (&d)[4], const uint32_t (&a)[4],
                                         const uint32_t (&b)[2]) {
    asm volatile(
        "mma.sync.aligned.m16n8k16.row.col.f32.bf16.bf16.f32 "
        "{%0,%1,%2,%3}, {%4,%5,%6,%7}, {%8,%9}, {%0,%1,%2,%3};"
        : "+f"(d[0]), "+f"(d[1]), "+f"(d[2]), "+f"(d[3])
        : "r"(a[0]), "r"(a[1]), "r"(a[2]), "r"(a[3]), "r"(b[0]), "r"(b[1]));
}

// ---------------- graph preprocessing ---------------------------------------
__global__ void zero_deg_kernel() {
    int i = blockIdx.x * blockDim.x + threadIdx.x;
    if (i < N_NODES) { g_deg_out[i] = 0; g_deg_in[i] = 0; }
}

__global__ void degree_kernel(const int* __restrict__ src, const int* __restrict__ dst) {
    for (int e = blockIdx.x * blockDim.x + threadIdx.x; e < N_EDGES;
         e += gridDim.x * blockDim.x) {
        atomicAdd(&g_deg_out[src[e]], 1);
        atomicAdd(&g_deg_in[dst[e]], 1);
    }
}

__global__ void scales_kernel() {
    int i = blockIdx.x * blockDim.x + threadIdx.x;
    if (i < N_NODES) {
        g_sout[i] = rsqrtf((float)max(g_deg_out[i], 1));
        g_sin[i]  = rsqrtf((float)max(g_deg_in[i], 1));
    }
}

__global__ void scan_block_kernel() {
    __shared__ int sh[1024];
    int t = threadIdx.x;
    int i = blockIdx.x * 1024 + t;
    int v = (i < N_NODES) ? g_deg_in[i] : 0;
    sh[t] = v;
    __syncthreads();
    for (int off = 1; off < 1024; off <<= 1) {
        int x = sh[t];
        int y = (t >= off) ? sh[t - off] : 0;
        __syncthreads();
        sh[t] = x + y;
        __syncthreads();
    }
    if (i < N_NODES) g_rowptr[i] = sh[t] - v;
    if (t == 1023) g_part[blockIdx.x] = sh[1023];
}

__global__ void scan_part_kernel() {
    __shared__ int sh[128];
    int t = threadIdx.x;
    int v = (t < SCAN_BLOCKS) ? g_part[t] : 0;
    sh[t] = v;
    __syncthreads();
    for (int off = 1; off < 128; off <<= 1) {
        int x = sh[t];
        int y = (t >= off) ? sh[t - off] : 0;
        __syncthreads();
        sh[t] = x + y;
        __syncthreads();
    }
    g_poff[t] = sh[t] - v;
}

__global__ void scan_finish_kernel() {
    int i = blockIdx.x * blockDim.x + threadIdx.x;
    if (i < N_NODES) {
        int r = g_rowptr[i] + g_poff[i >> 10];
        g_rowptr[i] = r;
        g_cursor[i] = r;
    }
    if (i == 0) g_rowptr[N_NODES] = N_EDGES;
}

__global__ void csr_fill_kernel(const int* __restrict__ src, const int* __restrict__ dst) {
    for (int e = blockIdx.x * blockDim.x + threadIdx.x; e < N_EDGES;
         e += gridDim.x * blockDim.x) {
        int d = dst[e];
        int pos = atomicAdd(&g_cursor[d], 1);
        g_colsrc[pos] = src[e];
    }
}

// ------- weight transpose + bf16 split: W[K][N] -> Wt_hi/lo[N][K] -----------
__global__ void wsplit_kernel(const float* __restrict__ W, __nv_bfloat16* __restrict__ Th,
                              __nv_bfloat16* __restrict__ Tl, int K, int N) {
    int i = blockIdx.x * blockDim.x + threadIdx.x;
    if (i < K * N) {
        int k = i / N, n = i % N;
        float v = W[i];
        __nv_bfloat16 h = __float2bfloat16(v);
        __nv_bfloat16 l = __float2bfloat16(v - __bfloat162float(h));
        Th[(size_t)n * K + k] = h;
        Tl[(size_t)n * K + k] = l;
    }
}

// ---------------- bf16x3 tensor-core GEMM -----------------------------------
// g_Hh = fp16( diag(g_sout) * A @ Wt^T )  with D = Ahi*Bhi + Ahi*Blo + Alo*Bhi.
// BM=128, BN=128, BK=32, 8 warps (2m x 4n), warp tile 64x32, mma.m16n8k16 bf16.
template <int NC, int KT, bool A_GLOBAL>
__global__ __launch_bounds__(256, 2)
void gemm_bf16x3(const float* __restrict__ Aparam,
                 const __nv_bfloat16* __restrict__ Bh,
                 const __nv_bfloat16* __restrict__ Bl, int M) {
    constexpr int BK = 32, PAD = 40;   // 40*2=80B row stride: conflict-free ldmatrix
    __shared__ __align__(16) __nv_bfloat16 Ah[128 * PAD];
    __shared__ __align__(16) __nv_bfloat16 Al[128 * PAD];
    __shared__ __align__(16) __nv_bfloat16 Bhs[128 * PAD];
    __shared__ __align__(16) __nv_bfloat16 Bls[128 * PAD];

    const int tid = threadIdx.x;
    const int lane = tid & 31, warp = tid >> 5;
    const int wm = warp >> 2, wn = warp & 3;     // 2 x 4 warp grid
    const int bn = blockIdx.x, bm = blockIdx.y;
    const float* __restrict__ A = A_GLOBAL ? g_X : Aparam;

    float c[4][4][4];
#pragma unroll
    for (int mi = 0; mi < 4; mi++)
#pragma unroll
        for (int ni = 0; ni < 4; ni++)
#pragma unroll
            for (int q = 0; q < 4; q++) c[mi][ni][q] = 0.f;

    const uint32_t sAh = smem_u32(Ah), sAl = smem_u32(Al);
    const uint32_t sBh = smem_u32(Bhs), sBl = smem_u32(Bls);

    const int kiters = KT / BK;
    for (int kt = 0; kt < kiters; kt++) {
        const int k0 = kt * BK;

        // ---- A tile: 128x32 fp32, rowscale + bf16 hi/lo split ----
#pragma unroll
        for (int q = 0; q < 4; q++) {
            const int idx = q * 256 + tid;
            const int row = idx >> 3, f4 = idx & 7;
            const int grow = bm * 128 + row;
            float4 v = make_float4(0.f, 0.f, 0.f, 0.f);
            float sc = 0.f;
            if (grow < M) {
                sc = g_sout[grow];
                v = *(const float4*)(A + (size_t)grow * KT + k0 + f4 * 4);
            }
            v.x *= sc; v.y *= sc; v.z *= sc; v.w *= sc;
            __nv_bfloat16 h0 = __float2bfloat16(v.x), h1 = __float2bfloat16(v.y);
            __nv_bfloat16 h2 = __float2bfloat16(v.z), h3 = __float2bfloat16(v.w);
            __nv_bfloat16 l0 = __float2bfloat16(v.x - __bfloat162float(h0));
            __nv_bfloat16 l1 = __float2bfloat16(v.y - __bfloat162float(h1));
            __nv_bfloat16 l2 = __float2bfloat16(v.z - __bfloat162float(h2));
            __nv_bfloat16 l3 = __float2bfloat16(v.w - __bfloat162float(h3));
            const int off = row * PAD + f4 * 4;
            *(__nv_bfloat162*)&Ah[off]     = __halves2bfloat162(h0, h1);
            *(__nv_bfloat162*)&Ah[off + 2] = __halves2bfloat162(h2, h3);
            *(__nv_bfloat162*)&Al[off]     = __halves2bfloat162(l0, l1);
            *(__nv_bfloat162*)&Al[off + 2] = __halves2bfloat162(l2, l3);
        }

        // ---- B tile: 128x32 bf16 hi/lo straight copy (pre-split weights) ----
#pragma unroll
        for (int q = 0; q < 2; q++) {
            const int idx = q * 256 + tid;
            const int row = idx >> 2, c16 = idx & 3;
            const int gn = bn * 128 + row;          // NC is a multiple of 128
            const uint4 vh = *(const uint4*)(Bh + (size_t)gn * KT + k0 + c16 * 8);
            const uint4 vl = *(const uint4*)(Bl + (size_t)gn * KT + k0 + c16 * 8);
            *(uint4*)&Bhs[row * PAD + c16 * 8] = vh;
            *(uint4*)&Bls[row * PAD + c16 * 8] = vl;
        }
        __syncthreads();

        // ---- compute: 2 k-steps of 16, 3 MMA combos each ----
#pragma unroll
        for (int kk = 0; kk < 2; kk++) {
            const int kc = kk * 16;
            const int l16 = lane & 15;
            uint32_t bhf[4][2], blf[4][2];
#pragma unroll
            for (int ni = 0; ni < 4; ni++) {
                const uint32_t boff =
                    (uint32_t)((wn * 32 + ni * 8 + (l16 & 7)) * PAD + kc + (l16 >> 3) * 8) * 2u;
                ldsm_x2(bhf[ni], sBh + boff);
                ldsm_x2(blf[ni], sBl + boff);
            }
#pragma unroll
            for (int mi = 0; mi < 4; mi++) {
                const uint32_t aoff =
                    (uint32_t)((wm * 64 + mi * 16 + (lane & 15)) * PAD + kc + (lane >> 4) * 8) * 2u;
                uint32_t ahf[4], alf[4];
                ldsm_x4(ahf, sAh + aoff);
                ldsm_x4(alf, sAl + aoff);
#pragma unroll
                for (int ni = 0; ni < 4; ni++) {
                    mma_bf16(c[mi][ni], ahf, bhf[ni]);
                    mma_bf16(c[mi][ni], ahf, blf[ni]);
                    mma_bf16(c[mi][ni], alf, bhf[ni]);
                }
            }
        }
        __syncthreads();
    }

    // ---- epilogue: fp32 accum -> fp16 store (half2) ----
#pragma unroll
    for (int mi = 0; mi < 4; mi++) {
        const int r0 = bm * 128 + wm * 64 + mi * 16 + (lane >> 2);
#pragma unroll
        for (int ni = 0; ni < 4; ni++) {
            const int col = bn * 128 + wn * 32 + ni * 8 + 2 * (lane & 3);
            if (r0 < M)
                *(__half2*)(g_Hh + (size_t)r0 * NC + col) =
                    __floats2half2_rn(c[mi][ni][0], c[mi][ni][1]);
            if (r0 + 8 < M)
                *(__half2*)(g_Hh + (size_t)(r0 + 8) * NC + col) =
                    __floats2half2_rn(c[mi][ni][2], c[mi][ni][3]);
        }
    }
}

// ---------------- pull-based aggregation (atomic-free, fp16 gather) ---------
// THREADS = COLS/2: each thread owns exactly one half2 (cols 2t, 2t+1).
template <int COLS, bool RELU>
__global__ __launch_bounds__(COLS / 2)
void aggregate_kernel(const float* __restrict__ bias) {
    const int v = blockIdx.x;
    const int t = threadIdx.x;
    constexpr int H2C = COLS / 2;

    float ax = 0.f, ay = 0.f;

    const int beg = g_rowptr[v];
    const int end = g_rowptr[v + 1];
    const __half2* __restrict__ Hm = (const __half2*)g_Hh;

    int e = beg;
    for (; e + 3 < end; e += 4) {
        int s0 = g_colsrc[e + 0], s1 = g_colsrc[e + 1];
        int s2 = g_colsrc[e + 2], s3 = g_colsrc[e + 3];
        float2 v0 = __half22float2(Hm[(size_t)s0 * H2C + t]);
        float2 v1 = __half22float2(Hm[(size_t)s1 * H2C + t]);
        float2 v2 = __half22float2(Hm[(size_t)s2 * H2C + t]);
        float2 v3 = __half22float2(Hm[(size_t)s3 * H2C + t]);
        ax += (v0.x + v1.x) + (v2.x + v3.x);
        ay += (v0.y + v1.y) + (v2.y + v3.y);
    }
    for (; e < end; e++) {
        int s = g_colsrc[e];
        float2 v0 = __half22float2(Hm[(size_t)s * H2C + t]);
        ax += v0.x;
        ay += v0.y;
    }

    const float si = g_sin[v];
    float2 b = *(const float2*)(bias + 2 * t);
    float ox = fmaf(ax, si, b.x);
    float oy = fmaf(ay, si, b.y);
    if (RELU) { ox = fmaxf(ox, 0.f); oy = fmaxf(oy, 0.f); }
    *(float2*)(g_X + (size_t)v * COLS + 2 * t) = make_float2(ox, oy);
}

// ---------------- output head: relu(x@Wo1+bo1)@Wo2+bo2 ----------------------
__global__ __launch_bounds__(256)
void head_kernel(const float* __restrict__ Wo1, const float* __restrict__ bo1,
                 const float* __restrict__ Wo2, const float* __restrict__ bo2,
                 float* __restrict__ out) {
    __shared__ __align__(16) float sW1[H2 * ENDD];
    __shared__ float sb1[ENDD], sW2[ENDD];
    __shared__ float sx[8][H2];

    const int tid = threadIdx.x;
    for (int i = tid; i < H2 * ENDD; i += 256) sW1[i] = Wo1[i];
    if (tid < ENDD) { sb1[tid] = bo1[tid]; sW2[tid] = Wo2[tid]; }
    __syncthreads();

    const float bout = bo2[0];
    const int warp = tid >> 5, lane = tid & 31;

    for (int v = blockIdx.x * 8 + warp; v < N_NODES; v += gridDim.x * 8) {
        const float* xr = g_X + (size_t)v * H2;
#pragma unroll
        for (int q = 0; q < 4; q++) sx[warp][lane + 32 * q] = xr[lane + 32 * q];
        __syncwarp();

        float h0 = sb1[lane], h1 = sb1[lane + 32];
#pragma unroll 8
        for (int k = 0; k < H2; k++) {
            float xk = sx[warp][k];
            h0 = fmaf(xk, sW1[k * ENDD + lane], h0);
            h1 = fmaf(xk, sW1[k * ENDD + lane + 32], h1);
        }
        h0 = fmaxf(h0, 0.f);
        h1 = fmaxf(h1, 0.f);
        float p = h0 * sW2[lane] + h1 * sW2[lane + 32];
#pragma unroll
        for (int off = 16; off; off >>= 1) p += __shfl_down_sync(0xffffffffu, p, off);
        if (lane == 0) out[v] = p + bout;
        __syncwarp();
    }
}

// ---------------- launch -----------------------------------------------------
extern "C" void kernel_launch(void* const* d_in, const int* in_sizes, int n_in,
                              void* d_out, int out_size) {
    const float* feat = (const float*)d_in[0];   // [N, 64, 8] -> [N, 512]
    const int*   src  = (const int*)d_in[1];
    const int*   dst  = (const int*)d_in[2];
    const float* W1   = (const float*)d_in[3];
    const float* b1   = (const float*)d_in[4];
    const float* W2   = (const float*)d_in[5];
    const float* b2   = (const float*)d_in[6];
    const float* Wo1  = (const float*)d_in[7];
    const float* bo1  = (const float*)d_in[8];
    const float* Wo2  = (const float*)d_in[9];
    const float* bo2  = (const float*)d_in[10];
    float* out = (float*)d_out;

    const int nb_nodes = (N_NODES + 255) / 256;
    const int mtiles = (N_NODES + 127) / 128;   // 782

    __nv_bfloat16 *t1h, *t1l, *t2h, *t2l;
    cudaGetSymbolAddress((void**)&t1h, g_W1t_hi);
    cudaGetSymbolAddress((void**)&t1l, g_W1t_lo);
    cudaGetSymbolAddress((void**)&t2h, g_W2t_hi);
    cudaGetSymbolAddress((void**)&t2l, g_W2t_lo);

    // graph preprocessing: degrees, scales, CSR-by-dst; weight transpose/split
    zero_deg_kernel<<<nb_nodes, 256>>>();
    degree_kernel<<<2048, 256>>>(src, dst);
    scales_kernel<<<nb_nodes, 256>>>();
    scan_block_kernel<<<SCAN_BLOCKS, 1024>>>();
    scan_part_kernel<<<1, 128>>>();
    scan_finish_kernel<<<nb_nodes, 256>>>();
    csr_fill_kernel<<<2048, 256>>>(src, dst);
    wsplit_kernel<<<(K1 * H1 + 255) / 256, 256>>>(W1, t1h, t1l, K1, H1);
    wsplit_kernel<<<(H1 * H2 + 255) / 256, 256>>>(W2, t2h, t2l, H1, H2);

    // layer 1: H = (sout * X) @ W1 ; X2 = relu(sin * agg(H) + b1)
    {
        dim3 grid(H1 / 128, mtiles);
        gemm_bf16x3<H1, K1, false><<<grid, 256>>>(feat, t1h, t1l, N_NODES);
    }
    aggregate_kernel<H1, true><<<N_NODES, H1 / 2>>>(b1);

    // layer 2: H = (sout * X2) @ W2 ; X3 = sin * agg(H) + b2
    {
        dim3 grid(H2 / 128, mtiles);
        gemm_bf16x3<H2, H1, true><<<grid, 256>>>(nullptr, t2h, t2l, N_NODES);
    }
    aggregate_kernel<H2, false><<<N_NODES, H2 / 2>>>(b2);

    // head
    head_kernel<<<296, 256>>>(Wo1, bo1, Wo2, bo2, out);
}

// round 8
// speedup vs baseline: 1.7848x; 1.0317x over previous
#include <cuda_runtime.h>
#include <cuda_bf16.h>
#include <cuda_fp16.h>
#include <cstdint>

#define N_NODES 100000
#define N_EDGES 3200000
#define K1 512      // in_dim * n_seq
#define H1 256
#define H2 128
#define ENDD 64

// ---------------- scratch (device globals; no allocation allowed) -----------
__device__ __half g_Hh[(size_t)N_NODES * H1];  // GEMM outputs, fp16 (agg input)
__device__ float g_X[(size_t)N_NODES * H1];    // aggregated activations (fp32)
__device__ int   g_deg_out[N_NODES];
__device__ int   g_deg_in[N_NODES];
__device__ float g_sout[N_NODES];
__device__ float g_sin[N_NODES];
__device__ int   g_rowptr[N_NODES + 1];
__device__ int   g_cursor[N_NODES];
__device__ int   g_colsrc[N_EDGES];
#define SCAN_BLOCKS ((N_NODES + 1023) / 1024)   // 98
__device__ int   g_part[128];
__device__ int   g_poff[128];
// transposed + bf16-split weights: Wt[n][k]
__device__ __nv_bfloat16 g_W1t_hi[H1 * K1];
__device__ __nv_bfloat16 g_W1t_lo[H1 * K1];
__device__ __nv_bfloat16 g_W2t_hi[H2 * H1];
__device__ __nv_bfloat16 g_W2t_lo[H2 * H1];

// ---------------- PTX helpers ------------------------------------------------
__device__ __forceinline__ uint32_t smem_u32(const void* p) {
    uint32_t a;
    asm("{ .reg .u64 t; cvta.to.shared.u64 t, %1; cvt.u32.u64 %0, t; }"
        : "=r"(a) : "l"(p));
    return a;
}

__device__ __forceinline__ void ldsm_x4(uint32_t (&r)[4], uint32_t a) {
    asm volatile("ldmatrix.sync.aligned.m8n8.x4.shared.b16 {%0,%1,%2,%3}, [%4];"
                 : "=r"(r[0]), "=r"(r[1]), "=r"(r[2]), "=r"(r[3]) : "r"(a));
}

__device__ __forceinline__ void ldsm_x2(uint32_t (&r)[2], uint32_t a) {
    asm volatile("ldmatrix.sync.aligned.m8n8.x2.shared.b16 {%0,%1}, [%2];"
                 : "=r"(r[0]), "=r"(r[1]) : "r"(a));
}

__device__ __forceinline__ void mma_bf16(float (&d)[4], const uint32_t (&a)[4],
                                         const uint32_t (&b)[2]) {
    asm volatile(
        "mma.sync.aligned.m16n8k16.row.col.f32.bf16.bf16.f32 "
        "{%0,%1,%2,%3}, {%4,%5,%6,%7}, {%8,%9}, {%0,%1,%2,%3};"
        : "+f"(d[0]), "+f"(d[1]), "+f"(d[2]), "+f"(d[3])
        : "r"(a[0]), "r"(a[1]), "r"(a[2]), "r"(a[3]), "r"(b[0]), "r"(b[1]));
}

__device__ __forceinline__ void cp_async16(uint32_t smem_dst, const void* gsrc,
                                           int src_bytes) {
    asm volatile("cp.async.cg.shared.global [%0], [%1], 16, %2;"
                 :: "r"(smem_dst), "l"(gsrc), "r"(src_bytes));
}
__device__ __forceinline__ void cp_commit() {
    asm volatile("cp.async.commit_group;");
}
__device__ __forceinline__ void cp_wait_all() {
    asm volatile("cp.async.wait_group 0;");
}

// ---------------- graph preprocessing ---------------------------------------
__global__ void zero_deg_kernel() {
    int i = blockIdx.x * blockDim.x + threadIdx.x;
    if (i < N_NODES) { g_deg_out[i] = 0; g_deg_in[i] = 0; }
}

__global__ void degree_kernel(const int* __restrict__ src, const int* __restrict__ dst) {
    for (int e = blockIdx.x * blockDim.x + threadIdx.x; e < N_EDGES;
         e += gridDim.x * blockDim.x) {
        atomicAdd(&g_deg_out[src[e]], 1);
        atomicAdd(&g_deg_in[dst[e]], 1);
    }
}

__global__ void scales_kernel() {
    int i = blockIdx.x * blockDim.x + threadIdx.x;
    if (i < N_NODES) {
        g_sout[i] = rsqrtf((float)max(g_deg_out[i], 1));
        g_sin[i]  = rsqrtf((float)max(g_deg_in[i], 1));
    }
}

__global__ void scan_block_kernel() {
    __shared__ int sh[1024];
    int t = threadIdx.x;
    int i = blockIdx.x * 1024 + t;
    int v = (i < N_NODES) ? g_deg_in[i] : 0;
    sh[t] = v;
    __syncthreads();
    for (int off = 1; off < 1024; off <<= 1) {
        int x = sh[t];
        int y = (t >= off) ? sh[t - off] : 0;
        __syncthreads();
        sh[t] = x + y;
        __syncthreads();
    }
    if (i < N_NODES) g_rowptr[i] = sh[t] - v;
    if (t == 1023) g_part[blockIdx.x] = sh[1023];
}

__global__ void scan_part_kernel() {
    __shared__ int sh[128];
    int t = threadIdx.x;
    int v = (t < SCAN_BLOCKS) ? g_part[t] : 0;
    sh[t] = v;
    __syncthreads();
    for (int off = 1; off < 128; off <<= 1) {
        int x = sh[t];
        int y = (t >= off) ? sh[t - off] : 0;
        __syncthreads();
        sh[t] = x + y;
        __syncthreads();
    }
    g_poff[t] = sh[t] - v;
}

__global__ void scan_finish_kernel() {
    int i = blockIdx.x * blockDim.x + threadIdx.x;
    if (i < N_NODES) {
        int r = g_rowptr[i] + g_poff[i >> 10];
        g_rowptr[i] = r;
        g_cursor[i] = r;
    }
    if (i == 0) g_rowptr[N_NODES] = N_EDGES;
}

__global__ void csr_fill_kernel(const int* __restrict__ src, const int* __restrict__ dst) {
    for (int e = blockIdx.x * blockDim.x + threadIdx.x; e < N_EDGES;
         e += gridDim.x * blockDim.x) {
        int d = dst[e];
        int pos = atomicAdd(&g_cursor[d], 1);
        g_colsrc[pos] = src[e];
    }
}

// ------- weight transpose + bf16 split: W[K][N] -> Wt_hi/lo[N][K] -----------
__global__ void wsplit_kernel(const float* __restrict__ W, __nv_bfloat16* __restrict__ Th,
                              __nv_bfloat16* __restrict__ Tl, int K, int N) {
    int i = blockIdx.x * blockDim.x + threadIdx.x;
    if (i < K * N) {
        int k = i / N, n = i % N;
        float v = W[i];
        __nv_bfloat16 h = __float2bfloat16(v);
        __nv_bfloat16 l = __float2bfloat16(v - __bfloat162float(h));
        Th[(size_t)n * K + k] = h;
        Tl[(size_t)n * K + k] = l;
    }
}

// ---------------- bf16x3 tensor-core GEMM, cp.async pipelined ----------------
// g_Hh = fp16( diag(g_sout) * A @ Wt^T )  with D = Ahi*Bhi + Ahi*Blo + Alo*Bhi.
// BM=128, BN=128, BK=32, 8 warps (2m x 4n), warp tile 64x32, mma.m16n8k16 bf16.
// Double-buffered raw-A (fp32) + B (bf16) via cp.async; Ah/Al converted between syncs.
#define GPAD 40   // bf16 elements per SMEM row (80 B): conflict-free ldmatrix

// dynamic SMEM byte offsets
#define RAWA_OFF  0u          // 2 x 16384 (128x32 fp32)
#define RAWA_STR  16384u
#define BH_OFF    32768u      // 2 x 10240 (128xGPAD bf16)
#define BL_OFF    53248u
#define BSTAGE    10240u
#define AH_OFF    73728u      // 1 x 10240
#define AL_OFF    83968u
#define GSMEM_TOT 94208

template <int NC, int KT, bool A_GLOBAL>
__global__ __launch_bounds__(256, 2)
void gemm_bf16x3(const float* __restrict__ Aparam,
                 const __nv_bfloat16* __restrict__ Bh,
                 const __nv_bfloat16* __restrict__ Bl, int M) {
    extern __shared__ __align__(16) char smem[];
    const uint32_t sm = smem_u32(smem);

    const int tid = threadIdx.x;
    const int lane = tid & 31, warp = tid >> 5;
    const int wm = warp >> 2, wn = warp & 3;     // 2 x 4 warp grid
    const int bn = blockIdx.x, bm = blockIdx.y;
    const float* __restrict__ A = A_GLOBAL ? g_X : Aparam;

    float c[4][4][4];
#pragma unroll
    for (int mi = 0; mi < 4; mi++)
#pragma unroll
        for (int ni = 0; ni < 4; ni++)
#pragma unroll
            for (int q = 0; q < 4; q++) c[mi][ni][q] = 0.f;

    const int kiters = KT / 32;

    // ---- stage-issue helper (A: 4 chunks/thread, B hi+lo: 2 chunks each) ----
    auto issue_stage = [&](int kt, int stage) {
        const int k0 = kt * 32;
        const uint32_t rawA = sm + RAWA_OFF + (uint32_t)stage * RAWA_STR;
        const uint32_t bh = sm + BH_OFF + (uint32_t)stage * BSTAGE;
        const uint32_t bl = sm + BL_OFF + (uint32_t)stage * BSTAGE;
#pragma unroll
        for (int j = 0; j < 4; j++) {
            const int cchunk = j * 256 + tid;             // 0..1023
            const int row = cchunk >> 3, cc = (cchunk & 7) * 4;
            const int grow = bm * 128 + row;
            cp_async16(rawA + (uint32_t)(row * 128 + cc * 4),
                       A + (size_t)grow * KT + k0 + cc, (grow < M) ? 16 : 0);
        }
#pragma unroll
        for (int j = 0; j < 2; j++) {
            const int cchunk = j * 256 + tid;             // 0..511
            const int row = cchunk >> 2, cc = (cchunk & 3) * 8;
            const int gn = bn * 128 + row;                // NC multiple of 128
            const uint32_t doff = (uint32_t)(row * (GPAD * 2) + cc * 2);
            cp_async16(bh + doff, Bh + (size_t)gn * KT + k0 + cc, 16);
            cp_async16(bl + doff, Bl + (size_t)gn * KT + k0 + cc, 16);
        }
        cp_commit();
    };

    issue_stage(0, 0);

    for (int kt = 0; kt < kiters; kt++) {
        const int stage = kt & 1;
        cp_wait_all();          // stage kt resident
        __syncthreads();        // everyone done computing kt-1 (freed stage kt+1 bufs)

        if (kt + 1 < kiters) issue_stage(kt + 1, stage ^ 1);

        // ---- convert rawA[stage] -> Ah/Al with rowscale ----
        {
            const float4* raw =
                (const float4*)(smem + RAWA_OFF + (uint32_t)stage * RAWA_STR);
            __nv_bfloat16* AhP = (__nv_bfloat16*)(smem + AH_OFF);
            __nv_bfloat16* AlP = (__nv_bfloat16*)(smem + AL_OFF);
#pragma unroll
            for (int j = 0; j < 4; j++) {
                const int cchunk = j * 256 + tid;
                const int row = cchunk >> 3, col = (cchunk & 7) * 4;
                const int grow = bm * 128 + row;
                const float sc = (grow < M) ? g_sout[grow] : 0.f;
                float4 v = raw[row * 8 + (cchunk & 7)];
                v.x *= sc; v.y *= sc; v.z *= sc; v.w *= sc;
                __nv_bfloat16 h0 = __float2bfloat16(v.x), h1 = __float2bfloat16(v.y);
                __nv_bfloat16 h2 = __float2bfloat16(v.z), h3 = __float2bfloat16(v.w);
                __nv_bfloat16 l0 = __float2bfloat16(v.x - __bfloat162float(h0));
                __nv_bfloat16 l1 = __float2bfloat16(v.y - __bfloat162float(h1));
                __nv_bfloat16 l2 = __float2bfloat16(v.z - __bfloat162float(h2));
                __nv_bfloat16 l3 = __float2bfloat16(v.w - __bfloat162float(h3));
                const int off = row * GPAD + col;
                *(__nv_bfloat162*)&AhP[off]     = __halves2bfloat162(h0, h1);
                *(__nv_bfloat162*)&AhP[off + 2] = __halves2bfloat162(h2, h3);
                *(__nv_bfloat162*)&AlP[off]     = __halves2bfloat162(l0, l1);
                *(__nv_bfloat162*)&AlP[off + 2] = __halves2bfloat162(l2, l3);
            }
        }
        __syncthreads();

        // ---- compute: 2 k-steps of 16, 3 MMA combos each ----
        const uint32_t sAh = sm + AH_OFF, sAl = sm + AL_OFF;
        const uint32_t sBh = sm + BH_OFF + (uint32_t)stage * BSTAGE;
        const uint32_t sBl = sm + BL_OFF + (uint32_t)stage * BSTAGE;
#pragma unroll
        for (int kk = 0; kk < 2; kk++) {
            const int kc = kk * 16;
            const int l16 = lane & 15;
            uint32_t bhf[4][2], blf[4][2];
#pragma unroll
            for (int ni = 0; ni < 4; ni++) {
                const uint32_t boff =
                    (uint32_t)((wn * 32 + ni * 8 + (l16 & 7)) * GPAD + kc + (l16 >> 3) * 8) * 2u;
                ldsm_x2(bhf[ni], sBh + boff);
                ldsm_x2(blf[ni], sBl + boff);
            }
#pragma unroll
            for (int mi = 0; mi < 4; mi++) {
                const uint32_t aoff =
                    (uint32_t)((wm * 64 + mi * 16 + (lane & 15)) * GPAD + kc + (lane >> 4) * 8) * 2u;
                uint32_t ahf[4], alf[4];
                ldsm_x4(ahf, sAh + aoff);
                ldsm_x4(alf, sAl + aoff);
#pragma unroll
                for (int ni = 0; ni < 4; ni++) {
                    mma_bf16(c[mi][ni], ahf, bhf[ni]);
                    mma_bf16(c[mi][ni], ahf, blf[ni]);
                    mma_bf16(c[mi][ni], alf, bhf[ni]);
                }
            }
        }
    }

    // ---- epilogue: fp32 accum -> fp16 store (half2) ----
#pragma unroll
    for (int mi = 0; mi < 4; mi++) {
        const int r0 = bm * 128 + wm * 64 + mi * 16 + (lane >> 2);
#pragma unroll
        for (int ni = 0; ni < 4; ni++) {
            const int col = bn * 128 + wn * 32 + ni * 8 + 2 * (lane & 3);
            if (r0 < M)
                *(__half2*)(g_Hh + (size_t)r0 * NC + col) =
                    __floats2half2_rn(c[mi][ni][0], c[mi][ni][1]);
            if (r0 + 8 < M)
                *(__half2*)(g_Hh + (size_t)(r0 + 8) * NC + col) =
                    __floats2half2_rn(c[mi][ni][2], c[mi][ni][3]);
        }
    }
}

// ---------------- pull-based aggregation (atomic-free, fp16 gather) ---------
// THREADS = COLS/2: each thread owns exactly one half2 (cols 2t, 2t+1).
template <int COLS, bool RELU>
__global__ __launch_bounds__(COLS / 2)
void aggregate_kernel(const float* __restrict__ bias) {
    const int v = blockIdx.x;
    const int t = threadIdx.x;
    constexpr int H2C = COLS / 2;

    float ax = 0.f, ay = 0.f;

    const int beg = g_rowptr[v];
    const int end = g_rowptr[v + 1];
    const __half2* __restrict__ Hm = (const __half2*)g_Hh;

    int e = beg;
    for (; e + 3 < end; e += 4) {
        int s0 = g_colsrc[e + 0], s1 = g_colsrc[e + 1];
        int s2 = g_colsrc[e + 2], s3 = g_colsrc[e + 3];
        float2 v0 = __half22float2(Hm[(size_t)s0 * H2C + t]);
        float2 v1 = __half22float2(Hm[(size_t)s1 * H2C + t]);
        float2 v2 = __half22float2(Hm[(size_t)s2 * H2C + t]);
        float2 v3 = __half22float2(Hm[(size_t)s3 * H2C + t]);
        ax += (v0.x + v1.x) + (v2.x + v3.x);
        ay += (v0.y + v1.y) + (v2.y + v3.y);
    }
    for (; e < end; e++) {
        int s = g_colsrc[e];
        float2 v0 = __half22float2(Hm[(size_t)s * H2C + t]);
        ax += v0.x;
        ay += v0.y;
    }

    const float si = g_sin[v];
    float2 b = *(const float2*)(bias + 2 * t);
    float ox = fmaf(ax, si, b.x);
    float oy = fmaf(ay, si, b.y);
    if (RELU) { ox = fmaxf(ox, 0.f); oy = fmaxf(oy, 0.f); }
    *(float2*)(g_X + (size_t)v * COLS + 2 * t) = make_float2(ox, oy);
}

// ---------------- output head: relu(x@Wo1+bo1)@Wo2+bo2 ----------------------
__global__ __launch_bounds__(256)
void head_kernel(const float* __restrict__ Wo1, const float* __restrict__ bo1,
                 const float* __restrict__ Wo2, const float* __restrict__ bo2,
                 float* __restrict__ out) {
    __shared__ __align__(16) float sW1[H2 * ENDD];
    __shared__ float sb1[ENDD], sW2[ENDD];
    __shared__ float sx[8][H2];

    const int tid = threadIdx.x;
    for (int i = tid; i < H2 * ENDD; i += 256) sW1[i] = Wo1[i];
    if (tid < ENDD) { sb1[tid] = bo1[tid]; sW2[tid] = Wo2[tid]; }
    __syncthreads();

    const float bout = bo2[0];
    const int warp = tid >> 5, lane = tid & 31;

    for (int v = blockIdx.x * 8 + warp; v < N_NODES; v += gridDim.x * 8) {
        const float* xr = g_X + (size_t)v * H2;
#pragma unroll
        for (int q = 0; q < 4; q++) sx[warp][lane + 32 * q] = xr[lane + 32 * q];
        __syncwarp();

        float h0 = sb1[lane], h1 = sb1[lane + 32];
#pragma unroll 8
        for (int k = 0; k < H2; k++) {
            float xk = sx[warp][k];
            h0 = fmaf(xk, sW1[k * ENDD + lane], h0);
            h1 = fmaf(xk, sW1[k * ENDD + lane + 32], h1);
        }
        h0 = fmaxf(h0, 0.f);
        h1 = fmaxf(h1, 0.f);
        float p = h0 * sW2[lane] + h1 * sW2[lane + 32];
#pragma unroll
        for (int off = 16; off; off >>= 1) p += __shfl_down_sync(0xffffffffu, p, off);
        if (lane == 0) out[v] = p + bout;
        __syncwarp();
    }
}

// ---------------- launch -----------------------------------------------------
extern "C" void kernel_launch(void* const* d_in, const int* in_sizes, int n_in,
                              void* d_out, int out_size) {
    const float* feat = (const float*)d_in[0];   // [N, 64, 8] -> [N, 512]
    const int*   src  = (const int*)d_in[1];
    const int*   dst  = (const int*)d_in[2];
    const float* W1   = (const float*)d_in[3];
    const float* b1   = (const float*)d_in[4];
    const float* W2   = (const float*)d_in[5];
    const float* b2   = (const float*)d_in[6];
    const float* Wo1  = (const float*)d_in[7];
    const float* bo1  = (const float*)d_in[8];
    const float* Wo2  = (const float*)d_in[9];
    const float* bo2  = (const float*)d_in[10];
    float* out = (float*)d_out;

    const int nb_nodes = (N_NODES + 255) / 256;
    const int mtiles = (N_NODES + 127) / 128;   // 782

    __nv_bfloat16 *t1h, *t1l, *t2h, *t2l;
    cudaGetSymbolAddress((void**)&t1h, g_W1t_hi);
    cudaGetSymbolAddress((void**)&t1l, g_W1t_lo);
    cudaGetSymbolAddress((void**)&t2h, g_W2t_hi);
    cudaGetSymbolAddress((void**)&t2l, g_W2t_lo);

    cudaFuncSetAttribute(gemm_bf16x3<H1, K1, false>,
                         cudaFuncAttributeMaxDynamicSharedMemorySize, GSMEM_TOT);
    cudaFuncSetAttribute(gemm_bf16x3<H2, H1, true>,
                         cudaFuncAttributeMaxDynamicSharedMemorySize, GSMEM_TOT);

    // graph preprocessing: degrees, scales, CSR-by-dst; weight transpose/split
    zero_deg_kernel<<<nb_nodes, 256>>>();
    degree_kernel<<<2048, 256>>>(src, dst);
    scales_kernel<<<nb_nodes, 256>>>();
    scan_block_kernel<<<SCAN_BLOCKS, 1024>>>();
    scan_part_kernel<<<1, 128>>>();
    scan_finish_kernel<<<nb_nodes, 256>>>();
    csr_fill_kernel<<<2048, 256>>>(src, dst);
    wsplit_kernel<<<(K1 * H1 + 255) / 256, 256>>>(W1, t1h, t1l, K1, H1);
    wsplit_kernel<<<(H1 * H2 + 255) / 256, 256>>>(W2, t2h, t2l, H1, H2);

    // layer 1: H = (sout * X) @ W1 ; X2 = relu(sin * agg(H) + b1)
    {
        dim3 grid(H1 / 128, mtiles);
        gemm_bf16x3<H1, K1, false><<<grid, 256, GSMEM_TOT>>>(feat, t1h, t1l, N_NODES);
    }
    aggregate_kernel<H1, true><<<N_NODES, H1 / 2>>>(b1);

    // layer 2: H = (sout * X2) @ W2 ; X3 = sin * agg(H) + b2
    {
        dim3 grid(H2 / 128, mtiles);
        gemm_bf16x3<H2, H1, true><<<grid, 256, GSMEM_TOT>>>(nullptr, t2h, t2l, N_NODES);
    }
    aggregate_kernel<H2, false><<<N_NODES, H2 / 2>>>(b2);

    // head
    head_kernel<<<296, 256>>>(Wo1, bo1, Wo2, bo2, out);
}

// round 9
// speedup vs baseline: 1.8129x; 1.0158x over previous
#include <cuda_runtime.h>
#include <cuda_bf16.h>
#include <cuda_fp16.h>
#include <cstdint>

#define N_NODES 100000
#define N_EDGES 3200000
#define K1 512      // in_dim * n_seq
#define H1 256
#define H2 128
#define ENDD 64

// ---------------- scratch (device globals; no allocation allowed) -----------
__device__ __half g_Hh[(size_t)N_NODES * H1];  // GEMM outputs, fp16 (agg input)
__device__ float g_X[(size_t)N_NODES * H1];    // aggregated activations (fp32)
__device__ int   g_deg_out[N_NODES];
__device__ int   g_deg_in[N_NODES];
__device__ float g_sout[N_NODES];
__device__ float g_sin[N_NODES];
__device__ int   g_rowptr[N_NODES + 1];
__device__ int   g_cursor[N_NODES];
__device__ int   g_colsrc[N_EDGES];
#define SCAN_BLOCKS ((N_NODES + 1023) / 1024)   // 98
__device__ int   g_part[128];
__device__ int   g_poff[128];
// transposed + bf16-split weights: Wt[n][k]
__device__ __nv_bfloat16 g_W1t_hi[H1 * K1];
__device__ __nv_bfloat16 g_W1t_lo[H1 * K1];
__device__ __nv_bfloat16 g_W2t_hi[H2 * H1];
__device__ __nv_bfloat16 g_W2t_lo[H2 * H1];

// ---------------- PTX helpers ------------------------------------------------
__device__ __forceinline__ uint32_t smem_u32(const void* p) {
    uint32_t a;
    asm("{ .reg .u64 t; cvta.to.shared.u64 t, %1; cvt.u32.u64 %0, t; }"
        : "=r"(a) : "l"(p));
    return a;
}

__device__ __forceinline__ void ldsm_x4(uint32_t (&r)[4], uint32_t a) {
    asm volatile("ldmatrix.sync.aligned.m8n8.x4.shared.b16 {%0,%1,%2,%3}, [%4];"
                 : "=r"(r[0]), "=r"(r[1]), "=r"(r[2]), "=r"(r[3]) : "r"(a));
}

__device__ __forceinline__ void ldsm_x2(uint32_t (&r)[2], uint32_t a) {
    asm volatile("ldmatrix.sync.aligned.m8n8.x2.shared.b16 {%0,%1}, [%2];"
                 : "=r"(r[0]), "=r"(r[1]) : "r"(a));
}

__device__ __forceinline__ void mma_bf16(float (&d)[4], const uint32_t (&a)[4],
                                         const uint32_t (&b)[2]) {
    asm volatile(
        "mma.sync.aligned.m16n8k16.row.col.f32.bf16.bf16.f32 "
        "{%0,%1,%2,%3}, {%4,%5,%6,%7}, {%8,%9}, {%0,%1,%2,%3};"
        : "+f"(d[0]), "+f"(d[1]), "+f"(d[2]), "+f"(d[3])
        : "r"(a[0]), "r"(a[1]), "r"(a[2]), "r"(a[3]), "r"(b[0]), "r"(b[1]));
}

__device__ __forceinline__ void cp_async16(uint32_t smem_dst, const void* gsrc,
                                           int src_bytes) {
    asm volatile("cp.async.cg.shared.global [%0], [%1], 16, %2;"
                 :: "r"(smem_dst), "l"(gsrc), "r"(src_bytes));
}
__device__ __forceinline__ void cp_commit() {
    asm volatile("cp.async.commit_group;");
}
__device__ __forceinline__ void cp_wait_all() {
    asm volatile("cp.async.wait_group 0;");
}

// ---------------- graph preprocessing ---------------------------------------
__global__ void zero_deg_kernel() {
    int i = blockIdx.x * blockDim.x + threadIdx.x;
    if (i < N_NODES) { g_deg_out[i] = 0; g_deg_in[i] = 0; }
}

__global__ void degree_kernel(const int* __restrict__ src, const int* __restrict__ dst) {
    for (int e = blockIdx.x * blockDim.x + threadIdx.x; e < N_EDGES;
         e += gridDim.x * blockDim.x) {
        atomicAdd(&g_deg_out[src[e]], 1);
        atomicAdd(&g_deg_in[dst[e]], 1);
    }
}

__global__ void scales_kernel() {
    int i = blockIdx.x * blockDim.x + threadIdx.x;
    if (i < N_NODES) {
        g_sout[i] = rsqrtf((float)max(g_deg_out[i], 1));
        g_sin[i]  = rsqrtf((float)max(g_deg_in[i], 1));
    }
}

__global__ void scan_block_kernel() {
    __shared__ int sh[1024];
    int t = threadIdx.x;
    int i = blockIdx.x * 1024 + t;
    int v = (i < N_NODES) ? g_deg_in[i] : 0;
    sh[t] = v;
    __syncthreads();
    for (int off = 1; off < 1024; off <<= 1) {
        int x = sh[t];
        int y = (t >= off) ? sh[t - off] : 0;
        __syncthreads();
        sh[t] = x + y;
        __syncthreads();
    }
    if (i < N_NODES) g_rowptr[i] = sh[t] - v;
    if (t == 1023) g_part[blockIdx.x] = sh[1023];
}

__global__ void scan_part_kernel() {
    __shared__ int sh[128];
    int t = threadIdx.x;
    int v = (t < SCAN_BLOCKS) ? g_part[t] : 0;
    sh[t] = v;
    __syncthreads();
    for (int off = 1; off < 128; off <<= 1) {
        int x = sh[t];
        int y = (t >= off) ? sh[t - off] : 0;
        __syncthreads();
        sh[t] = x + y;
        __syncthreads();
    }
    g_poff[t] = sh[t] - v;
}

__global__ void scan_finish_kernel() {
    int i = blockIdx.x * blockDim.x + threadIdx.x;
    if (i < N_NODES) {
        int r = g_rowptr[i] + g_poff[i >> 10];
        g_rowptr[i] = r;
        g_cursor[i] = r;
    }
    if (i == 0) g_rowptr[N_NODES] = N_EDGES;
}

__global__ void csr_fill_kernel(const int* __restrict__ src, const int* __restrict__ dst) {
    for (int e = blockIdx.x * blockDim.x + threadIdx.x; e < N_EDGES;
         e += gridDim.x * blockDim.x) {
        int d = dst[e];
        int pos = atomicAdd(&g_cursor[d], 1);
        g_colsrc[pos] = src[e];
    }
}

// ------- weight transpose + bf16 split: W[K][N] -> Wt_hi/lo[N][K] -----------
__global__ void wsplit_kernel(const float* __restrict__ W, __nv_bfloat16* __restrict__ Th,
                              __nv_bfloat16* __restrict__ Tl, int K, int N) {
    int i = blockIdx.x * blockDim.x + threadIdx.x;
    if (i < K * N) {
        int k = i / N, n = i % N;
        float v = W[i];
        __nv_bfloat16 h = __float2bfloat16(v);
        __nv_bfloat16 l = __float2bfloat16(v - __bfloat162float(h));
        Th[(size_t)n * K + k] = h;
        Tl[(size_t)n * K + k] = l;
    }
}

// ---------------- bf16x3 tensor-core GEMM, cp.async pipelined ----------------
// g_Hh = fp16( A @ Wt^T )  with D = Ahi*Bhi + Ahi*Blo + Alo*Bhi.  (no rowscale:
// degree normalization is folded into the aggregation kernels)
// BM=128, BN=128, BK=32, 8 warps (2m x 4n), warp tile 64x32, mma.m16n8k16 bf16.
#define GPAD 40   // bf16 elements per SMEM row (80 B): conflict-free ldmatrix

// dynamic SMEM byte offsets
#define RAWA_OFF  0u          // 2 x 16384 (128x32 fp32)
#define RAWA_STR  16384u
#define BH_OFF    32768u      // 2 x 10240 (128xGPAD bf16)
#define BL_OFF    53248u
#define BSTAGE    10240u
#define AH_OFF    73728u      // 1 x 10240
#define AL_OFF    83968u
#define GSMEM_TOT 94208

template <int NC, int KT, bool A_GLOBAL>
__global__ __launch_bounds__(256, 2)
void gemm_bf16x3(const float* __restrict__ Aparam,
                 const __nv_bfloat16* __restrict__ Bh,
                 const __nv_bfloat16* __restrict__ Bl, int M) {
    extern __shared__ __align__(16) char smem[];
    const uint32_t sm = smem_u32(smem);

    const int tid = threadIdx.x;
    const int lane = tid & 31, warp = tid >> 5;
    const int wm = warp >> 2, wn = warp & 3;     // 2 x 4 warp grid
    const int bn = blockIdx.x, bm = blockIdx.y;
    const float* __restrict__ A = A_GLOBAL ? g_X : Aparam;

    float c[4][4][4];
#pragma unroll
    for (int mi = 0; mi < 4; mi++)
#pragma unroll
        for (int ni = 0; ni < 4; ni++)
#pragma unroll
            for (int q = 0; q < 4; q++) c[mi][ni][q] = 0.f;

    const int kiters = KT / 32;

    // ---- stage-issue helper (A: 4 chunks/thread, B hi+lo: 2 chunks each) ----
    auto issue_stage = [&](int kt, int stage) {
        const int k0 = kt * 32;
        const uint32_t rawA = sm + RAWA_OFF + (uint32_t)stage * RAWA_STR;
        const uint32_t bh = sm + BH_OFF + (uint32_t)stage * BSTAGE;
        const uint32_t bl = sm + BL_OFF + (uint32_t)stage * BSTAGE;
#pragma unroll
        for (int j = 0; j < 4; j++) {
            const int cchunk = j * 256 + tid;             // 0..1023
            const int row = cchunk >> 3, cc = (cchunk & 7) * 4;
            const int grow = bm * 128 + row;
            cp_async16(rawA + (uint32_t)(row * 128 + cc * 4),
                       A + (size_t)grow * KT + k0 + cc, (grow < M) ? 16 : 0);
        }
#pragma unroll
        for (int j = 0; j < 2; j++) {
            const int cchunk = j * 256 + tid;             // 0..511
            const int row = cchunk >> 2, cc = (cchunk & 3) * 8;
            const int gn = bn * 128 + row;                // NC multiple of 128
            const uint32_t doff = (uint32_t)(row * (GPAD * 2) + cc * 2);
            cp_async16(bh + doff, Bh + (size_t)gn * KT + k0 + cc, 16);
            cp_async16(bl + doff, Bl + (size_t)gn * KT + k0 + cc, 16);
        }
        cp_commit();
    };

    issue_stage(0, 0);

    for (int kt = 0; kt < kiters; kt++) {
        const int stage = kt & 1;
        cp_wait_all();          // stage kt resident
        __syncthreads();        // everyone done computing kt-1 (freed stage kt+1 bufs)

        if (kt + 1 < kiters) issue_stage(kt + 1, stage ^ 1);

        // ---- convert rawA[stage] -> Ah/Al (bf16 hi/lo split) ----
        {
            const float4* raw =
                (const float4*)(smem + RAWA_OFF + (uint32_t)stage * RAWA_STR);
            __nv_bfloat16* AhP = (__nv_bfloat16*)(smem + AH_OFF);
            __nv_bfloat16* AlP = (__nv_bfloat16*)(smem + AL_OFF);
#pragma unroll
            for (int j = 0; j < 4; j++) {
                const int cchunk = j * 256 + tid;
                const int row = cchunk >> 3, col = (cchunk & 7) * 4;
                float4 v = raw[row * 8 + (cchunk & 7)];
                __nv_bfloat16 h0 = __float2bfloat16(v.x), h1 = __float2bfloat16(v.y);
                __nv_bfloat16 h2 = __float2bfloat16(v.z), h3 = __float2bfloat16(v.w);
                __nv_bfloat16 l0 = __float2bfloat16(v.x - __bfloat162float(h0));
                __nv_bfloat16 l1 = __float2bfloat16(v.y - __bfloat162float(h1));
                __nv_bfloat16 l2 = __float2bfloat16(v.z - __bfloat162float(h2));
                __nv_bfloat16 l3 = __float2bfloat16(v.w - __bfloat162float(h3));
                const int off = row * GPAD + col;
                *(__nv_bfloat162*)&AhP[off]     = __halves2bfloat162(h0, h1);
                *(__nv_bfloat162*)&AhP[off + 2] = __halves2bfloat162(h2, h3);
                *(__nv_bfloat162*)&AlP[off]     = __halves2bfloat162(l0, l1);
                *(__nv_bfloat162*)&AlP[off + 2] = __halves2bfloat162(l2, l3);
            }
        }
        __syncthreads();

        // ---- compute: 2 k-steps of 16, 3 MMA combos each ----
        const uint32_t sAh = sm + AH_OFF, sAl = sm + AL_OFF;
        const uint32_t sBh = sm + BH_OFF + (uint32_t)stage * BSTAGE;
        const uint32_t sBl = sm + BL_OFF + (uint32_t)stage * BSTAGE;
#pragma unroll
        for (int kk = 0; kk < 2; kk++) {
            const int kc = kk * 16;
            const int l16 = lane & 15;
            uint32_t bhf[4][2], blf[4][2];
#pragma unroll
            for (int ni = 0; ni < 4; ni++) {
                const uint32_t boff =
                    (uint32_t)((wn * 32 + ni * 8 + (l16 & 7)) * GPAD + kc + (l16 >> 3) * 8) * 2u;
                ldsm_x2(bhf[ni], sBh + boff);
                ldsm_x2(blf[ni], sBl + boff);
            }
#pragma unroll
            for (int mi = 0; mi < 4; mi++) {
                const uint32_t aoff =
                    (uint32_t)((wm * 64 + mi * 16 + (lane & 15)) * GPAD + kc + (lane >> 4) * 8) * 2u;
                uint32_t ahf[4], alf[4];
                ldsm_x4(ahf, sAh + aoff);
                ldsm_x4(alf, sAl + aoff);
#pragma unroll
                for (int ni = 0; ni < 4; ni++) {
                    mma_bf16(c[mi][ni], ahf, bhf[ni]);
                    mma_bf16(c[mi][ni], ahf, blf[ni]);
                    mma_bf16(c[mi][ni], alf, bhf[ni]);
                }
            }
        }
    }

    // ---- epilogue: fp32 accum -> fp16 store (half2) ----
#pragma unroll
    for (int mi = 0; mi < 4; mi++) {
        const int r0 = bm * 128 + wm * 64 + mi * 16 + (lane >> 2);
#pragma unroll
        for (int ni = 0; ni < 4; ni++) {
            const int col = bn * 128 + wn * 32 + ni * 8 + 2 * (lane & 3);
            if (r0 < M)
                *(__half2*)(g_Hh + (size_t)r0 * NC + col) =
                    __floats2half2_rn(c[mi][ni][0], c[mi][ni][1]);
            if (r0 + 8 < M)
                *(__half2*)(g_Hh + (size_t)(r0 + 8) * NC + col) =
                    __floats2half2_rn(c[mi][ni][2], c[mi][ni][3]);
        }
    }
}

// ---------------- pull-based aggregation (atomic-free, fp16 gather) ---------
// THREADS = COLS/2: each thread owns exactly one half2 (cols 2t, 2t+1).
// L1MODE: gathered rows weighted by sout[s]; output = sout[v]*relu(sin[v]*acc+b)
//         (prescales layer 2's input, so GEMMs stay scale-free).
// else:   plain gather; output = sin[v]*acc + b.
template <int COLS, bool L1MODE>
__global__ __launch_bounds__(COLS / 2)
void aggregate_kernel(const float* __restrict__ bias) {
    const int v = blockIdx.x;
    const int t = threadIdx.x;
    constexpr int H2C = COLS / 2;

    float ax = 0.f, ay = 0.f;

    const int beg = g_rowptr[v];
    const int end = g_rowptr[v + 1];
    const __half2* __restrict__ Hm = (const __half2*)g_Hh;

    int e = beg;
    for (; e + 3 < end; e += 4) {
        int s0 = g_colsrc[e + 0], s1 = g_colsrc[e + 1];
        int s2 = g_colsrc[e + 2], s3 = g_colsrc[e + 3];
        float2 v0 = __half22float2(Hm[(size_t)s0 * H2C + t]);
        float2 v1 = __half22float2(Hm[(size_t)s1 * H2C + t]);
        float2 v2 = __half22float2(Hm[(size_t)s2 * H2C + t]);
        float2 v3 = __half22float2(Hm[(size_t)s3 * H2C + t]);
        if (L1MODE) {
            float w0 = __ldg(&g_sout[s0]), w1 = __ldg(&g_sout[s1]);
            float w2 = __ldg(&g_sout[s2]), w3 = __ldg(&g_sout[s3]);
            ax = fmaf(v0.x, w0, ax); ay = fmaf(v0.y, w0, ay);
            ax = fmaf(v1.x, w1, ax); ay = fmaf(v1.y, w1, ay);
            ax = fmaf(v2.x, w2, ax); ay = fmaf(v2.y, w2, ay);
            ax = fmaf(v3.x, w3, ax); ay = fmaf(v3.y, w3, ay);
        } else {
            ax += (v0.x + v1.x) + (v2.x + v3.x);
            ay += (v0.y + v1.y) + (v2.y + v3.y);
        }
    }
    for (; e < end; e++) {
        int s = g_colsrc[e];
        float2 v0 = __half22float2(Hm[(size_t)s * H2C + t]);
        if (L1MODE) {
            float w0 = __ldg(&g_sout[s]);
            ax = fmaf(v0.x, w0, ax); ay = fmaf(v0.y, w0, ay);
        } else {
            ax += v0.x;
            ay += v0.y;
        }
    }

    const float si = g_sin[v];
    float2 b = *(const float2*)(bias + 2 * t);
    float ox = fmaf(ax, si, b.x);
    float oy = fmaf(ay, si, b.y);
    if (L1MODE) {
        const float so = g_sout[v];
        ox = fmaxf(ox, 0.f) * so;
        oy = fmaxf(oy, 0.f) * so;
    }
    *(float2*)(g_X + (size_t)v * COLS + 2 * t) = make_float2(ox, oy);
}

// ---------------- output head: relu(x@Wo1+bo1)@Wo2+bo2 ----------------------
__global__ __launch_bounds__(256)
void head_kernel(const float* __restrict__ Wo1, const float* __restrict__ bo1,
                 const float* __restrict__ Wo2, const float* __restrict__ bo2,
                 float* __restrict__ out) {
    __shared__ __align__(16) float sW1[H2 * ENDD];
    __shared__ float sb1[ENDD], sW2[ENDD];
    __shared__ float sx[8][H2];

    const int tid = threadIdx.x;
    for (int i = tid; i < H2 * ENDD; i += 256) sW1[i] = Wo1[i];
    if (tid < ENDD) { sb1[tid] = bo1[tid]; sW2[tid] = Wo2[tid]; }
    __syncthreads();

    const float bout = bo2[0];
    const int warp = tid >> 5, lane = tid & 31;

    for (int v = blockIdx.x * 8 + warp; v < N_NODES; v += gridDim.x * 8) {
        const float* xr = g_X + (size_t)v * H2;
#pragma unroll
        for (int q = 0; q < 4; q++) sx[warp][lane + 32 * q] = xr[lane + 32 * q];
        __syncwarp();

        float h0 = sb1[lane], h1 = sb1[lane + 32];
#pragma unroll 8
        for (int k = 0; k < H2; k++) {
            float xk = sx[warp][k];
            h0 = fmaf(xk, sW1[k * ENDD + lane], h0);
            h1 = fmaf(xk, sW1[k * ENDD + lane + 32], h1);
        }
        h0 = fmaxf(h0, 0.f);
        h1 = fmaxf(h1, 0.f);
        float p = h0 * sW2[lane] + h1 * sW2[lane + 32];
#pragma unroll
        for (int off = 16; off; off >>= 1) p += __shfl_down_sync(0xffffffffu, p, off);
        if (lane == 0) out[v] = p + bout;
        __syncwarp();
    }
}

// ---------------- launch -----------------------------------------------------
extern "C" void kernel_launch(void* const* d_in, const int* in_sizes, int n_in,
                              void* d_out, int out_size) {
    const float* feat = (const float*)d_in[0];   // [N, 64, 8] -> [N, 512]
    const int*   src  = (const int*)d_in[1];
    const int*   dst  = (const int*)d_in[2];
    const float* W1   = (const float*)d_in[3];
    const float* b1   = (const float*)d_in[4];
    const float* W2   = (const float*)d_in[5];
    const float* b2   = (const float*)d_in[6];
    const float* Wo1  = (const float*)d_in[7];
    const float* bo1  = (const float*)d_in[8];
    const float* Wo2  = (const float*)d_in[9];
    const float* bo2  = (const float*)d_in[10];
    float* out = (float*)d_out;

    const int nb_nodes = (N_NODES + 255) / 256;
    const int mtiles = (N_NODES + 127) / 128;   // 782

    __nv_bfloat16 *t1h, *t1l, *t2h, *t2l;
    cudaGetSymbolAddress((void**)&t1h, g_W1t_hi);
    cudaGetSymbolAddress((void**)&t1l, g_W1t_lo);
    cudaGetSymbolAddress((void**)&t2h, g_W2t_hi);
    cudaGetSymbolAddress((void**)&t2l, g_W2t_lo);

    cudaFuncSetAttribute(gemm_bf16x3<H1, K1, false>,
                         cudaFuncAttributeMaxDynamicSharedMemorySize, GSMEM_TOT);
    cudaFuncSetAttribute(gemm_bf16x3<H2, H1, true>,
                         cudaFuncAttributeMaxDynamicSharedMemorySize, GSMEM_TOT);

    // one-time side stream + fork/join events (reused across calls/capture)
    static cudaStream_t s_pre = nullptr;
    static cudaEvent_t ev_fork = nullptr, ev_pre = nullptr;
    if (s_pre == nullptr) {
        cudaStreamCreateWithFlags(&s_pre, cudaStreamNonBlocking);
        cudaEventCreateWithFlags(&ev_fork, cudaEventDisableTiming);
        cudaEventCreateWithFlags(&ev_pre, cudaEventDisableTiming);
    }

    // ---- fork: graph preprocessing on side stream ----
    cudaEventRecord(ev_fork, 0);
    cudaStreamWaitEvent(s_pre, ev_fork, 0);
    zero_deg_kernel<<<nb_nodes, 256, 0, s_pre>>>();
    degree_kernel<<<2048, 256, 0, s_pre>>>(src, dst);
    scales_kernel<<<nb_nodes, 256, 0, s_pre>>>();
    scan_block_kernel<<<SCAN_BLOCKS, 1024, 0, s_pre>>>();
    scan_part_kernel<<<1, 128, 0, s_pre>>>();
    scan_finish_kernel<<<nb_nodes, 256, 0, s_pre>>>();
    csr_fill_kernel<<<2048, 256, 0, s_pre>>>(src, dst);
    cudaEventRecord(ev_pre, s_pre);

    // ---- main stream: weight split + graph-independent GEMM1 ----
    wsplit_kernel<<<(K1 * H1 + 255) / 256, 256>>>(W1, t1h, t1l, K1, H1);
    wsplit_kernel<<<(H1 * H2 + 255) / 256, 256>>>(W2, t2h, t2l, H1, H2);
    {
        dim3 grid(H1 / 128, mtiles);
        gemm_bf16x3<H1, K1, false><<<grid, 256, GSMEM_TOT>>>(feat, t1h, t1l, N_NODES);
    }

    // ---- join: aggregation needs CSR + scales + GEMM1 ----
    cudaStreamWaitEvent(0, ev_pre, 0);
    aggregate_kernel<H1, true><<<N_NODES, H1 / 2>>>(b1);

    // layer 2 (scale-free GEMM; agg2 plain gather)
    {
        dim3 grid(H2 / 128, mtiles);
        gemm_bf16x3<H2, H1, true><<<grid, 256, GSMEM_TOT>>>(nullptr, t2h, t2l, N_NODES);
    }
    aggregate_kernel<H2, false><<<N_NODES, H2 / 2>>>(b2);

    // head
    head_kernel<<<296, 256>>>(Wo1, bo1, Wo2, bo2, out);
}

// round 10
// speedup vs baseline: 2.0026x; 1.1046x over previous
#include <cuda_runtime.h>
#include <cuda_bf16.h>
#include <cuda_fp16.h>
#include <cstdint>

#define N_NODES 100000
#define N_EDGES 3200000
#define K1 512      // in_dim * n_seq
#define H1 256
#define H2 128
#define ENDD 64

// ---------------- scratch (device globals; no allocation allowed) -----------
__device__ __half g_Hh[(size_t)N_NODES * H1];  // GEMM outputs, fp16 (agg input)
__device__ __half g_Xh[(size_t)N_NODES * H1];  // layer-2 input, fp16 (agg1 out)
__device__ float g_X[(size_t)N_NODES * H1];    // agg2 output (fp32, head input)
__device__ int   g_deg_out[N_NODES];
__device__ int   g_deg_in[N_NODES];
__device__ float g_sout[N_NODES];
__device__ float g_sin[N_NODES];
__device__ int   g_rowptr[N_NODES + 1];
__device__ int   g_cursor[N_NODES];
__device__ int   g_colsrc[N_EDGES];
#define SCAN_BLOCKS ((N_NODES + 1023) / 1024)   // 98
__device__ int   g_part[128];
__device__ int   g_poff[128];
// transposed + fp16-split weights: Wt[n][k]
__device__ __half g_W1t_hi[H1 * K1];
__device__ __half g_W1t_lo[H1 * K1];
__device__ __half g_W2t_hi[H2 * H1];
__device__ __half g_W2t_lo[H2 * H1];

// ---------------- PTX helpers ------------------------------------------------
__device__ __forceinline__ uint32_t smem_u32(const void* p) {
    uint32_t a;
    asm("{ .reg .u64 t; cvta.to.shared.u64 t, %1; cvt.u32.u64 %0, t; }"
        : "=r"(a) : "l"(p));
    return a;
}

__device__ __forceinline__ void ldsm_x4(uint32_t (&r)[4], uint32_t a) {
    asm volatile("ldmatrix.sync.aligned.m8n8.x4.shared.b16 {%0,%1,%2,%3}, [%4];"
                 : "=r"(r[0]), "=r"(r[1]), "=r"(r[2]), "=r"(r[3]) : "r"(a));
}

__device__ __forceinline__ void ldsm_x2(uint32_t (&r)[2], uint32_t a) {
    asm volatile("ldmatrix.sync.aligned.m8n8.x2.shared.b16 {%0,%1}, [%2];"
                 : "=r"(r[0]), "=r"(r[1]) : "r"(a));
}

__device__ __forceinline__ void mma_fp16(float (&d)[4], const uint32_t (&a)[4],
                                         const uint32_t (&b)[2]) {
    asm volatile(
        "mma.sync.aligned.m16n8k16.row.col.f32.f16.f16.f32 "
        "{%0,%1,%2,%3}, {%4,%5,%6,%7}, {%8,%9}, {%0,%1,%2,%3};"
        : "+f"(d[0]), "+f"(d[1]), "+f"(d[2]), "+f"(d[3])
        : "r"(a[0]), "r"(a[1]), "r"(a[2]), "r"(a[3]), "r"(b[0]), "r"(b[1]));
}

__device__ __forceinline__ void cp_async16(uint32_t smem_dst, const void* gsrc,
                                           int src_bytes) {
    asm volatile("cp.async.cg.shared.global [%0], [%1], 16, %2;"
                 :: "r"(smem_dst), "l"(gsrc), "r"(src_bytes));
}
__device__ __forceinline__ void cp_commit() {
    asm volatile("cp.async.commit_group;");
}
__device__ __forceinline__ void cp_wait_all() {
    asm volatile("cp.async.wait_group 0;");
}

// ---------------- graph preprocessing ---------------------------------------
__global__ void zero_deg_kernel() {
    int i = blockIdx.x * blockDim.x + threadIdx.x;
    if (i < N_NODES) { g_deg_out[i] = 0; g_deg_in[i] = 0; }
}

__global__ void degree_kernel(const int* __restrict__ src, const int* __restrict__ dst) {
    for (int e = blockIdx.x * blockDim.x + threadIdx.x; e < N_EDGES;
         e += gridDim.x * blockDim.x) {
        atomicAdd(&g_deg_out[src[e]], 1);
        atomicAdd(&g_deg_in[dst[e]], 1);
    }
}

__global__ void scales_kernel() {
    int i = blockIdx.x * blockDim.x + threadIdx.x;
    if (i < N_NODES) {
        g_sout[i] = rsqrtf((float)max(g_deg_out[i], 1));
        g_sin[i]  = rsqrtf((float)max(g_deg_in[i], 1));
    }
}

__global__ void scan_block_kernel() {
    __shared__ int sh[1024];
    int t = threadIdx.x;
    int i = blockIdx.x * 1024 + t;
    int v = (i < N_NODES) ? g_deg_in[i] : 0;
    sh[t] = v;
    __syncthreads();
    for (int off = 1; off < 1024; off <<= 1) {
        int x = sh[t];
        int y = (t >= off) ? sh[t - off] : 0;
        __syncthreads();
        sh[t] = x + y;
        __syncthreads();
    }
    if (i < N_NODES) g_rowptr[i] = sh[t] - v;
    if (t == 1023) g_part[blockIdx.x] = sh[1023];
}

__global__ void scan_part_kernel() {
    __shared__ int sh[128];
    int t = threadIdx.x;
    int v = (t < SCAN_BLOCKS) ? g_part[t] : 0;
    sh[t] = v;
    __syncthreads();
    for (int off = 1; off < 128; off <<= 1) {
        int x = sh[t];
        int y = (t >= off) ? sh[t - off] : 0;
        __syncthreads();
        sh[t] = x + y;
        __syncthreads();
    }
    g_poff[t] = sh[t] - v;
}

__global__ void scan_finish_kernel() {
    int i = blockIdx.x * blockDim.x + threadIdx.x;
    if (i < N_NODES) {
        int r = g_rowptr[i] + g_poff[i >> 10];
        g_rowptr[i] = r;
        g_cursor[i] = r;
    }
    if (i == 0) g_rowptr[N_NODES] = N_EDGES;
}

__global__ void csr_fill_kernel(const int* __restrict__ src, const int* __restrict__ dst) {
    for (int e = blockIdx.x * blockDim.x + threadIdx.x; e < N_EDGES;
         e += gridDim.x * blockDim.x) {
        int d = dst[e];
        int pos = atomicAdd(&g_cursor[d], 1);
        g_colsrc[pos] = src[e];
    }
}

// ------- weight transpose + fp16 split: W[K][N] -> Wt_hi/lo[N][K] -----------
__global__ void wsplit_kernel(const float* __restrict__ W, __half* __restrict__ Th,
                              __half* __restrict__ Tl, int K, int N) {
    int i = blockIdx.x * blockDim.x + threadIdx.x;
    if (i < K * N) {
        int k = i / N, n = i % N;
        float v = W[i];
        __half h = __float2half_rn(v);
        __half l = __float2half_rn(v - __half2float(h));
        Th[(size_t)n * K + k] = h;
        Tl[(size_t)n * K + k] = l;
    }
}

// ---------------- fp16x2 tensor-core GEMM, cp.async pipelined ----------------
// g_Hh = fp16( A @ Wt^T )  with D = A*Bhi + A*Blo (A fp16, B split to 22 bits).
// Degree normalization folded into the aggregation kernels.
// BM=128, BN=128, BK=32, 8 warps (2m x 4n), warp tile 64x32, mma.m16n8k16 f16.
// A_HALF=false: A fp32 (feat), staged raw + converted to fp16 in SMEM.
// A_HALF=true:  A already fp16 (g_Xh), cp.async lands directly in MMA layout.
#define GPAD 40   // fp16 elements per SMEM row (80 B): conflict-free ldmatrix

// dynamic SMEM byte offsets
#define AH_OFF    0u          // !A_HALF: 1 x 10240 ; A_HALF: 2 x 10240
#define AH_STR    10240u
#define RAWA_OFF  20480u      // 2 x 16384 (128x32 fp32) — !A_HALF only
#define RAWA_STR  16384u
#define BH_OFF    53248u      // 2 x 10240
#define BL_OFF    73728u
#define BSTAGE    10240u
#define GSMEM_TOT 94208

template <int NC, int KT, bool A_HALF>
__global__ __launch_bounds__(256, 2)
void gemm_fp16x2(const float* __restrict__ Aparam,
                 const __half* __restrict__ Bh,
                 const __half* __restrict__ Bl, int M) {
    extern __shared__ __align__(16) char smem[];
    const uint32_t sm = smem_u32(smem);

    const int tid = threadIdx.x;
    const int lane = tid & 31, warp = tid >> 5;
    const int wm = warp >> 2, wn = warp & 3;     // 2 x 4 warp grid
    const int bn = blockIdx.x, bm = blockIdx.y;

    float c[4][4][4];
#pragma unroll
    for (int mi = 0; mi < 4; mi++)
#pragma unroll
        for (int ni = 0; ni < 4; ni++)
#pragma unroll
            for (int q = 0; q < 4; q++) c[mi][ni][q] = 0.f;

    const int kiters = KT / 32;

    // ---- stage-issue helper ----
    auto issue_stage = [&](int kt, int stage) {
        const int k0 = kt * 32;
        if (A_HALF) {
            // A fp16: 128 rows x 32 cols = 512 x 16B chunks, 2 per thread,
            // directly into MMA-ready GPAD layout.
            const uint32_t ah = sm + AH_OFF + (uint32_t)stage * AH_STR;
#pragma unroll
            for (int j = 0; j < 2; j++) {
                const int cchunk = j * 256 + tid;         // 0..511
                const int row = cchunk >> 2, cc = cchunk & 3;   // 8 halfs per chunk
                const int grow = bm * 128 + row;
                cp_async16(ah + (uint32_t)(row * (GPAD * 2) + cc * 16),
                           g_Xh + (size_t)grow * KT + k0 + cc * 8,
                           (grow < M) ? 16 : 0);
            }
        } else {
            const uint32_t rawA = sm + RAWA_OFF + (uint32_t)stage * RAWA_STR;
#pragma unroll
            for (int j = 0; j < 4; j++) {
                const int cchunk = j * 256 + tid;         // 0..1023
                const int row = cchunk >> 3, cc = (cchunk & 7) * 4;
                const int grow = bm * 128 + row;
                cp_async16(rawA + (uint32_t)(row * 128 + cc * 4),
                           Aparam + (size_t)grow * KT + k0 + cc,
                           (grow < M) ? 16 : 0);
            }
        }
        const uint32_t bh = sm + BH_OFF + (uint32_t)stage * BSTAGE;
        const uint32_t bl = sm + BL_OFF + (uint32_t)stage * BSTAGE;
#pragma unroll
        for (int j = 0; j < 2; j++) {
            const int cchunk = j * 256 + tid;             // 0..511
            const int row = cchunk >> 2, cc = (cchunk & 3) * 8;
            const int gn = bn * 128 + row;                // NC multiple of 128
            const uint32_t doff = (uint32_t)(row * (GPAD * 2) + cc * 2);
            cp_async16(bh + doff, Bh + (size_t)gn * KT + k0 + cc, 16);
            cp_async16(bl + doff, Bl + (size_t)gn * KT + k0 + cc, 16);
        }
        cp_commit();
    };

    issue_stage(0, 0);

    for (int kt = 0; kt < kiters; kt++) {
        const int stage = kt & 1;
        cp_wait_all();          // stage kt resident
        __syncthreads();        // all warps done with kt-1's buffers

        if (kt + 1 < kiters) issue_stage(kt + 1, stage ^ 1);

        if (!A_HALF) {
            // ---- convert rawA[stage] fp32 -> fp16 into the single Ah buffer ----
            const float4* raw =
                (const float4*)(smem + RAWA_OFF + (uint32_t)stage * RAWA_STR);
            __half* AhP = (__half*)(smem + AH_OFF);
#pragma unroll
            for (int j = 0; j < 4; j++) {
                const int cchunk = j * 256 + tid;
                const int row = cchunk >> 3, col = (cchunk & 7) * 4;
                float4 v = raw[row * 8 + (cchunk & 7)];
                const int off = row * GPAD + col;
                *(__half2*)&AhP[off]     = __floats2half2_rn(v.x, v.y);
                *(__half2*)&AhP[off + 2] = __floats2half2_rn(v.z, v.w);
            }
            __syncthreads();
        }

        // ---- compute: 2 k-steps of 16, 2 MMA passes each (Bhi, Blo) ----
        const uint32_t sAh =
            A_HALF ? (sm + AH_OFF + (uint32_t)stage * AH_STR) : (sm + AH_OFF);
        const uint32_t sBh = sm + BH_OFF + (uint32_t)stage * BSTAGE;
        const uint32_t sBl = sm + BL_OFF + (uint32_t)stage * BSTAGE;
#pragma unroll
        for (int kk = 0; kk < 2; kk++) {
            const int kc = kk * 16;
            const int l16 = lane & 15;
            uint32_t bhf[4][2], blf[4][2];
#pragma unroll
            for (int ni = 0; ni < 4; ni++) {
                const uint32_t boff =
                    (uint32_t)((wn * 32 + ni * 8 + (l16 & 7)) * GPAD + kc + (l16 >> 3) * 8) * 2u;
                ldsm_x2(bhf[ni], sBh + boff);
                ldsm_x2(blf[ni], sBl + boff);
            }
#pragma unroll
            for (int mi = 0; mi < 4; mi++) {
                const uint32_t aoff =
                    (uint32_t)((wm * 64 + mi * 16 + (lane & 15)) * GPAD + kc + (lane >> 4) * 8) * 2u;
                uint32_t ahf[4];
                ldsm_x4(ahf, sAh + aoff);
#pragma unroll
                for (int ni = 0; ni < 4; ni++) {
                    mma_fp16(c[mi][ni], ahf, bhf[ni]);
                    mma_fp16(c[mi][ni], ahf, blf[ni]);
                }
            }
        }
    }

    // ---- epilogue: fp32 accum -> fp16 store (half2) ----
#pragma unroll
    for (int mi = 0; mi < 4; mi++) {
        const int r0 = bm * 128 + wm * 64 + mi * 16 + (lane >> 2);
#pragma unroll
        for (int ni = 0; ni < 4; ni++) {
            const int col = bn * 128 + wn * 32 + ni * 8 + 2 * (lane & 3);
            if (r0 < M)
                *(__half2*)(g_Hh + (size_t)r0 * NC + col) =
                    __floats2half2_rn(c[mi][ni][0], c[mi][ni][1]);
            if (r0 + 8 < M)
                *(__half2*)(g_Hh + (size_t)(r0 + 8) * NC + col) =
                    __floats2half2_rn(c[mi][ni][2], c[mi][ni][3]);
        }
    }
}

// ---------------- pull-based aggregation (atomic-free, fp16 gather) ---------
// THREADS = COLS/2: each thread owns exactly one half2 (cols 2t, 2t+1).
// L1MODE: gathered rows weighted by sout[s]; output (fp16 to g_Xh)
//         = sout[v]*relu(sin[v]*acc+b)  (prescales layer 2's input).
// else:   plain gather; output (fp32 to g_X) = sin[v]*acc + b.
template <int COLS, bool L1MODE>
__global__ __launch_bounds__(COLS / 2)
void aggregate_kernel(const float* __restrict__ bias) {
    const int v = blockIdx.x;
    const int t = threadIdx.x;
    constexpr int H2C = COLS / 2;

    float ax = 0.f, ay = 0.f;

    const int beg = g_rowptr[v];
    const int end = g_rowptr[v + 1];
    const __half2* __restrict__ Hm = (const __half2*)g_Hh;

    int e = beg;
    for (; e + 3 < end; e += 4) {
        int s0 = g_colsrc[e + 0], s1 = g_colsrc[e + 1];
        int s2 = g_colsrc[e + 2], s3 = g_colsrc[e + 3];
        float2 v0 = __half22float2(Hm[(size_t)s0 * H2C + t]);
        float2 v1 = __half22float2(Hm[(size_t)s1 * H2C + t]);
        float2 v2 = __half22float2(Hm[(size_t)s2 * H2C + t]);
        float2 v3 = __half22float2(Hm[(size_t)s3 * H2C + t]);
        if (L1MODE) {
            float w0 = __ldg(&g_sout[s0]), w1 = __ldg(&g_sout[s1]);
            float w2 = __ldg(&g_sout[s2]), w3 = __ldg(&g_sout[s3]);
            ax = fmaf(v0.x, w0, ax); ay = fmaf(v0.y, w0, ay);
            ax = fmaf(v1.x, w1, ax); ay = fmaf(v1.y, w1, ay);
            ax = fmaf(v2.x, w2, ax); ay = fmaf(v2.y, w2, ay);
            ax = fmaf(v3.x, w3, ax); ay = fmaf(v3.y, w3, ay);
        } else {
            ax += (v0.x + v1.x) + (v2.x + v3.x);
            ay += (v0.y + v1.y) + (v2.y + v3.y);
        }
    }
    for (; e < end; e++) {
        int s = g_colsrc[e];
        float2 v0 = __half22float2(Hm[(size_t)s * H2C + t]);
        if (L1MODE) {
            float w0 = __ldg(&g_sout[s]);
            ax = fmaf(v0.x, w0, ax); ay = fmaf(v0.y, w0, ay);
        } else {
            ax += v0.x;
            ay += v0.y;
        }
    }

    const float si = g_sin[v];
    float2 b = *(const float2*)(bias + 2 * t);
    float ox = fmaf(ax, si, b.x);
    float oy = fmaf(ay, si, b.y);
    if (L1MODE) {
        const float so = g_sout[v];
        ox = fmaxf(ox, 0.f) * so;
        oy = fmaxf(oy, 0.f) * so;
        *(__half2*)(g_Xh + (size_t)v * COLS + 2 * t) = __floats2half2_rn(ox, oy);
    } else {
        *(float2*)(g_X + (size_t)v * COLS + 2 * t) = make_float2(ox, oy);
    }
}

// ---------------- output head: relu(x@Wo1+bo1)@Wo2+bo2 ----------------------
__global__ __launch_bounds__(256)
void head_kernel(const float* __restrict__ Wo1, const float* __restrict__ bo1,
                 const float* __restrict__ Wo2, const float* __restrict__ bo2,
                 float* __restrict__ out) {
    __shared__ __align__(16) float sW1[H2 * ENDD];
    __shared__ float sb1[ENDD], sW2[ENDD];
    __shared__ float sx[8][H2];

    const int tid = threadIdx.x;
    for (int i = tid; i < H2 * ENDD; i += 256) sW1[i] = Wo1[i];
    if (tid < ENDD) { sb1[tid] = bo1[tid]; sW2[tid] = Wo2[tid]; }
    __syncthreads();

    const float bout = bo2[0];
    const int warp = tid >> 5, lane = tid & 31;

    for (int v = blockIdx.x * 8 + warp; v < N_NODES; v += gridDim.x * 8) {
        const float* xr = g_X + (size_t)v * H2;
#pragma unroll
        for (int q = 0; q < 4; q++) sx[warp][lane + 32 * q] = xr[lane + 32 * q];
        __syncwarp();

        float h0 = sb1[lane], h1 = sb1[lane + 32];
#pragma unroll 8
        for (int k = 0; k < H2; k++) {
            float xk = sx[warp][k];
            h0 = fmaf(xk, sW1[k * ENDD + lane], h0);
            h1 = fmaf(xk, sW1[k * ENDD + lane + 32], h1);
        }
        h0 = fmaxf(h0, 0.f);
        h1 = fmaxf(h1, 0.f);
        float p = h0 * sW2[lane] + h1 * sW2[lane + 32];
#pragma unroll
        for (int off = 16; off; off >>= 1) p += __shfl_down_sync(0xffffffffu, p, off);
        if (lane == 0) out[v] = p + bout;
        __syncwarp();
    }
}

// ---------------- launch -----------------------------------------------------
extern "C" void kernel_launch(void* const* d_in, const int* in_sizes, int n_in,
                              void* d_out, int out_size) {
    const float* feat = (const float*)d_in[0];   // [N, 64, 8] -> [N, 512]
    const int*   src  = (const int*)d_in[1];
    const int*   dst  = (const int*)d_in[2];
    const float* W1   = (const float*)d_in[3];
    const float* b1   = (const float*)d_in[4];
    const float* W2   = (const float*)d_in[5];
    const float* b2   = (const float*)d_in[6];
    const float* Wo1  = (const float*)d_in[7];
    const float* bo1  = (const float*)d_in[8];
    const float* Wo2  = (const float*)d_in[9];
    const float* bo2  = (const float*)d_in[10];
    float* out = (float*)d_out;

    const int nb_nodes = (N_NODES + 255) / 256;
    const int mtiles = (N_NODES + 127) / 128;   // 782

    __half *t1h, *t1l, *t2h, *t2l;
    cudaGetSymbolAddress((void**)&t1h, g_W1t_hi);
    cudaGetSymbolAddress((void**)&t1l, g_W1t_lo);
    cudaGetSymbolAddress((void**)&t2h, g_W2t_hi);
    cudaGetSymbolAddress((void**)&t2l, g_W2t_lo);

    cudaFuncSetAttribute(gemm_fp16x2<H1, K1, false>,
                         cudaFuncAttributeMaxDynamicSharedMemorySize, GSMEM_TOT);
    cudaFuncSetAttribute(gemm_fp16x2<H2, H1, true>,
                         cudaFuncAttributeMaxDynamicSharedMemorySize, GSMEM_TOT);

    // one-time side stream + fork/join events (reused across calls/capture)
    static cudaStream_t s_pre = nullptr;
    static cudaEvent_t ev_fork = nullptr, ev_pre = nullptr;
    if (s_pre == nullptr) {
        cudaStreamCreateWithFlags(&s_pre, cudaStreamNonBlocking);
        cudaEventCreateWithFlags(&ev_fork, cudaEventDisableTiming);
        cudaEventCreateWithFlags(&ev_pre, cudaEventDisableTiming);
    }

    // ---- fork: graph preprocessing on side stream ----
    cudaEventRecord(ev_fork, 0);
    cudaStreamWaitEvent(s_pre, ev_fork, 0);
    zero_deg_kernel<<<nb_nodes, 256, 0, s_pre>>>();
    degree_kernel<<<2048, 256, 0, s_pre>>>(src, dst);
    scales_kernel<<<nb_nodes, 256, 0, s_pre>>>();
    scan_block_kernel<<<SCAN_BLOCKS, 1024, 0, s_pre>>>();
    scan_part_kernel<<<1, 128, 0, s_pre>>>();
    scan_finish_kernel<<<nb_nodes, 256, 0, s_pre>>>();
    csr_fill_kernel<<<2048, 256, 0, s_pre>>>(src, dst);
    cudaEventRecord(ev_pre, s_pre);

    // ---- main stream: weight split + graph-independent GEMM1 ----
    wsplit_kernel<<<(K1 * H1 + 255) / 256, 256>>>(W1, t1h, t1l, K1, H1);
    wsplit_kernel<<<(H1 * H2 + 255) / 256, 256>>>(W2, t2h, t2l, H1, H2);
    {
        dim3 grid(H1 / 128, mtiles);
        gemm_fp16x2<H1, K1, false><<<grid, 256, GSMEM_TOT>>>(feat, t1h, t1l, N_NODES);
    }

    // ---- join: aggregation needs CSR + scales + GEMM1 ----
    cudaStreamWaitEvent(0, ev_pre, 0);
    aggregate_kernel<H1, true><<<N_NODES, H1 / 2>>>(b1);

    // layer 2 (fp16 A directly from g_Xh; agg2 plain gather)
    {
        dim3 grid(H2 / 128, mtiles);
        gemm_fp16x2<H2, H1, true><<<grid, 256, GSMEM_TOT>>>(nullptr, t2h, t2l, N_NODES);
    }
    aggregate_kernel<H2, false><<<N_NODES, H2 / 2>>>(b2);

    // head
    head_kernel<<<296, 256>>>(Wo1, bo1, Wo2, bo2, out);
}

// round 11
// speedup vs baseline: 2.1974x; 1.0973x over previous
#include <cuda_runtime.h>
#include <cuda_bf16.h>
#include <cuda_fp16.h>
#include <cstdint>

#define N_NODES 100000
#define N_EDGES 3200000
#define K1 512      // in_dim * n_seq
#define H1 256
#define H2 128
#define ENDD 64

// ---------------- scratch (device globals; no allocation allowed) -----------
__device__ __half g_Hh[(size_t)N_NODES * H1];  // GEMM outputs, fp16 (agg input)
__device__ __half g_Xh[(size_t)N_NODES * H1];  // layer-2 input, fp16 (agg1 out)
__device__ float g_X[(size_t)N_NODES * H1];    // agg2 output (fp32, head input)
__device__ int   g_deg_out[N_NODES];
__device__ int   g_deg_in[N_NODES];
__device__ float g_sout[N_NODES];
__device__ float g_sin[N_NODES];
__device__ int   g_rowptr[N_NODES + 1];
__device__ int   g_cursor[N_NODES];
__device__ int   g_colsrc[N_EDGES];
#define SCAN_BLOCKS ((N_NODES + 1023) / 1024)   // 98
__device__ int   g_part[128];
__device__ int   g_poff[128];
// transposed fp16 weights: Wt[n][k]
__device__ __half g_W1t[H1 * K1];
__device__ __half g_W2t[H2 * H1];

// ---------------- PTX helpers ------------------------------------------------
__device__ __forceinline__ uint32_t smem_u32(const void* p) {
    uint32_t a;
    asm("{ .reg .u64 t; cvta.to.shared.u64 t, %1; cvt.u32.u64 %0, t; }"
        : "=r"(a) : "l"(p));
    return a;
}

__device__ __forceinline__ void ldsm_x4(uint32_t (&r)[4], uint32_t a) {
    asm volatile("ldmatrix.sync.aligned.m8n8.x4.shared.b16 {%0,%1,%2,%3}, [%4];"
                 : "=r"(r[0]), "=r"(r[1]), "=r"(r[2]), "=r"(r[3]) : "r"(a));
}

__device__ __forceinline__ void ldsm_x2(uint32_t (&r)[2], uint32_t a) {
    asm volatile("ldmatrix.sync.aligned.m8n8.x2.shared.b16 {%0,%1}, [%2];"
                 : "=r"(r[0]), "=r"(r[1]) : "r"(a));
}

__device__ __forceinline__ void mma_fp16(float (&d)[4], const uint32_t (&a)[4],
                                         const uint32_t (&b)[2]) {
    asm volatile(
        "mma.sync.aligned.m16n8k16.row.col.f32.f16.f16.f32 "
        "{%0,%1,%2,%3}, {%4,%5,%6,%7}, {%8,%9}, {%0,%1,%2,%3};"
        : "+f"(d[0]), "+f"(d[1]), "+f"(d[2]), "+f"(d[3])
        : "r"(a[0]), "r"(a[1]), "r"(a[2]), "r"(a[3]), "r"(b[0]), "r"(b[1]));
}

__device__ __forceinline__ void cp_async16(uint32_t smem_dst, const void* gsrc,
                                           int src_bytes) {
    asm volatile("cp.async.cg.shared.global [%0], [%1], 16, %2;"
                 :: "r"(smem_dst), "l"(gsrc), "r"(src_bytes));
}
__device__ __forceinline__ void cp_commit() {
    asm volatile("cp.async.commit_group;");
}
__device__ __forceinline__ void cp_wait_all() {
    asm volatile("cp.async.wait_group 0;");
}

// ---------------- graph preprocessing ---------------------------------------
__global__ void zero_deg_kernel() {
    int i = blockIdx.x * blockDim.x + threadIdx.x;
    if (i < N_NODES) { g_deg_out[i] = 0; g_deg_in[i] = 0; }
}

__global__ void degree_kernel(const int* __restrict__ src, const int* __restrict__ dst) {
    for (int e = blockIdx.x * blockDim.x + threadIdx.x; e < N_EDGES;
         e += gridDim.x * blockDim.x) {
        atomicAdd(&g_deg_out[src[e]], 1);
        atomicAdd(&g_deg_in[dst[e]], 1);
    }
}

__global__ void scales_kernel() {
    int i = blockIdx.x * blockDim.x + threadIdx.x;
    if (i < N_NODES) {
        g_sout[i] = rsqrtf((float)max(g_deg_out[i], 1));
        g_sin[i]  = rsqrtf((float)max(g_deg_in[i], 1));
    }
}

__global__ void scan_block_kernel() {
    __shared__ int sh[1024];
    int t = threadIdx.x;
    int i = blockIdx.x * 1024 + t;
    int v = (i < N_NODES) ? g_deg_in[i] : 0;
    sh[t] = v;
    __syncthreads();
    for (int off = 1; off < 1024; off <<= 1) {
        int x = sh[t];
        int y = (t >= off) ? sh[t - off] : 0;
        __syncthreads();
        sh[t] = x + y;
        __syncthreads();
    }
    if (i < N_NODES) g_rowptr[i] = sh[t] - v;
    if (t == 1023) g_part[blockIdx.x] = sh[1023];
}

__global__ void scan_part_kernel() {
    __shared__ int sh[128];
    int t = threadIdx.x;
    int v = (t < SCAN_BLOCKS) ? g_part[t] : 0;
    sh[t] = v;
    __syncthreads();
    for (int off = 1; off < 128; off <<= 1) {
        int x = sh[t];
        int y = (t >= off) ? sh[t - off] : 0;
        __syncthreads();
        sh[t] = x + y;
        __syncthreads();
    }
    g_poff[t] = sh[t] - v;
}

__global__ void scan_finish_kernel() {
    int i = blockIdx.x * blockDim.x + threadIdx.x;
    if (i < N_NODES) {
        int r = g_rowptr[i] + g_poff[i >> 10];
        g_rowptr[i] = r;
        g_cursor[i] = r;
    }
    if (i == 0) g_rowptr[N_NODES] = N_EDGES;
}

__global__ void csr_fill_kernel(const int* __restrict__ src, const int* __restrict__ dst) {
    for (int e = blockIdx.x * blockDim.x + threadIdx.x; e < N_EDGES;
         e += gridDim.x * blockDim.x) {
        int d = dst[e];
        int pos = atomicAdd(&g_cursor[d], 1);
        g_colsrc[pos] = src[e];
    }
}

// ------- weight transpose to fp16: W[K][N] -> Wt[N][K] ----------------------
__global__ void wconv_kernel(const float* __restrict__ W, __half* __restrict__ T,
                             int K, int N) {
    int i = blockIdx.x * blockDim.x + threadIdx.x;
    if (i < K * N) {
        int k = i / N, n = i % N;
        T[(size_t)n * K + k] = __float2half_rn(W[i]);
    }
}

// ---------------- fp16 tensor-core GEMM, cp.async pipelined ------------------
// g_Hh = fp16( A @ Wt^T ).  Degree normalization folded into aggregation.
// BM=128, BN=128, BK=32, 8 warps (2m x 4n), warp tile 64x32, mma.m16n8k16 f16.
// A_HALF=false: A fp32 (feat), staged raw + converted to fp16 in SMEM.
// A_HALF=true:  A already fp16 (g_Xh), cp.async lands directly in MMA layout.
#define GPAD 40   // fp16 elements per SMEM row (80 B): conflict-free ldmatrix

// dynamic SMEM byte offsets
#define AH_OFF    0u          // !A_HALF: 1 x 10240 ; A_HALF: 2 x 10240
#define AH_STR    10240u
#define RAWA_OFF  20480u      // 2 x 16384 (128x32 fp32) — !A_HALF only
#define RAWA_STR  16384u
#define BH_OFF    53248u      // 2 x 10240
#define BSTAGE    10240u
#define GSMEM_TOT 73728

template <int NC, int KT, bool A_HALF>
__global__ __launch_bounds__(256, 2)
void gemm_fp16(const float* __restrict__ Aparam,
               const __half* __restrict__ Bh, int M) {
    extern __shared__ __align__(16) char smem[];
    const uint32_t sm = smem_u32(smem);

    const int tid = threadIdx.x;
    const int lane = tid & 31, warp = tid >> 5;
    const int wm = warp >> 2, wn = warp & 3;     // 2 x 4 warp grid
    const int bn = blockIdx.x, bm = blockIdx.y;

    float c[4][4][4];
#pragma unroll
    for (int mi = 0; mi < 4; mi++)
#pragma unroll
        for (int ni = 0; ni < 4; ni++)
#pragma unroll
            for (int q = 0; q < 4; q++) c[mi][ni][q] = 0.f;

    const int kiters = KT / 32;

    // ---- stage-issue helper ----
    auto issue_stage = [&](int kt, int stage) {
        const int k0 = kt * 32;
        if (A_HALF) {
            const uint32_t ah = sm + AH_OFF + (uint32_t)stage * AH_STR;
#pragma unroll
            for (int j = 0; j < 2; j++) {
                const int cchunk = j * 256 + tid;         // 0..511
                const int row = cchunk >> 2, cc = cchunk & 3;   // 8 halfs per chunk
                const int grow = bm * 128 + row;
                cp_async16(ah + (uint32_t)(row * (GPAD * 2) + cc * 16),
                           g_Xh + (size_t)grow * KT + k0 + cc * 8,
                           (grow < M) ? 16 : 0);
            }
        } else {
            const uint32_t rawA = sm + RAWA_OFF + (uint32_t)stage * RAWA_STR;
#pragma unroll
            for (int j = 0; j < 4; j++) {
                const int cchunk = j * 256 + tid;         // 0..1023
                const int row = cchunk >> 3, cc = (cchunk & 7) * 4;
                const int grow = bm * 128 + row;
                cp_async16(rawA + (uint32_t)(row * 128 + cc * 4),
                           Aparam + (size_t)grow * KT + k0 + cc,
                           (grow < M) ? 16 : 0);
            }
        }
        const uint32_t bh = sm + BH_OFF + (uint32_t)stage * BSTAGE;
#pragma unroll
        for (int j = 0; j < 2; j++) {
            const int cchunk = j * 256 + tid;             // 0..511
            const int row = cchunk >> 2, cc = (cchunk & 3) * 8;
            const int gn = bn * 128 + row;                // NC multiple of 128
            cp_async16(bh + (uint32_t)(row * (GPAD * 2) + cc * 2),
                       Bh + (size_t)gn * KT + k0 + cc, 16);
        }
        cp_commit();
    };

    issue_stage(0, 0);

    for (int kt = 0; kt < kiters; kt++) {
        const int stage = kt & 1;
        cp_wait_all();          // stage kt resident
        __syncthreads();        // all warps done with kt-1's buffers

        if (kt + 1 < kiters) issue_stage(kt + 1, stage ^ 1);

        if (!A_HALF) {
            // ---- convert rawA[stage] fp32 -> fp16 into the single Ah buffer ----
            const float4* raw =
                (const float4*)(smem + RAWA_OFF + (uint32_t)stage * RAWA_STR);
            __half* AhP = (__half*)(smem + AH_OFF);
#pragma unroll
            for (int j = 0; j < 4; j++) {
                const int cchunk = j * 256 + tid;
                const int row = cchunk >> 3, col = (cchunk & 7) * 4;
                float4 v = raw[row * 8 + (cchunk & 7)];
                const int off = row * GPAD + col;
                *(__half2*)&AhP[off]     = __floats2half2_rn(v.x, v.y);
                *(__half2*)&AhP[off + 2] = __floats2half2_rn(v.z, v.w);
            }
            __syncthreads();
        }

        // ---- compute: 2 k-steps of 16, single fp16 MMA pass ----
        const uint32_t sAh =
            A_HALF ? (sm + AH_OFF + (uint32_t)stage * AH_STR) : (sm + AH_OFF);
        const uint32_t sBh = sm + BH_OFF + (uint32_t)stage * BSTAGE;
#pragma unroll
        for (int kk = 0; kk < 2; kk++) {
            const int kc = kk * 16;
            const int l16 = lane & 15;
            uint32_t bhf[4][2];
#pragma unroll
            for (int ni = 0; ni < 4; ni++) {
                const uint32_t boff =
                    (uint32_t)((wn * 32 + ni * 8 + (l16 & 7)) * GPAD + kc + (l16 >> 3) * 8) * 2u;
                ldsm_x2(bhf[ni], sBh + boff);
            }
#pragma unroll
            for (int mi = 0; mi < 4; mi++) {
                const uint32_t aoff =
                    (uint32_t)((wm * 64 + mi * 16 + (lane & 15)) * GPAD + kc + (lane >> 4) * 8) * 2u;
                uint32_t ahf[4];
                ldsm_x4(ahf, sAh + aoff);
#pragma unroll
                for (int ni = 0; ni < 4; ni++)
                    mma_fp16(c[mi][ni], ahf, bhf[ni]);
            }
        }
    }

    // ---- epilogue: fp32 accum -> fp16 store (half2) ----
#pragma unroll
    for (int mi = 0; mi < 4; mi++) {
        const int r0 = bm * 128 + wm * 64 + mi * 16 + (lane >> 2);
#pragma unroll
        for (int ni = 0; ni < 4; ni++) {
            const int col = bn * 128 + wn * 32 + ni * 8 + 2 * (lane & 3);
            if (r0 < M)
                *(__half2*)(g_Hh + (size_t)r0 * NC + col) =
                    __floats2half2_rn(c[mi][ni][0], c[mi][ni][1]);
            if (r0 + 8 < M)
                *(__half2*)(g_Hh + (size_t)(r0 + 8) * NC + col) =
                    __floats2half2_rn(c[mi][ni][2], c[mi][ni][3]);
        }
    }
}

// ---------------- pull-based aggregation (atomic-free, fp16 gather) ---------
// THREADS = COLS/2: each thread owns exactly one half2 (cols 2t, 2t+1).
// L1MODE: gathered rows weighted by sout[s]; output (fp16 to g_Xh)
//         = sout[v]*relu(sin[v]*acc+b)  (prescales layer 2's input).
// else:   plain gather; output (fp32 to g_X) = sin[v]*acc + b.
template <int COLS, bool L1MODE>
__global__ __launch_bounds__(COLS / 2)
void aggregate_kernel(const float* __restrict__ bias) {
    const int v = blockIdx.x;
    const int t = threadIdx.x;
    constexpr int H2C = COLS / 2;

    float ax = 0.f, ay = 0.f;

    const int beg = g_rowptr[v];
    const int end = g_rowptr[v + 1];
    const __half2* __restrict__ Hm = (const __half2*)g_Hh;

    int e = beg;
    for (; e + 3 < end; e += 4) {
        int s0 = g_colsrc[e + 0], s1 = g_colsrc[e + 1];
        int s2 = g_colsrc[e + 2], s3 = g_colsrc[e + 3];
        float2 v0 = __half22float2(Hm[(size_t)s0 * H2C + t]);
        float2 v1 = __half22float2(Hm[(size_t)s1 * H2C + t]);
        float2 v2 = __half22float2(Hm[(size_t)s2 * H2C + t]);
        float2 v3 = __half22float2(Hm[(size_t)s3 * H2C + t]);
        if (L1MODE) {
            float w0 = __ldg(&g_sout[s0]), w1 = __ldg(&g_sout[s1]);
            float w2 = __ldg(&g_sout[s2]), w3 = __ldg(&g_sout[s3]);
            ax = fmaf(v0.x, w0, ax); ay = fmaf(v0.y, w0, ay);
            ax = fmaf(v1.x, w1, ax); ay = fmaf(v1.y, w1, ay);
            ax = fmaf(v2.x, w2, ax); ay = fmaf(v2.y, w2, ay);
            ax = fmaf(v3.x, w3, ax); ay = fmaf(v3.y, w3, ay);
        } else {
            ax += (v0.x + v1.x) + (v2.x + v3.x);
            ay += (v0.y + v1.y) + (v2.y + v3.y);
        }
    }
    for (; e < end; e++) {
        int s = g_colsrc[e];
        float2 v0 = __half22float2(Hm[(size_t)s * H2C + t]);
        if (L1MODE) {
            float w0 = __ldg(&g_sout[s]);
            ax = fmaf(v0.x, w0, ax); ay = fmaf(v0.y, w0, ay);
        } else {
            ax += v0.x;
            ay += v0.y;
        }
    }

    const float si = g_sin[v];
    float2 b = *(const float2*)(bias + 2 * t);
    float ox = fmaf(ax, si, b.x);
    float oy = fmaf(ay, si, b.y);
    if (L1MODE) {
        const float so = g_sout[v];
        ox = fmaxf(ox, 0.f) * so;
        oy = fmaxf(oy, 0.f) * so;
        *(__half2*)(g_Xh + (size_t)v * COLS + 2 * t) = __floats2half2_rn(ox, oy);
    } else {
        *(float2*)(g_X + (size_t)v * COLS + 2 * t) = make_float2(ox, oy);
    }
}

// ---------------- output head: relu(x@Wo1+bo1)@Wo2+bo2 ----------------------
__global__ __launch_bounds__(256)
void head_kernel(const float* __restrict__ Wo1, const float* __restrict__ bo1,
                 const float* __restrict__ Wo2, const float* __restrict__ bo2,
                 float* __restrict__ out) {
    __shared__ __align__(16) float sW1[H2 * ENDD];
    __shared__ float sb1[ENDD], sW2[ENDD];
    __shared__ float sx[8][H2];

    const int tid = threadIdx.x;
    for (int i = tid; i < H2 * ENDD; i += 256) sW1[i] = Wo1[i];
    if (tid < ENDD) { sb1[tid] = bo1[tid]; sW2[tid] = Wo2[tid]; }
    __syncthreads();

    const float bout = bo2[0];
    const int warp = tid >> 5, lane = tid & 31;

    for (int v = blockIdx.x * 8 + warp; v < N_NODES; v += gridDim.x * 8) {
        const float* xr = g_X + (size_t)v * H2;
#pragma unroll
        for (int q = 0; q < 4; q++) sx[warp][lane + 32 * q] = xr[lane + 32 * q];
        __syncwarp();

        float h0 = sb1[lane], h1 = sb1[lane + 32];
#pragma unroll 8
        for (int k = 0; k < H2; k++) {
            float xk = sx[warp][k];
            h0 = fmaf(xk, sW1[k * ENDD + lane], h0);
            h1 = fmaf(xk, sW1[k * ENDD + lane + 32], h1);
        }
        h0 = fmaxf(h0, 0.f);
        h1 = fmaxf(h1, 0.f);
        float p = h0 * sW2[lane] + h1 * sW2[lane + 32];
#pragma unroll
        for (int off = 16; off; off >>= 1) p += __shfl_down_sync(0xffffffffu, p, off);
        if (lane == 0) out[v] = p + bout;
        __syncwarp();
    }
}

// ---------------- launch -----------------------------------------------------
extern "C" void kernel_launch(void* const* d_in, const int* in_sizes, int n_in,
                              void* d_out, int out_size) {
    const float* feat = (const float*)d_in[0];   // [N, 64, 8] -> [N, 512]
    const int*   src  = (const int*)d_in[1];
    const int*   dst  = (const int*)d_in[2];
    const float* W1   = (const float*)d_in[3];
    const float* b1   = (const float*)d_in[4];
    const float* W2   = (const float*)d_in[5];
    const float* b2   = (const float*)d_in[6];
    const float* Wo1  = (const float*)d_in[7];
    const float* bo1  = (const float*)d_in[8];
    const float* Wo2  = (const float*)d_in[9];
    const float* bo2  = (const float*)d_in[10];
    float* out = (float*)d_out;

    const int nb_nodes = (N_NODES + 255) / 256;
    const int mtiles = (N_NODES + 127) / 128;   // 782

    __half *t1, *t2;
    cudaGetSymbolAddress((void**)&t1, g_W1t);
    cudaGetSymbolAddress((void**)&t2, g_W2t);

    cudaFuncSetAttribute(gemm_fp16<H1, K1, false>,
                         cudaFuncAttributeMaxDynamicSharedMemorySize, GSMEM_TOT);
    cudaFuncSetAttribute(gemm_fp16<H2, H1, true>,
                         cudaFuncAttributeMaxDynamicSharedMemorySize, GSMEM_TOT);

    // one-time side stream + fork/join events (reused across calls/capture)
    static cudaStream_t s_pre = nullptr;
    static cudaEvent_t ev_fork = nullptr, ev_pre = nullptr;
    if (s_pre == nullptr) {
        cudaStreamCreateWithFlags(&s_pre, cudaStreamNonBlocking);
        cudaEventCreateWithFlags(&ev_fork, cudaEventDisableTiming);
        cudaEventCreateWithFlags(&ev_pre, cudaEventDisableTiming);
    }

    // ---- fork: graph preprocessing on side stream ----
    cudaEventRecord(ev_fork, 0);
    cudaStreamWaitEvent(s_pre, ev_fork, 0);
    zero_deg_kernel<<<nb_nodes, 256, 0, s_pre>>>();
    degree_kernel<<<2048, 256, 0, s_pre>>>(src, dst);
    scales_kernel<<<nb_nodes, 256, 0, s_pre>>>();
    scan_block_kernel<<<SCAN_BLOCKS, 1024, 0, s_pre>>>();
    scan_part_kernel<<<1, 128, 0, s_pre>>>();
    scan_finish_kernel<<<nb_nodes, 256, 0, s_pre>>>();
    csr_fill_kernel<<<2048, 256, 0, s_pre>>>(src, dst);
    cudaEventRecord(ev_pre, s_pre);

    // ---- main stream: weight transpose + graph-independent GEMM1 ----
    wconv_kernel<<<(K1 * H1 + 255) / 256, 256>>>(W1, t1, K1, H1);
    wconv_kernel<<<(H1 * H2 + 255) / 256, 256>>>(W2, t2, H1, H2);
    {
        dim3 grid(H1 / 128, mtiles);
        gemm_fp16<H1, K1, false><<<grid, 256, GSMEM_TOT>>>(feat, t1, N_NODES);
    }

    // ---- join: aggregation needs CSR + scales + GEMM1 ----
    cudaStreamWaitEvent(0, ev_pre, 0);
    aggregate_kernel<H1, true><<<N_NODES, H1 / 2>>>(b1);

    // layer 2 (fp16 A directly from g_Xh; agg2 plain gather)
    {
        dim3 grid(H2 / 128, mtiles);
        gemm_fp16<H2, H1, true><<<grid, 256, GSMEM_TOT>>>(nullptr, t2, N_NODES);
    }
    aggregate_kernel<H2, false><<<N_NODES, H2 / 2>>>(b2);

    // head
    head_kernel<<<296, 256>>>(Wo1, bo1, Wo2, bo2, out);
}

// round 12
// speedup vs baseline: 2.5953x; 1.1811x over previous
#include <cuda_runtime.h>
#include <cuda_bf16.h>
#include <cuda_fp16.h>
#include <cstdint>

#define N_NODES 100000
#define N_EDGES 3200000
#define K1 512      // in_dim * n_seq
#define H1 256
#define H2 128
#define ENDD 64

// ---------------- scratch (device globals; no allocation allowed) -----------
__device__ __half g_Hh[(size_t)N_NODES * H1];  // GEMM outputs, fp16 (agg input)
__device__ __half g_Xh[(size_t)N_NODES * H1];  // layer-2 GEMM input (agg1 out)
__device__ __half g_Xh2[(size_t)N_NODES * H2]; // head GEMM input (agg2 out)
__device__ int   g_deg_out[N_NODES];
__device__ int   g_deg_in[N_NODES];
__device__ float g_sout[N_NODES];
__device__ float g_sin[N_NODES];
__device__ int   g_rowptr[N_NODES + 1];
__device__ int   g_cursor[N_NODES];
__device__ int   g_colsrc[N_EDGES];
#define SCAN_BLOCKS ((N_NODES + 1023) / 1024)   // 98
__device__ int   g_part[128];
__device__ int   g_poff[128];
// transposed fp16 weights: Wt[n][k]
__device__ __half g_W1t[H1 * K1];
__device__ __half g_W2t[H2 * H1];
__device__ __half g_Wo1t[ENDD * H2];

// ---------------- PTX helpers ------------------------------------------------
__device__ __forceinline__ uint32_t smem_u32(const void* p) {
    uint32_t a;
    asm("{ .reg .u64 t; cvta.to.shared.u64 t, %1; cvt.u32.u64 %0, t; }"
        : "=r"(a) : "l"(p));
    return a;
}

__device__ __forceinline__ void ldsm_x4(uint32_t (&r)[4], uint32_t a) {
    asm volatile("ldmatrix.sync.aligned.m8n8.x4.shared.b16 {%0,%1,%2,%3}, [%4];"
                 : "=r"(r[0]), "=r"(r[1]), "=r"(r[2]), "=r"(r[3]) : "r"(a));
}

__device__ __forceinline__ void ldsm_x2(uint32_t (&r)[2], uint32_t a) {
    asm volatile("ldmatrix.sync.aligned.m8n8.x2.shared.b16 {%0,%1}, [%2];"
                 : "=r"(r[0]), "=r"(r[1]) : "r"(a));
}

__device__ __forceinline__ void mma_fp16(float (&d)[4], const uint32_t (&a)[4],
                                         const uint32_t (&b)[2]) {
    asm volatile(
        "mma.sync.aligned.m16n8k16.row.col.f32.f16.f16.f32 "
        "{%0,%1,%2,%3}, {%4,%5,%6,%7}, {%8,%9}, {%0,%1,%2,%3};"
        : "+f"(d[0]), "+f"(d[1]), "+f"(d[2]), "+f"(d[3])
        : "r"(a[0]), "r"(a[1]), "r"(a[2]), "r"(a[3]), "r"(b[0]), "r"(b[1]));
}

__device__ __forceinline__ void cp_async16(uint32_t smem_dst, const void* gsrc,
                                           int src_bytes) {
    asm volatile("cp.async.cg.shared.global [%0], [%1], 16, %2;"
                 :: "r"(smem_dst), "l"(gsrc), "r"(src_bytes));
}
__device__ __forceinline__ void cp_commit() {
    asm volatile("cp.async.commit_group;");
}
__device__ __forceinline__ void cp_wait_all() {
    asm volatile("cp.async.wait_group 0;");
}

// ---------------- graph preprocessing ---------------------------------------
__global__ void zero_deg_kernel() {
    int i = blockIdx.x * blockDim.x + threadIdx.x;
    if (i < N_NODES) { g_deg_out[i] = 0; g_deg_in[i] = 0; }
}

__global__ void degree_kernel(const int* __restrict__ src, const int* __restrict__ dst) {
    for (int e = blockIdx.x * blockDim.x + threadIdx.x; e < N_EDGES;
         e += gridDim.x * blockDim.x) {
        atomicAdd(&g_deg_out[src[e]], 1);
        atomicAdd(&g_deg_in[dst[e]], 1);
    }
}

__global__ void scales_kernel() {
    int i = blockIdx.x * blockDim.x + threadIdx.x;
    if (i < N_NODES) {
        g_sout[i] = rsqrtf((float)max(g_deg_out[i], 1));
        g_sin[i]  = rsqrtf((float)max(g_deg_in[i], 1));
    }
}

__global__ void scan_block_kernel() {
    __shared__ int sh[1024];
    int t = threadIdx.x;
    int i = blockIdx.x * 1024 + t;
    int v = (i < N_NODES) ? g_deg_in[i] : 0;
    sh[t] = v;
    __syncthreads();
    for (int off = 1; off < 1024; off <<= 1) {
        int x = sh[t];
        int y = (t >= off) ? sh[t - off] : 0;
        __syncthreads();
        sh[t] = x + y;
        __syncthreads();
    }
    if (i < N_NODES) g_rowptr[i] = sh[t] - v;
    if (t == 1023) g_part[blockIdx.x] = sh[1023];
}

__global__ void scan_part_kernel() {
    __shared__ int sh[128];
    int t = threadIdx.x;
    int v = (t < SCAN_BLOCKS) ? g_part[t] : 0;
    sh[t] = v;
    __syncthreads();
    for (int off = 1; off < 128; off <<= 1) {
        int x = sh[t];
        int y = (t >= off) ? sh[t - off] : 0;
        __syncthreads();
        sh[t] = x + y;
        __syncthreads();
    }
    g_poff[t] = sh[t] - v;
}

__global__ void scan_finish_kernel() {
    int i = blockIdx.x * blockDim.x + threadIdx.x;
    if (i < N_NODES) {
        int r = g_rowptr[i] + g_poff[i >> 10];
        g_rowptr[i] = r;
        g_cursor[i] = r;
    }
    if (i == 0) g_rowptr[N_NODES] = N_EDGES;
}

__global__ void csr_fill_kernel(const int* __restrict__ src, const int* __restrict__ dst) {
    for (int e = blockIdx.x * blockDim.x + threadIdx.x; e < N_EDGES;
         e += gridDim.x * blockDim.x) {
        int d = dst[e];
        int pos = atomicAdd(&g_cursor[d], 1);
        g_colsrc[pos] = src[e];
    }
}

// ------- weight transpose to fp16: W[K][N] -> Wt[N][K] ----------------------
__global__ void wconv_kernel(const float* __restrict__ W, __half* __restrict__ T,
                             int K, int N) {
    int i = blockIdx.x * blockDim.x + threadIdx.x;
    if (i < K * N) {
        int k = i / N, n = i % N;
        T[(size_t)n * K + k] = __float2half_rn(W[i]);
    }
}

#define GPAD 40   // fp16 elements per SMEM row (80 B): conflict-free ldmatrix

// ---------------- GEMM1: fp32 A (feat), BM=64 x BN=256(all of N), BK=32 ------
// 8 warps (2m x 4n), warp tile 32x64, single bn tile => A read exactly once.
#define G1_AH_OFF   0u          // 64 x GPAD fp16 = 5120 (single)
#define G1_RAWA_OFF 5120u       // 2 x 8192 (64x32 fp32)
#define G1_RAWA_STR 8192u
#define G1_BH_OFF   21504u      // 2 x 20480 (256 x GPAD fp16)
#define G1_BSTAGE   20480u
#define G1_SMEM     62464

__global__ __launch_bounds__(256, 2)
void gemm1_wide(const float* __restrict__ A, const __half* __restrict__ Bh, int M) {
    extern __shared__ __align__(16) char smem[];
    const uint32_t sm = smem_u32(smem);

    const int tid = threadIdx.x;
    const int lane = tid & 31, warp = tid >> 5;
    const int wm = warp >> 2, wn = warp & 3;     // 2 x 4 warp grid
    const int bm = blockIdx.x;

    float c[2][8][4];
#pragma unroll
    for (int mi = 0; mi < 2; mi++)
#pragma unroll
        for (int ni = 0; ni < 8; ni++)
#pragma unroll
            for (int q = 0; q < 4; q++) c[mi][ni][q] = 0.f;

    const int kiters = K1 / 32;    // 16

    auto issue_stage = [&](int kt, int stage) {
        const int k0 = kt * 32;
        const uint32_t rawA = sm + G1_RAWA_OFF + (uint32_t)stage * G1_RAWA_STR;
#pragma unroll
        for (int j = 0; j < 2; j++) {
            const int cchunk = j * 256 + tid;             // 0..511
            const int row = cchunk >> 3, cc = (cchunk & 7) * 4;
            const int grow = bm * 64 + row;
            cp_async16(rawA + (uint32_t)(row * 128 + cc * 4),
                       A + (size_t)grow * K1 + k0 + cc, (grow < M) ? 16 : 0);
        }
        const uint32_t bh = sm + G1_BH_OFF + (uint32_t)stage * G1_BSTAGE;
#pragma unroll
        for (int j = 0; j < 4; j++) {
            const int cchunk = j * 256 + tid;             // 0..1023
            const int row = cchunk >> 2, cc = (cchunk & 3) * 8;   // row 0..255
            cp_async16(bh + (uint32_t)(row * (GPAD * 2) + cc * 2),
                       Bh + (size_t)row * K1 + k0 + cc, 16);
        }
        cp_commit();
    };

    issue_stage(0, 0);

    for (int kt = 0; kt < kiters; kt++) {
        const int stage = kt & 1;
        cp_wait_all();
        __syncthreads();

        if (kt + 1 < kiters) issue_stage(kt + 1, stage ^ 1);

        // convert rawA[stage] fp32 -> fp16 into single Ah buffer
        {
            const float4* raw =
                (const float4*)(smem + G1_RAWA_OFF + (uint32_t)stage * G1_RAWA_STR);
            __half* AhP = (__half*)(smem + G1_AH_OFF);
#pragma unroll
            for (int j = 0; j < 2; j++) {
                const int cchunk = j * 256 + tid;
                const int row = cchunk >> 3, col = (cchunk & 7) * 4;
                float4 v = raw[row * 8 + (cchunk & 7)];
                const int off = row * GPAD + col;
                *(__half2*)&AhP[off]     = __floats2half2_rn(v.x, v.y);
                *(__half2*)&AhP[off + 2] = __floats2half2_rn(v.z, v.w);
            }
        }
        __syncthreads();

        const uint32_t sAh = sm + G1_AH_OFF;
        const uint32_t sBh = sm + G1_BH_OFF + (uint32_t)stage * G1_BSTAGE;
#pragma unroll
        for (int kk = 0; kk < 2; kk++) {
            const int kc = kk * 16;
            const int l16 = lane & 15;
            uint32_t bhf[8][2];
#pragma unroll
            for (int ni = 0; ni < 8; ni++) {
                const uint32_t boff =
                    (uint32_t)((wn * 64 + ni * 8 + (l16 & 7)) * GPAD + kc + (l16 >> 3) * 8) * 2u;
                ldsm_x2(bhf[ni], sBh + boff);
            }
#pragma unroll
            for (int mi = 0; mi < 2; mi++) {
                const uint32_t aoff =
                    (uint32_t)((wm * 32 + mi * 16 + (lane & 15)) * GPAD + kc + (lane >> 4) * 8) * 2u;
                uint32_t ahf[4];
                ldsm_x4(ahf, sAh + aoff);
#pragma unroll
                for (int ni = 0; ni < 8; ni++)
                    mma_fp16(c[mi][ni], ahf, bhf[ni]);
            }
        }
    }

    // epilogue: fp16 store
#pragma unroll
    for (int mi = 0; mi < 2; mi++) {
        const int r0 = bm * 64 + wm * 32 + mi * 16 + (lane >> 2);
#pragma unroll
        for (int ni = 0; ni < 8; ni++) {
            const int col = wn * 64 + ni * 8 + 2 * (lane & 3);
            if (r0 < M)
                *(__half2*)(g_Hh + (size_t)r0 * H1 + col) =
                    __floats2half2_rn(c[mi][ni][0], c[mi][ni][1]);
            if (r0 + 8 < M)
                *(__half2*)(g_Hh + (size_t)(r0 + 8) * H1 + col) =
                    __floats2half2_rn(c[mi][ni][2], c[mi][ni][3]);
        }
    }
}

// ---------------- GEMM2: fp16 A (g_Xh), BM=128 x BN=128, BK=32 ---------------
#define G2_AH_OFF  0u           // 2 x 10240
#define G2_AH_STR  10240u
#define G2_BH_OFF  20480u       // 2 x 10240
#define G2_BSTAGE  10240u
#define G2_SMEM    40960

__global__ __launch_bounds__(256, 2)
void gemm2_fp16(const __half* __restrict__ Bh, int M) {
    extern __shared__ __align__(16) char smem[];
    const uint32_t sm = smem_u32(smem);

    const int tid = threadIdx.x;
    const int lane = tid & 31, warp = tid >> 5;
    const int wm = warp >> 2, wn = warp & 3;
    const int bm = blockIdx.x;

    float c[4][4][4];
#pragma unroll
    for (int mi = 0; mi < 4; mi++)
#pragma unroll
        for (int ni = 0; ni < 4; ni++)
#pragma unroll
            for (int q = 0; q < 4; q++) c[mi][ni][q] = 0.f;

    const int kiters = H1 / 32;   // 8

    auto issue_stage = [&](int kt, int stage) {
        const int k0 = kt * 32;
        const uint32_t ah = sm + G2_AH_OFF + (uint32_t)stage * G2_AH_STR;
#pragma unroll
        for (int j = 0; j < 2; j++) {
            const int cchunk = j * 256 + tid;         // 0..511
            const int row = cchunk >> 2, cc = cchunk & 3;
            const int grow = bm * 128 + row;
            cp_async16(ah + (uint32_t)(row * (GPAD * 2) + cc * 16),
                       g_Xh + (size_t)grow * H1 + k0 + cc * 8,
                       (grow < M) ? 16 : 0);
        }
        const uint32_t bh = sm + G2_BH_OFF + (uint32_t)stage * G2_BSTAGE;
#pragma unroll
        for (int j = 0; j < 2; j++) {
            const int cchunk = j * 256 + tid;
            const int row = cchunk >> 2, cc = (cchunk & 3) * 8;
            cp_async16(bh + (uint32_t)(row * (GPAD * 2) + cc * 2),
                       Bh + (size_t)row * H1 + k0 + cc, 16);
        }
        cp_commit();
    };

    issue_stage(0, 0);

    for (int kt = 0; kt < kiters; kt++) {
        const int stage = kt & 1;
        cp_wait_all();
        __syncthreads();

        if (kt + 1 < kiters) issue_stage(kt + 1, stage ^ 1);

        const uint32_t sAh = sm + G2_AH_OFF + (uint32_t)stage * G2_AH_STR;
        const uint32_t sBh = sm + G2_BH_OFF + (uint32_t)stage * G2_BSTAGE;
#pragma unroll
        for (int kk = 0; kk < 2; kk++) {
            const int kc = kk * 16;
            const int l16 = lane & 15;
            uint32_t bhf[4][2];
#pragma unroll
            for (int ni = 0; ni < 4; ni++) {
                const uint32_t boff =
                    (uint32_t)((wn * 32 + ni * 8 + (l16 & 7)) * GPAD + kc + (l16 >> 3) * 8) * 2u;
                ldsm_x2(bhf[ni], sBh + boff);
            }
#pragma unroll
            for (int mi = 0; mi < 4; mi++) {
                const uint32_t aoff =
                    (uint32_t)((wm * 64 + mi * 16 + (lane & 15)) * GPAD + kc + (lane >> 4) * 8) * 2u;
                uint32_t ahf[4];
                ldsm_x4(ahf, sAh + aoff);
#pragma unroll
                for (int ni = 0; ni < 4; ni++)
                    mma_fp16(c[mi][ni], ahf, bhf[ni]);
            }
        }
    }

#pragma unroll
    for (int mi = 0; mi < 4; mi++) {
        const int r0 = bm * 128 + wm * 64 + mi * 16 + (lane >> 2);
#pragma unroll
        for (int ni = 0; ni < 4; ni++) {
            const int col = wn * 32 + ni * 8 + 2 * (lane & 3);
            if (r0 < M)
                *(__half2*)(g_Hh + (size_t)r0 * H2 + col) =
                    __floats2half2_rn(c[mi][ni][0], c[mi][ni][1]);
            if (r0 + 8 < M)
                *(__half2*)(g_Hh + (size_t)(r0 + 8) * H2 + col) =
                    __floats2half2_rn(c[mi][ni][2], c[mi][ni][3]);
        }
    }
}

// ---------------- head GEMM: out = relu(Xh2 @ Wo1 + bo1) @ Wo2 + bo2 ---------
// BM=128, BN=64(all), BK=32, kiters=4; 8 warps 2x4, warp tile 64x16 (FM=4,FN=2).
// Epilogue fuses relu + Wo2 dot: quad shfl reduce -> smem cross-warp reduce.
#define HG_AH_OFF  0u           // 2 x 10240
#define HG_AH_STR  10240u
#define HG_BH_OFF  20480u       // 2 x 5120 (64 x GPAD)
#define HG_BSTAGE  5120u
#define HG_RED_OFF 30720u       // 128 x 4 floats
#define HG_SMEM    32768

__global__ __launch_bounds__(256, 2)
void head_gemm(const __half* __restrict__ Bh, const float* __restrict__ bo1,
               const float* __restrict__ Wo2, const float* __restrict__ bo2,
               float* __restrict__ out, int M) {
    extern __shared__ __align__(16) char smem[];
    const uint32_t sm = smem_u32(smem);

    const int tid = threadIdx.x;
    const int lane = tid & 31, warp = tid >> 5;
    const int wm = warp >> 2, wn = warp & 3;
    const int bm = blockIdx.x;

    float c[4][2][4];
#pragma unroll
    for (int mi = 0; mi < 4; mi++)
#pragma unroll
        for (int ni = 0; ni < 2; ni++)
#pragma unroll
            for (int q = 0; q < 4; q++) c[mi][ni][q] = 0.f;

    const int kiters = H2 / 32;   // 4

    auto issue_stage = [&](int kt, int stage) {
        const int k0 = kt * 32;
        const uint32_t ah = sm + HG_AH_OFF + (uint32_t)stage * HG_AH_STR;
#pragma unroll
        for (int j = 0; j < 2; j++) {
            const int cchunk = j * 256 + tid;         // 0..511
            const int row = cchunk >> 2, cc = cchunk & 3;
            const int grow = bm * 128 + row;
            cp_async16(ah + (uint32_t)(row * (GPAD * 2) + cc * 16),
                       g_Xh2 + (size_t)grow * H2 + k0 + cc * 8,
                       (grow < M) ? 16 : 0);
        }
        const uint32_t bh = sm + HG_BH_OFF + (uint32_t)stage * HG_BSTAGE;
        if (tid < 256) {                              // 64 rows x 4 chunks
            const int row = tid >> 2, cc = (tid & 3) * 8;
            cp_async16(bh + (uint32_t)(row * (GPAD * 2) + cc * 2),
                       Bh + (size_t)row * H2 + k0 + cc, 16);
        }
        cp_commit();
    };

    issue_stage(0, 0);

    for (int kt = 0; kt < kiters; kt++) {
        const int stage = kt & 1;
        cp_wait_all();
        __syncthreads();

        if (kt + 1 < kiters) issue_stage(kt + 1, stage ^ 1);

        const uint32_t sAh = sm + HG_AH_OFF + (uint32_t)stage * HG_AH_STR;
        const uint32_t sBh = sm + HG_BH_OFF + (uint32_t)stage * HG_BSTAGE;
#pragma unroll
        for (int kk = 0; kk < 2; kk++) {
            const int kc = kk * 16;
            const int l16 = lane & 15;
            uint32_t bhf[2][2];
#pragma unroll
            for (int ni = 0; ni < 2; ni++) {
                const uint32_t boff =
                    (uint32_t)((wn * 16 + ni * 8 + (l16 & 7)) * GPAD + kc + (l16 >> 3) * 8) * 2u;
                ldsm_x2(bhf[ni], sBh + boff);
            }
#pragma unroll
            for (int mi = 0; mi < 4; mi++) {
                const uint32_t aoff =
                    (uint32_t)((wm * 64 + mi * 16 + (lane & 15)) * GPAD + kc + (lane >> 4) * 8) * 2u;
                uint32_t ahf[4];
                ldsm_x4(ahf, sAh + aoff);
#pragma unroll
                for (int ni = 0; ni < 2; ni++)
                    mma_fp16(c[mi][ni], ahf, bhf[ni]);
            }
        }
    }

    // ---- fused epilogue: relu(+bo1) dot Wo2, reduce to one float per row ----
    float* sred = (float*)(smem + HG_RED_OFF);    // [128][4]
    __syncthreads();   // SMEM A/B no longer needed; sred region is disjoint anyway
#pragma unroll
    for (int mi = 0; mi < 4; mi++) {
        float pA = 0.f, pB = 0.f;
#pragma unroll
        for (int ni = 0; ni < 2; ni++) {
            const int cl = wn * 16 + ni * 8 + 2 * (lane & 3);
            const float b0 = __ldg(bo1 + cl), b1 = __ldg(bo1 + cl + 1);
            const float w0 = __ldg(Wo2 + cl), w1 = __ldg(Wo2 + cl + 1);
            pA += fmaxf(c[mi][ni][0] + b0, 0.f) * w0 + fmaxf(c[mi][ni][1] + b1, 0.f) * w1;
            pB += fmaxf(c[mi][ni][2] + b0, 0.f) * w0 + fmaxf(c[mi][ni][3] + b1, 0.f) * w1;
        }
        pA += __shfl_xor_sync(0xffffffffu, pA, 1);
        pA += __shfl_xor_sync(0xffffffffu, pA, 2);
        pB += __shfl_xor_sync(0xffffffffu, pB, 1);
        pB += __shfl_xor_sync(0xffffffffu, pB, 2);
        if ((lane & 3) == 0) {
            const int wr = wm * 64 + mi * 16 + (lane >> 2);
            sred[wr * 4 + wn] = pA;
            sred[(wr + 8) * 4 + wn] = pB;
        }
    }
    __syncthreads();
    if (tid < 128) {
        const int row = bm * 128 + tid;
        if (row < M)
            out[row] = sred[tid * 4] + sred[tid * 4 + 1] + sred[tid * 4 + 2] +
                       sred[tid * 4 + 3] + __ldg(bo2);
    }
}

// ---------------- pull-based aggregation (atomic-free, fp16 gather) ---------
// THREADS = COLS/2: each thread owns exactly one half2 (cols 2t, 2t+1).
// L1MODE: gathered rows weighted by sout[s]; out fp16 g_Xh = sout*relu(sin*acc+b)
// else:   plain gather; out fp16 g_Xh2 = sin*acc + b.
template <int COLS, bool L1MODE>
__global__ __launch_bounds__(COLS / 2)
void aggregate_kernel(const float* __restrict__ bias) {
    const int v = blockIdx.x;
    const int t = threadIdx.x;
    constexpr int H2C = COLS / 2;

    float ax = 0.f, ay = 0.f;

    const int beg = g_rowptr[v];
    const int end = g_rowptr[v + 1];
    const __half2* __restrict__ Hm = (const __half2*)g_Hh;

    int e = beg;
    for (; e + 3 < end; e += 4) {
        int s0 = g_colsrc[e + 0], s1 = g_colsrc[e + 1];
        int s2 = g_colsrc[e + 2], s3 = g_colsrc[e + 3];
        float2 v0 = __half22float2(Hm[(size_t)s0 * H2C + t]);
        float2 v1 = __half22float2(Hm[(size_t)s1 * H2C + t]);
        float2 v2 = __half22float2(Hm[(size_t)s2 * H2C + t]);
        float2 v3 = __half22float2(Hm[(size_t)s3 * H2C + t]);
        if (L1MODE) {
            float w0 = __ldg(&g_sout[s0]), w1 = __ldg(&g_sout[s1]);
            float w2 = __ldg(&g_sout[s2]), w3 = __ldg(&g_sout[s3]);
            ax = fmaf(v0.x, w0, ax); ay = fmaf(v0.y, w0, ay);
            ax = fmaf(v1.x, w1, ax); ay = fmaf(v1.y, w1, ay);
            ax = fmaf(v2.x, w2, ax); ay = fmaf(v2.y, w2, ay);
            ax = fmaf(v3.x, w3, ax); ay = fmaf(v3.y, w3, ay);
        } else {
            ax += (v0.x + v1.x) + (v2.x + v3.x);
            ay += (v0.y + v1.y) + (v2.y + v3.y);
        }
    }
    for (; e < end; e++) {
        int s = g_colsrc[e];
        float2 v0 = __half22float2(Hm[(size_t)s * H2C + t]);
        if (L1MODE) {
            float w0 = __ldg(&g_sout[s]);
            ax = fmaf(v0.x, w0, ax); ay = fmaf(v0.y, w0, ay);
        } else {
            ax += v0.x;
            ay += v0.y;
        }
    }

    const float si = g_sin[v];
    float2 b = *(const float2*)(bias + 2 * t);
    float ox = fmaf(ax, si, b.x);
    float oy = fmaf(ay, si, b.y);
    if (L1MODE) {
        const float so = g_sout[v];
        ox = fmaxf(ox, 0.f) * so;
        oy = fmaxf(oy, 0.f) * so;
        *(__half2*)(g_Xh + (size_t)v * COLS + 2 * t) = __floats2half2_rn(ox, oy);
    } else {
        *(__half2*)(g_Xh2 + (size_t)v * COLS + 2 * t) = __floats2half2_rn(ox, oy);
    }
}

// ---------------- launch -----------------------------------------------------
extern "C" void kernel_launch(void* const* d_in, const int* in_sizes, int n_in,
                              void* d_out, int out_size) {
    const float* feat = (const float*)d_in[0];   // [N, 64, 8] -> [N, 512]
    const int*   src  = (const int*)d_in[1];
    const int*   dst  = (const int*)d_in[2];
    const float* W1   = (const float*)d_in[3];
    const float* b1   = (const float*)d_in[4];
    const float* W2   = (const float*)d_in[5];
    const float* b2   = (const float*)d_in[6];
    const float* Wo1  = (const float*)d_in[7];
    const float* bo1  = (const float*)d_in[8];
    const float* Wo2  = (const float*)d_in[9];
    const float* bo2  = (const float*)d_in[10];
    float* out = (float*)d_out;

    const int nb_nodes = (N_NODES + 255) / 256;
    const int mt64  = (N_NODES + 63) / 64;    // 1563
    const int mt128 = (N_NODES + 127) / 128;  // 782

    __half *t1, *t2, *to1;
    cudaGetSymbolAddress((void**)&t1, g_W1t);
    cudaGetSymbolAddress((void**)&t2, g_W2t);
    cudaGetSymbolAddress((void**)&to1, g_Wo1t);

    cudaFuncSetAttribute(gemm1_wide,
                         cudaFuncAttributeMaxDynamicSharedMemorySize, G1_SMEM);
    cudaFuncSetAttribute(gemm2_fp16,
                         cudaFuncAttributeMaxDynamicSharedMemorySize, G2_SMEM);
    cudaFuncSetAttribute(head_gemm,
                         cudaFuncAttributeMaxDynamicSharedMemorySize, HG_SMEM);

    // one-time side stream + fork/join events (reused across calls/capture)
    static cudaStream_t s_pre = nullptr;
    static cudaEvent_t ev_fork = nullptr, ev_pre = nullptr;
    if (s_pre == nullptr) {
        cudaStreamCreateWithFlags(&s_pre, cudaStreamNonBlocking);
        cudaEventCreateWithFlags(&ev_fork, cudaEventDisableTiming);
        cudaEventCreateWithFlags(&ev_pre, cudaEventDisableTiming);
    }

    // ---- fork: graph preprocessing on side stream ----
    cudaEventRecord(ev_fork, 0);
    cudaStreamWaitEvent(s_pre, ev_fork, 0);
    zero_deg_kernel<<<nb_nodes, 256, 0, s_pre>>>();
    degree_kernel<<<2048, 256, 0, s_pre>>>(src, dst);
    scales_kernel<<<nb_nodes, 256, 0, s_pre>>>();
    scan_block_kernel<<<SCAN_BLOCKS, 1024, 0, s_pre>>>();
    scan_part_kernel<<<1, 128, 0, s_pre>>>();
    scan_finish_kernel<<<nb_nodes, 256, 0, s_pre>>>();
    csr_fill_kernel<<<2048, 256, 0, s_pre>>>(src, dst);
    cudaEventRecord(ev_pre, s_pre);

    // ---- main stream: weight transpose + graph-independent GEMM1 ----
    wconv_kernel<<<(K1 * H1 + 255) / 256, 256>>>(W1, t1, K1, H1);
    wconv_kernel<<<(H1 * H2 + 255) / 256, 256>>>(W2, t2, H1, H2);
    wconv_kernel<<<(H2 * ENDD + 255) / 256, 256>>>(Wo1, to1, H2, ENDD);
    gemm1_wide<<<mt64, 256, G1_SMEM>>>(feat, t1, N_NODES);

    // ---- join: aggregation needs CSR + scales + GEMM1 ----
    cudaStreamWaitEvent(0, ev_pre, 0);
    aggregate_kernel<H1, true><<<N_NODES, H1 / 2>>>(b1);

    // layer 2 (fp16 A directly from g_Xh; agg2 -> fp16 g_Xh2)
    gemm2_fp16<<<mt128, 256, G2_SMEM>>>(t2, N_NODES);
    aggregate_kernel<H2, false><<<N_NODES, H2 / 2>>>(b2);

    // fused head GEMM (relu + Wo2 dot in epilogue)
    head_gemm<<<mt128, 256, HG_SMEM>>>(to1, bo1, Wo2, bo2, out, N_NODES);
}

// round 13
// speedup vs baseline: 3.5545x; 1.3696x over previous
#include <cuda_runtime.h>
#include <cuda_bf16.h>
#include <cuda_fp16.h>
#include <cstdint>

#define N_NODES 100000
#define N_EDGES 3200000
#define K1 512      // in_dim * n_seq
#define H1 256
#define H2 128
#define ENDD 64

// ---------------- scratch (device globals; no allocation allowed) -----------
__device__ __half g_Hh[(size_t)N_NODES * H1];  // GEMM outputs, fp16 (agg input)
__device__ __half g_Xh[(size_t)N_NODES * H1];  // layer-2 GEMM input (agg1 out)
__device__ __half g_Xh2[(size_t)N_NODES * H2]; // head GEMM input (agg2 out)
__device__ int   g_deg_out[N_NODES];
__device__ int   g_deg_in[N_NODES];
__device__ float g_sout[N_NODES];
__device__ float g_sin[N_NODES];
__device__ int   g_rowptr[N_NODES + 1];
__device__ int   g_cursor[N_NODES];
__device__ int   g_colsrc[N_EDGES];
#define SCAN_BLOCKS ((N_NODES + 1023) / 1024)   // 98
__device__ int   g_part[128];
__device__ int   g_poff[128];
// transposed fp16 weights: Wt[n][k]
__device__ __half g_W1t[H1 * K1];
__device__ __half g_W2t[H2 * H1];
__device__ __half g_Wo1t[ENDD * H2];

// ---------------- PTX helpers ------------------------------------------------
__device__ __forceinline__ uint32_t smem_u32(const void* p) {
    uint32_t a;
    asm("{ .reg .u64 t; cvta.to.shared.u64 t, %1; cvt.u32.u64 %0, t; }"
        : "=r"(a) : "l"(p));
    return a;
}

__device__ __forceinline__ void ldsm_x4(uint32_t (&r)[4], uint32_t a) {
    asm volatile("ldmatrix.sync.aligned.m8n8.x4.shared.b16 {%0,%1,%2,%3}, [%4];"
                 : "=r"(r[0]), "=r"(r[1]), "=r"(r[2]), "=r"(r[3]) : "r"(a));
}

__device__ __forceinline__ void ldsm_x2(uint32_t (&r)[2], uint32_t a) {
    asm volatile("ldmatrix.sync.aligned.m8n8.x2.shared.b16 {%0,%1}, [%2];"
                 : "=r"(r[0]), "=r"(r[1]) : "r"(a));
}

__device__ __forceinline__ void mma_fp16(float (&d)[4], const uint32_t (&a)[4],
                                         const uint32_t (&b)[2]) {
    asm volatile(
        "mma.sync.aligned.m16n8k16.row.col.f32.f16.f16.f32 "
        "{%0,%1,%2,%3}, {%4,%5,%6,%7}, {%8,%9}, {%0,%1,%2,%3};"
        : "+f"(d[0]), "+f"(d[1]), "+f"(d[2]), "+f"(d[3])
        : "r"(a[0]), "r"(a[1]), "r"(a[2]), "r"(a[3]), "r"(b[0]), "r"(b[1]));
}

__device__ __forceinline__ void cp_async16(uint32_t smem_dst, const void* gsrc,
                                           int src_bytes) {
    asm volatile("cp.async.cg.shared.global [%0], [%1], 16, %2;"
                 :: "r"(smem_dst), "l"(gsrc), "r"(src_bytes));
}
__device__ __forceinline__ void cp_commit() {
    asm volatile("cp.async.commit_group;");
}
__device__ __forceinline__ void cp_wait_all() {
    asm volatile("cp.async.wait_group 0;");
}

// ---------------- graph preprocessing ---------------------------------------
__global__ void zero_deg_kernel() {
    int i = blockIdx.x * blockDim.x + threadIdx.x;
    if (i < N_NODES) { g_deg_out[i] = 0; g_deg_in[i] = 0; }
}

__global__ void degree_kernel(const int* __restrict__ src, const int* __restrict__ dst) {
    for (int e = blockIdx.x * blockDim.x + threadIdx.x; e < N_EDGES;
         e += gridDim.x * blockDim.x) {
        atomicAdd(&g_deg_out[src[e]], 1);
        atomicAdd(&g_deg_in[dst[e]], 1);
    }
}

__global__ void scales_kernel() {
    int i = blockIdx.x * blockDim.x + threadIdx.x;
    if (i < N_NODES) {
        g_sout[i] = rsqrtf((float)max(g_deg_out[i], 1));
        g_sin[i]  = rsqrtf((float)max(g_deg_in[i], 1));
    }
}

__global__ void scan_block_kernel() {
    __shared__ int sh[1024];
    int t = threadIdx.x;
    int i = blockIdx.x * 1024 + t;
    int v = (i < N_NODES) ? g_deg_in[i] : 0;
    sh[t] = v;
    __syncthreads();
    for (int off = 1; off < 1024; off <<= 1) {
        int x = sh[t];
        int y = (t >= off) ? sh[t - off] : 0;
        __syncthreads();
        sh[t] = x + y;
        __syncthreads();
    }
    if (i < N_NODES) g_rowptr[i] = sh[t] - v;
    if (t == 1023) g_part[blockIdx.x] = sh[1023];
}

__global__ void scan_part_kernel() {
    __shared__ int sh[128];
    int t = threadIdx.x;
    int v = (t < SCAN_BLOCKS) ? g_part[t] : 0;
    sh[t] = v;
    __syncthreads();
    for (int off = 1; off < 128; off <<= 1) {
        int x = sh[t];
        int y = (t >= off) ? sh[t - off] : 0;
        __syncthreads();
        sh[t] = x + y;
        __syncthreads();
    }
    g_poff[t] = sh[t] - v;
}

__global__ void scan_finish_kernel() {
    int i = blockIdx.x * blockDim.x + threadIdx.x;
    if (i < N_NODES) {
        int r = g_rowptr[i] + g_poff[i >> 10];
        g_rowptr[i] = r;
        g_cursor[i] = r;
    }
    if (i == 0) g_rowptr[N_NODES] = N_EDGES;
}

__global__ void csr_fill_kernel(const int* __restrict__ src, const int* __restrict__ dst) {
    for (int e = blockIdx.x * blockDim.x + threadIdx.x; e < N_EDGES;
         e += gridDim.x * blockDim.x) {
        int d = dst[e];
        int pos = atomicAdd(&g_cursor[d], 1);
        g_colsrc[pos] = src[e];
    }
}

// ------- weight transpose to fp16: W[K][N] -> Wt[N][K] ----------------------
__global__ void wconv_kernel(const float* __restrict__ W, __half* __restrict__ T,
                             int K, int N) {
    int i = blockIdx.x * blockDim.x + threadIdx.x;
    if (i < K * N) {
        int k = i / N, n = i % N;
        T[(size_t)n * K + k] = __float2half_rn(W[i]);
    }
}

#define GPAD 40   // fp16 elements per SMEM row (80 B): conflict-free ldmatrix

// ---------------- GEMM1: fp32 A (feat), BM=64 x BN=256(all of N), BK=32 ------
#define G1_AH_OFF   0u          // 64 x GPAD fp16 = 5120 (single)
#define G1_RAWA_OFF 5120u       // 2 x 8192 (64x32 fp32)
#define G1_RAWA_STR 8192u
#define G1_BH_OFF   21504u      // 2 x 20480 (256 x GPAD fp16)
#define G1_BSTAGE   20480u
#define G1_SMEM     62464

__global__ __launch_bounds__(256, 2)
void gemm1_wide(const float* __restrict__ A, const __half* __restrict__ Bh, int M) {
    extern __shared__ __align__(16) char smem[];
    const uint32_t sm = smem_u32(smem);

    const int tid = threadIdx.x;
    const int lane = tid & 31, warp = tid >> 5;
    const int wm = warp >> 2, wn = warp & 3;     // 2 x 4 warp grid
    const int bm = blockIdx.x;

    float c[2][8][4];
#pragma unroll
    for (int mi = 0; mi < 2; mi++)
#pragma unroll
        for (int ni = 0; ni < 8; ni++)
#pragma unroll
            for (int q = 0; q < 4; q++) c[mi][ni][q] = 0.f;

    const int kiters = K1 / 32;    // 16

    auto issue_stage = [&](int kt, int stage) {
        const int k0 = kt * 32;
        const uint32_t rawA = sm + G1_RAWA_OFF + (uint32_t)stage * G1_RAWA_STR;
#pragma unroll
        for (int j = 0; j < 2; j++) {
            const int cchunk = j * 256 + tid;             // 0..511
            const int row = cchunk >> 3, cc = (cchunk & 7) * 4;
            const int grow = bm * 64 + row;
            cp_async16(rawA + (uint32_t)(row * 128 + cc * 4),
                       A + (size_t)grow * K1 + k0 + cc, (grow < M) ? 16 : 0);
        }
        const uint32_t bh = sm + G1_BH_OFF + (uint32_t)stage * G1_BSTAGE;
#pragma unroll
        for (int j = 0; j < 4; j++) {
            const int cchunk = j * 256 + tid;             // 0..1023
            const int row = cchunk >> 2, cc = (cchunk & 3) * 8;   // row 0..255
            cp_async16(bh + (uint32_t)(row * (GPAD * 2) + cc * 2),
                       Bh + (size_t)row * K1 + k0 + cc, 16);
        }
        cp_commit();
    };

    issue_stage(0, 0);

    for (int kt = 0; kt < kiters; kt++) {
        const int stage = kt & 1;
        cp_wait_all();
        __syncthreads();

        if (kt + 1 < kiters) issue_stage(kt + 1, stage ^ 1);

        // convert rawA[stage] fp32 -> fp16 into single Ah buffer
        {
            const float4* raw =
                (const float4*)(smem + G1_RAWA_OFF + (uint32_t)stage * G1_RAWA_STR);
            __half* AhP = (__half*)(smem + G1_AH_OFF);
#pragma unroll
            for (int j = 0; j < 2; j++) {
                const int cchunk = j * 256 + tid;
                const int row = cchunk >> 3, col = (cchunk & 7) * 4;
                float4 v = raw[row * 8 + (cchunk & 7)];
                const int off = row * GPAD + col;
                *(__half2*)&AhP[off]     = __floats2half2_rn(v.x, v.y);
                *(__half2*)&AhP[off + 2] = __floats2half2_rn(v.z, v.w);
            }
        }
        __syncthreads();

        const uint32_t sAh = sm + G1_AH_OFF;
        const uint32_t sBh = sm + G1_BH_OFF + (uint32_t)stage * G1_BSTAGE;
#pragma unroll
        for (int kk = 0; kk < 2; kk++) {
            const int kc = kk * 16;
            const int l16 = lane & 15;
            uint32_t bhf[8][2];
#pragma unroll
            for (int ni = 0; ni < 8; ni++) {
                const uint32_t boff =
                    (uint32_t)((wn * 64 + ni * 8 + (l16 & 7)) * GPAD + kc + (l16 >> 3) * 8) * 2u;
                ldsm_x2(bhf[ni], sBh + boff);
            }
#pragma unroll
            for (int mi = 0; mi < 2; mi++) {
                const uint32_t aoff =
                    (uint32_t)((wm * 32 + mi * 16 + (lane & 15)) * GPAD + kc + (lane >> 4) * 8) * 2u;
                uint32_t ahf[4];
                ldsm_x4(ahf, sAh + aoff);
#pragma unroll
                for (int ni = 0; ni < 8; ni++)
                    mma_fp16(c[mi][ni], ahf, bhf[ni]);
            }
        }
    }

    // epilogue: fp16 store
#pragma unroll
    for (int mi = 0; mi < 2; mi++) {
        const int r0 = bm * 64 + wm * 32 + mi * 16 + (lane >> 2);
#pragma unroll
        for (int ni = 0; ni < 8; ni++) {
            const int col = wn * 64 + ni * 8 + 2 * (lane & 3);
            if (r0 < M)
                *(__half2*)(g_Hh + (size_t)r0 * H1 + col) =
                    __floats2half2_rn(c[mi][ni][0], c[mi][ni][1]);
            if (r0 + 8 < M)
                *(__half2*)(g_Hh + (size_t)(r0 + 8) * H1 + col) =
                    __floats2half2_rn(c[mi][ni][2], c[mi][ni][3]);
        }
    }
}

// ---------------- GEMM2: fp16 A (g_Xh), BM=128 x BN=128, BK=32 ---------------
#define G2_AH_OFF  0u           // 2 x 10240
#define G2_AH_STR  10240u
#define G2_BH_OFF  20480u       // 2 x 10240
#define G2_BSTAGE  10240u
#define G2_SMEM    40960

__global__ __launch_bounds__(256, 2)
void gemm2_fp16(const __half* __restrict__ Bh, int M) {
    extern __shared__ __align__(16) char smem[];
    const uint32_t sm = smem_u32(smem);

    const int tid = threadIdx.x;
    const int lane = tid & 31, warp = tid >> 5;
    const int wm = warp >> 2, wn = warp & 3;
    const int bm = blockIdx.x;

    float c[4][4][4];
#pragma unroll
    for (int mi = 0; mi < 4; mi++)
#pragma unroll
        for (int ni = 0; ni < 4; ni++)
#pragma unroll
            for (int q = 0; q < 4; q++) c[mi][ni][q] = 0.f;

    const int kiters = H1 / 32;   // 8

    auto issue_stage = [&](int kt, int stage) {
        const int k0 = kt * 32;
        const uint32_t ah = sm + G2_AH_OFF + (uint32_t)stage * G2_AH_STR;
#pragma unroll
        for (int j = 0; j < 2; j++) {
            const int cchunk = j * 256 + tid;         // 0..511
            const int row = cchunk >> 2, cc = cchunk & 3;
            const int grow = bm * 128 + row;
            cp_async16(ah + (uint32_t)(row * (GPAD * 2) + cc * 16),
                       g_Xh + (size_t)grow * H1 + k0 + cc * 8,
                       (grow < M) ? 16 : 0);
        }
        const uint32_t bh = sm + G2_BH_OFF + (uint32_t)stage * G2_BSTAGE;
#pragma unroll
        for (int j = 0; j < 2; j++) {
            const int cchunk = j * 256 + tid;
            const int row = cchunk >> 2, cc = (cchunk & 3) * 8;
            cp_async16(bh + (uint32_t)(row * (GPAD * 2) + cc * 2),
                       Bh + (size_t)row * H1 + k0 + cc, 16);
        }
        cp_commit();
    };

    issue_stage(0, 0);

    for (int kt = 0; kt < kiters; kt++) {
        const int stage = kt & 1;
        cp_wait_all();
        __syncthreads();

        if (kt + 1 < kiters) issue_stage(kt + 1, stage ^ 1);

        const uint32_t sAh = sm + G2_AH_OFF + (uint32_t)stage * G2_AH_STR;
        const uint32_t sBh = sm + G2_BH_OFF + (uint32_t)stage * G2_BSTAGE;
#pragma unroll
        for (int kk = 0; kk < 2; kk++) {
            const int kc = kk * 16;
            const int l16 = lane & 15;
            uint32_t bhf[4][2];
#pragma unroll
            for (int ni = 0; ni < 4; ni++) {
                const uint32_t boff =
                    (uint32_t)((wn * 32 + ni * 8 + (l16 & 7)) * GPAD + kc + (l16 >> 3) * 8) * 2u;
                ldsm_x2(bhf[ni], sBh + boff);
            }
#pragma unroll
            for (int mi = 0; mi < 4; mi++) {
                const uint32_t aoff =
                    (uint32_t)((wm * 64 + mi * 16 + (lane & 15)) * GPAD + kc + (lane >> 4) * 8) * 2u;
                uint32_t ahf[4];
                ldsm_x4(ahf, sAh + aoff);
#pragma unroll
                for (int ni = 0; ni < 4; ni++)
                    mma_fp16(c[mi][ni], ahf, bhf[ni]);
            }
        }
    }

#pragma unroll
    for (int mi = 0; mi < 4; mi++) {
        const int r0 = bm * 128 + wm * 64 + mi * 16 + (lane >> 2);
#pragma unroll
        for (int ni = 0; ni < 4; ni++) {
            const int col = wn * 32 + ni * 8 + 2 * (lane & 3);
            if (r0 < M)
                *(__half2*)(g_Hh + (size_t)r0 * H2 + col) =
                    __floats2half2_rn(c[mi][ni][0], c[mi][ni][1]);
            if (r0 + 8 < M)
                *(__half2*)(g_Hh + (size_t)(r0 + 8) * H2 + col) =
                    __floats2half2_rn(c[mi][ni][2], c[mi][ni][3]);
        }
    }
}

// ---------------- head GEMM: out = relu(Xh2 @ Wo1 + bo1) @ Wo2 + bo2 ---------
#define HG_AH_OFF  0u           // 2 x 10240
#define HG_AH_STR  10240u
#define HG_BH_OFF  20480u       // 2 x 5120 (64 x GPAD)
#define HG_BSTAGE  5120u
#define HG_RED_OFF 30720u       // 128 x 4 floats
#define HG_SMEM    32768

__global__ __launch_bounds__(256, 2)
void head_gemm(const __half* __restrict__ Bh, const float* __restrict__ bo1,
               const float* __restrict__ Wo2, const float* __restrict__ bo2,
               float* __restrict__ out, int M) {
    extern __shared__ __align__(16) char smem[];
    const uint32_t sm = smem_u32(smem);

    const int tid = threadIdx.x;
    const int lane = tid & 31, warp = tid >> 5;
    const int wm = warp >> 2, wn = warp & 3;
    const int bm = blockIdx.x;

    float c[4][2][4];
#pragma unroll
    for (int mi = 0; mi < 4; mi++)
#pragma unroll
        for (int ni = 0; ni < 2; ni++)
#pragma unroll
            for (int q = 0; q < 4; q++) c[mi][ni][q] = 0.f;

    const int kiters = H2 / 32;   // 4

    auto issue_stage = [&](int kt, int stage) {
        const int k0 = kt * 32;
        const uint32_t ah = sm + HG_AH_OFF + (uint32_t)stage * HG_AH_STR;
#pragma unroll
        for (int j = 0; j < 2; j++) {
            const int cchunk = j * 256 + tid;         // 0..511
            const int row = cchunk >> 2, cc = cchunk & 3;
            const int grow = bm * 128 + row;
            cp_async16(ah + (uint32_t)(row * (GPAD * 2) + cc * 16),
                       g_Xh2 + (size_t)grow * H2 + k0 + cc * 8,
                       (grow < M) ? 16 : 0);
        }
        const uint32_t bh = sm + HG_BH_OFF + (uint32_t)stage * HG_BSTAGE;
        if (tid < 256) {                              // 64 rows x 4 chunks
            const int row = tid >> 2, cc = (tid & 3) * 8;
            cp_async16(bh + (uint32_t)(row * (GPAD * 2) + cc * 2),
                       Bh + (size_t)row * H2 + k0 + cc, 16);
        }
        cp_commit();
    };

    issue_stage(0, 0);

    for (int kt = 0; kt < kiters; kt++) {
        const int stage = kt & 1;
        cp_wait_all();
        __syncthreads();

        if (kt + 1 < kiters) issue_stage(kt + 1, stage ^ 1);

        const uint32_t sAh = sm + HG_AH_OFF + (uint32_t)stage * HG_AH_STR;
        const uint32_t sBh = sm + HG_BH_OFF + (uint32_t)stage * HG_BSTAGE;
#pragma unroll
        for (int kk = 0; kk < 2; kk++) {
            const int kc = kk * 16;
            const int l16 = lane & 15;
            uint32_t bhf[2][2];
#pragma unroll
            for (int ni = 0; ni < 2; ni++) {
                const uint32_t boff =
                    (uint32_t)((wn * 16 + ni * 8 + (l16 & 7)) * GPAD + kc + (l16 >> 3) * 8) * 2u;
                ldsm_x2(bhf[ni], sBh + boff);
            }
#pragma unroll
            for (int mi = 0; mi < 4; mi++) {
                const uint32_t aoff =
                    (uint32_t)((wm * 64 + mi * 16 + (lane & 15)) * GPAD + kc + (lane >> 4) * 8) * 2u;
                uint32_t ahf[4];
                ldsm_x4(ahf, sAh + aoff);
#pragma unroll
                for (int ni = 0; ni < 2; ni++)
                    mma_fp16(c[mi][ni], ahf, bhf[ni]);
            }
        }
    }

    // ---- fused epilogue: relu(+bo1) dot Wo2, reduce to one float per row ----
    float* sred = (float*)(smem + HG_RED_OFF);    // [128][4]
    __syncthreads();
#pragma unroll
    for (int mi = 0; mi < 4; mi++) {
        float pA = 0.f, pB = 0.f;
#pragma unroll
        for (int ni = 0; ni < 2; ni++) {
            const int cl = wn * 16 + ni * 8 + 2 * (lane & 3);
            const float b0 = __ldg(bo1 + cl), b1 = __ldg(bo1 + cl + 1);
            const float w0 = __ldg(Wo2 + cl), w1 = __ldg(Wo2 + cl + 1);
            pA += fmaxf(c[mi][ni][0] + b0, 0.f) * w0 + fmaxf(c[mi][ni][1] + b1, 0.f) * w1;
            pB += fmaxf(c[mi][ni][2] + b0, 0.f) * w0 + fmaxf(c[mi][ni][3] + b1, 0.f) * w1;
        }
        pA += __shfl_xor_sync(0xffffffffu, pA, 1);
        pA += __shfl_xor_sync(0xffffffffu, pA, 2);
        pB += __shfl_xor_sync(0xffffffffu, pB, 1);
        pB += __shfl_xor_sync(0xffffffffu, pB, 2);
        if ((lane & 3) == 0) {
            const int wr = wm * 64 + mi * 16 + (lane >> 2);
            sred[wr * 4 + wn] = pA;
            sred[(wr + 8) * 4 + wn] = pB;
        }
    }
    __syncthreads();
    if (tid < 128) {
        const int row = bm * 128 + tid;
        if (row < M)
            out[row] = sred[tid * 4] + sred[tid * 4 + 1] + sred[tid * 4 + 2] +
                       sred[tid * 4 + 3] + __ldg(bo2);
    }
}

// ---------------- warp-per-node aggregation (fp16 gather, LDG.128) ----------
// One warp per node, 8 nodes per 256-thread block. Each lane owns EPT=COLS/32
// columns and loads one uint4 (agg1) / uint2 (agg2) per edge — the whole row
// is ONE warp LDG instruction. fp32 accumulate; precision-identical to R12.
template <int COLS, bool L1MODE>
__global__ __launch_bounds__(256)
void aggregate_warp(const float* __restrict__ bias) {
    const int warp = threadIdx.x >> 5, lane = threadIdx.x & 31;
    const int v = blockIdx.x * 8 + warp;
    if (v >= N_NODES) return;
    constexpr int EPT = COLS / 32;        // 8 (agg1) or 4 (agg2)

    float acc[EPT];
#pragma unroll
    for (int i = 0; i < EPT; i++) acc[i] = 0.f;

    const __half* __restrict__ Hm = g_Hh;

    auto gather_one = [&](int ei) {
        const int s = g_colsrc[ei];
        const __half* r = Hm + (size_t)s * COLS + lane * EPT;
        float w = 1.f;
        if (L1MODE) w = __ldg(&g_sout[s]);
        if constexpr (EPT == 8) {
            const uint4 d = *(const uint4*)r;
            const float2 f0 = __half22float2(*(const __half2*)&d.x);
            const float2 f1 = __half22float2(*(const __half2*)&d.y);
            const float2 f2 = __half22float2(*(const __half2*)&d.z);
            const float2 f3 = __half22float2(*(const __half2*)&d.w);
            acc[0] = fmaf(f0.x, w, acc[0]); acc[1] = fmaf(f0.y, w, acc[1]);
            acc[2] = fmaf(f1.x, w, acc[2]); acc[3] = fmaf(f1.y, w, acc[3]);
            acc[4] = fmaf(f2.x, w, acc[4]); acc[5] = fmaf(f2.y, w, acc[5]);
            acc[6] = fmaf(f3.x, w, acc[6]); acc[7] = fmaf(f3.y, w, acc[7]);
        } else {
            const uint2 d = *(const uint2*)r;
            const float2 f0 = __half22float2(*(const __half2*)&d.x);
            const float2 f1 = __half22float2(*(const __half2*)&d.y);
            acc[0] = fmaf(f0.x, w, acc[0]); acc[1] = fmaf(f0.y, w, acc[1]);
            acc[2] = fmaf(f1.x, w, acc[2]); acc[3] = fmaf(f1.y, w, acc[3]);
        }
    };

    const int beg = g_rowptr[v];
    const int end = g_rowptr[v + 1];
    int e = beg;
    for (; e + 3 < end; e += 4) {
        gather_one(e + 0);
        gather_one(e + 1);
        gather_one(e + 2);
        gather_one(e + 3);
    }
    for (; e < end; e++) gather_one(e);

    const float si = g_sin[v];
    float o[EPT];
#pragma unroll
    for (int i = 0; i < EPT; i += 4) {
        const float4 b = *(const float4*)(bias + lane * EPT + i);
        o[i]     = fmaf(acc[i],     si, b.x);
        o[i + 1] = fmaf(acc[i + 1], si, b.y);
        o[i + 2] = fmaf(acc[i + 2], si, b.z);
        o[i + 3] = fmaf(acc[i + 3], si, b.w);
    }

    __half2 h[EPT / 2];
    if constexpr (L1MODE) {
        const float so = g_sout[v];
#pragma unroll
        for (int i = 0; i < EPT; i++) o[i] = fmaxf(o[i], 0.f) * so;
#pragma unroll
        for (int i = 0; i < EPT / 2; i++) h[i] = __floats2half2_rn(o[2 * i], o[2 * i + 1]);
        if constexpr (EPT == 8)
            *(uint4*)(g_Xh + (size_t)v * COLS + lane * EPT) = *(uint4*)h;
        else
            *(uint2*)(g_Xh + (size_t)v * COLS + lane * EPT) = *(uint2*)h;
    } else {
#pragma unroll
        for (int i = 0; i < EPT / 2; i++) h[i] = __floats2half2_rn(o[2 * i], o[2 * i + 1]);
        if constexpr (EPT == 8)
            *(uint4*)(g_Xh2 + (size_t)v * COLS + lane * EPT) = *(uint4*)h;
        else
            *(uint2*)(g_Xh2 + (size_t)v * COLS + lane * EPT) = *(uint2*)h;
    }
}

// ---------------- launch -----------------------------------------------------
extern "C" void kernel_launch(void* const* d_in, const int* in_sizes, int n_in,
                              void* d_out, int out_size) {
    const float* feat = (const float*)d_in[0];   // [N, 64, 8] -> [N, 512]
    const int*   src  = (const int*)d_in[1];
    const int*   dst  = (const int*)d_in[2];
    const float* W1   = (const float*)d_in[3];
    const float* b1   = (const float*)d_in[4];
    const float* W2   = (const float*)d_in[5];
    const float* b2   = (const float*)d_in[6];
    const float* Wo1  = (const float*)d_in[7];
    const float* bo1  = (const float*)d_in[8];
    const float* Wo2  = (const float*)d_in[9];
    const float* bo2  = (const float*)d_in[10];
    float* out = (float*)d_out;

    const int nb_nodes = (N_NODES + 255) / 256;
    const int mt64  = (N_NODES + 63) / 64;    // 1563
    const int mt128 = (N_NODES + 127) / 128;  // 782
    const int agrid = (N_NODES + 7) / 8;      // 12500

    __half *t1, *t2, *to1;
    cudaGetSymbolAddress((void**)&t1, g_W1t);
    cudaGetSymbolAddress((void**)&t2, g_W2t);
    cudaGetSymbolAddress((void**)&to1, g_Wo1t);

    cudaFuncSetAttribute(gemm1_wide,
                         cudaFuncAttributeMaxDynamicSharedMemorySize, G1_SMEM);
    cudaFuncSetAttribute(gemm2_fp16,
                         cudaFuncAttributeMaxDynamicSharedMemorySize, G2_SMEM);
    cudaFuncSetAttribute(head_gemm,
                         cudaFuncAttributeMaxDynamicSharedMemorySize, HG_SMEM);

    // one-time side stream + fork/join events (reused across calls/capture)
    static cudaStream_t s_pre = nullptr;
    static cudaEvent_t ev_fork = nullptr, ev_pre = nullptr;
    if (s_pre == nullptr) {
        cudaStreamCreateWithFlags(&s_pre, cudaStreamNonBlocking);
        cudaEventCreateWithFlags(&ev_fork, cudaEventDisableTiming);
        cudaEventCreateWithFlags(&ev_pre, cudaEventDisableTiming);
    }

    // ---- fork: graph preprocessing on side stream ----
    cudaEventRecord(ev_fork, 0);
    cudaStreamWaitEvent(s_pre, ev_fork, 0);
    zero_deg_kernel<<<nb_nodes, 256, 0, s_pre>>>();
    degree_kernel<<<2048, 256, 0, s_pre>>>(src, dst);
    scales_kernel<<<nb_nodes, 256, 0, s_pre>>>();
    scan_block_kernel<<<SCAN_BLOCKS, 1024, 0, s_pre>>>();
    scan_part_kernel<<<1, 128, 0, s_pre>>>();
    scan_finish_kernel<<<nb_nodes, 256, 0, s_pre>>>();
    csr_fill_kernel<<<2048, 256, 0, s_pre>>>(src, dst);
    cudaEventRecord(ev_pre, s_pre);

    // ---- main stream: weight transpose + graph-independent GEMM1 ----
    wconv_kernel<<<(K1 * H1 + 255) / 256, 256>>>(W1, t1, K1, H1);
    wconv_kernel<<<(H1 * H2 + 255) / 256, 256>>>(W2, t2, H1, H2);
    wconv_kernel<<<(H2 * ENDD + 255) / 256, 256>>>(Wo1, to1, H2, ENDD);
    gemm1_wide<<<mt64, 256, G1_SMEM>>>(feat, t1, N_NODES);

    // ---- join: aggregation needs CSR + scales + GEMM1 ----
    cudaStreamWaitEvent(0, ev_pre, 0);
    aggregate_warp<H1, true><<<agrid, 256>>>(b1);

    // layer 2 (fp16 A directly from g_Xh; agg2 -> fp16 g_Xh2)
    gemm2_fp16<<<mt128, 256, G2_SMEM>>>(t2, N_NODES);
    aggregate_warp<H2, false><<<agrid, 256>>>(b2);

    // fused head GEMM (relu + Wo2 dot in epilogue)
    head_gemm<<<mt128, 256, HG_SMEM>>>(to1, bo1, Wo2, bo2, out, N_NODES);
}

// round 14
// speedup vs baseline: 3.7022x; 1.0415x over previous
#include <cuda_runtime.h>
#include <cuda_bf16.h>
#include <cuda_fp16.h>
#include <cstdint>

#define N_NODES 100000
#define N_EDGES 3200000
#define K1 512      // in_dim * n_seq
#define H1 256
#define H2 128
#define ENDD 64

// ---------------- scratch (device globals; no allocation allowed) -----------
__device__ __half g_Hh[(size_t)N_NODES * H1];  // GEMM outputs, fp16 (agg input)
__device__ __half g_Xh[(size_t)N_NODES * H1];  // layer-2 GEMM input (agg1 out)
__device__ __half g_Xh2[(size_t)N_NODES * H2]; // head GEMM input (agg2 out)
__device__ int   g_deg_out[N_NODES];
__device__ int   g_deg_in[N_NODES];
__device__ float g_sout[N_NODES];
__device__ float g_sin[N_NODES];
__device__ int   g_rowptr[N_NODES + 1];
__device__ int   g_cursor[N_NODES];
__device__ int   g_colsrc[N_EDGES];
#define SCAN_BLOCKS ((N_NODES + 1023) / 1024)   // 98
__device__ int   g_part[128];
__device__ int   g_poff[128];
// transposed fp16 weights: Wt[n][k]
__device__ __half g_W1t[H1 * K1];
__device__ __half g_W2t[H2 * H1];
__device__ __half g_Wo1t[ENDD * H2];

// ---------------- PTX helpers ------------------------------------------------
__device__ __forceinline__ uint32_t smem_u32(const void* p) {
    uint32_t a;
    asm("{ .reg .u64 t; cvta.to.shared.u64 t, %1; cvt.u32.u64 %0, t; }"
        : "=r"(a) : "l"(p));
    return a;
}

__device__ __forceinline__ void ldsm_x4(uint32_t (&r)[4], uint32_t a) {
    asm volatile("ldmatrix.sync.aligned.m8n8.x4.shared.b16 {%0,%1,%2,%3}, [%4];"
                 : "=r"(r[0]), "=r"(r[1]), "=r"(r[2]), "=r"(r[3]) : "r"(a));
}

__device__ __forceinline__ void ldsm_x2(uint32_t (&r)[2], uint32_t a) {
    asm volatile("ldmatrix.sync.aligned.m8n8.x2.shared.b16 {%0,%1}, [%2];"
                 : "=r"(r[0]), "=r"(r[1]) : "r"(a));
}

__device__ __forceinline__ void mma_fp16(float (&d)[4], const uint32_t (&a)[4],
                                         const uint32_t (&b)[2]) {
    asm volatile(
        "mma.sync.aligned.m16n8k16.row.col.f32.f16.f16.f32 "
        "{%0,%1,%2,%3}, {%4,%5,%6,%7}, {%8,%9}, {%0,%1,%2,%3};"
        : "+f"(d[0]), "+f"(d[1]), "+f"(d[2]), "+f"(d[3])
        : "r"(a[0]), "r"(a[1]), "r"(a[2]), "r"(a[3]), "r"(b[0]), "r"(b[1]));
}

__device__ __forceinline__ void cp_async16(uint32_t smem_dst, const void* gsrc,
                                           int src_bytes) {
    asm volatile("cp.async.cg.shared.global [%0], [%1], 16, %2;"
                 :: "r"(smem_dst), "l"(gsrc), "r"(src_bytes));
}
__device__ __forceinline__ void cp_commit() {
    asm volatile("cp.async.commit_group;");
}
__device__ __forceinline__ void cp_wait_all() {
    asm volatile("cp.async.wait_group 0;");
}

// ---------------- graph preprocessing ---------------------------------------
__global__ void zero_deg_kernel() {
    int i = blockIdx.x * blockDim.x + threadIdx.x;
    if (i < N_NODES) { g_deg_out[i] = 0; g_deg_in[i] = 0; }
}

// vectorized: N_EDGES divisible by 4
__global__ void degree_kernel(const int4* __restrict__ src4,
                              const int4* __restrict__ dst4) {
    for (int i = blockIdx.x * blockDim.x + threadIdx.x; i < N_EDGES / 4;
         i += gridDim.x * blockDim.x) {
        int4 s = src4[i];
        atomicAdd(&g_deg_out[s.x], 1); atomicAdd(&g_deg_out[s.y], 1);
        atomicAdd(&g_deg_out[s.z], 1); atomicAdd(&g_deg_out[s.w], 1);
        int4 d = dst4[i];
        atomicAdd(&g_deg_in[d.x], 1); atomicAdd(&g_deg_in[d.y], 1);
        atomicAdd(&g_deg_in[d.z], 1); atomicAdd(&g_deg_in[d.w], 1);
    }
}

__global__ void scales_kernel() {
    int i = blockIdx.x * blockDim.x + threadIdx.x;
    if (i < N_NODES) {
        g_sout[i] = rsqrtf((float)max(g_deg_out[i], 1));
        g_sin[i]  = rsqrtf((float)max(g_deg_in[i], 1));
    }
}

__global__ void scan_block_kernel() {
    __shared__ int sh[1024];
    int t = threadIdx.x;
    int i = blockIdx.x * 1024 + t;
    int v = (i < N_NODES) ? g_deg_in[i] : 0;
    sh[t] = v;
    __syncthreads();
    for (int off = 1; off < 1024; off <<= 1) {
        int x = sh[t];
        int y = (t >= off) ? sh[t - off] : 0;
        __syncthreads();
        sh[t] = x + y;
        __syncthreads();
    }
    if (i < N_NODES) g_rowptr[i] = sh[t] - v;
    if (t == 1023) g_part[blockIdx.x] = sh[1023];
}

__global__ void scan_part_kernel() {
    __shared__ int sh[128];
    int t = threadIdx.x;
    int v = (t < SCAN_BLOCKS) ? g_part[t] : 0;
    sh[t] = v;
    __syncthreads();
    for (int off = 1; off < 128; off <<= 1) {
        int x = sh[t];
        int y = (t >= off) ? sh[t - off] : 0;
        __syncthreads();
        sh[t] = x + y;
        __syncthreads();
    }
    g_poff[t] = sh[t] - v;
}

__global__ void scan_finish_kernel() {
    int i = blockIdx.x * blockDim.x + threadIdx.x;
    if (i < N_NODES) {
        int r = g_rowptr[i] + g_poff[i >> 10];
        g_rowptr[i] = r;
        g_cursor[i] = r;
    }
    if (i == 0) g_rowptr[N_NODES] = N_EDGES;
}

__global__ void csr_fill_kernel(const int4* __restrict__ src4,
                                const int4* __restrict__ dst4) {
    for (int i = blockIdx.x * blockDim.x + threadIdx.x; i < N_EDGES / 4;
         i += gridDim.x * blockDim.x) {
        int4 d = dst4[i];
        int4 s = src4[i];
        g_colsrc[atomicAdd(&g_cursor[d.x], 1)] = s.x;
        g_colsrc[atomicAdd(&g_cursor[d.y], 1)] = s.y;
        g_colsrc[atomicAdd(&g_cursor[d.z], 1)] = s.z;
        g_colsrc[atomicAdd(&g_cursor[d.w], 1)] = s.w;
    }
}

// ------- weight transpose to fp16: W[K][N] -> Wt[N][K] ----------------------
__global__ void wconv_kernel(const float* __restrict__ W, __half* __restrict__ T,
                             int K, int N) {
    int i = blockIdx.x * blockDim.x + threadIdx.x;
    if (i < K * N) {
        int k = i / N, n = i % N;
        T[(size_t)n * K + k] = __float2half_rn(W[i]);
    }
}

#define GPAD 40   // fp16 elements per SMEM row (80 B): conflict-free ldmatrix

// ---------------- GEMM1: fp32 A (feat), BM=64 x BN=256(all of N), BK=32 ------
// Epilogue multiplies row r by g_sout[r] (fp32, exact) — so aggregation needs
// no per-edge scale load. GEMM1 therefore depends on scales (ev_scales).
#define G1_AH_OFF   0u          // 64 x GPAD fp16 = 5120 (single)
#define G1_RAWA_OFF 5120u       // 2 x 8192 (64x32 fp32)
#define G1_RAWA_STR 8192u
#define G1_BH_OFF   21504u      // 2 x 20480 (256 x GPAD fp16)
#define G1_BSTAGE   20480u
#define G1_SMEM     62464

__global__ __launch_bounds__(256, 2)
void gemm1_wide(const float* __restrict__ A, const __half* __restrict__ Bh, int M) {
    extern __shared__ __align__(16) char smem[];
    const uint32_t sm = smem_u32(smem);

    const int tid = threadIdx.x;
    const int lane = tid & 31, warp = tid >> 5;
    const int wm = warp >> 2, wn = warp & 3;     // 2 x 4 warp grid
    const int bm = blockIdx.x;

    float c[2][8][4];
#pragma unroll
    for (int mi = 0; mi < 2; mi++)
#pragma unroll
        for (int ni = 0; ni < 8; ni++)
#pragma unroll
            for (int q = 0; q < 4; q++) c[mi][ni][q] = 0.f;

    const int kiters = K1 / 32;    // 16

    auto issue_stage = [&](int kt, int stage) {
        const int k0 = kt * 32;
        const uint32_t rawA = sm + G1_RAWA_OFF + (uint32_t)stage * G1_RAWA_STR;
#pragma unroll
        for (int j = 0; j < 2; j++) {
            const int cchunk = j * 256 + tid;             // 0..511
            const int row = cchunk >> 3, cc = (cchunk & 7) * 4;
            const int grow = bm * 64 + row;
            cp_async16(rawA + (uint32_t)(row * 128 + cc * 4),
                       A + (size_t)grow * K1 + k0 + cc, (grow < M) ? 16 : 0);
        }
        const uint32_t bh = sm + G1_BH_OFF + (uint32_t)stage * G1_BSTAGE;
#pragma unroll
        for (int j = 0; j < 4; j++) {
            const int cchunk = j * 256 + tid;             // 0..1023
            const int row = cchunk >> 2, cc = (cchunk & 3) * 8;   // row 0..255
            cp_async16(bh + (uint32_t)(row * (GPAD * 2) + cc * 2),
                       Bh + (size_t)row * K1 + k0 + cc, 16);
        }
        cp_commit();
    };

    issue_stage(0, 0);

    for (int kt = 0; kt < kiters; kt++) {
        const int stage = kt & 1;
        cp_wait_all();
        __syncthreads();

        if (kt + 1 < kiters) issue_stage(kt + 1, stage ^ 1);

        // convert rawA[stage] fp32 -> fp16 into single Ah buffer
        {
            const float4* raw =
                (const float4*)(smem + G1_RAWA_OFF + (uint32_t)stage * G1_RAWA_STR);
            __half* AhP = (__half*)(smem + G1_AH_OFF);
#pragma unroll
            for (int j = 0; j < 2; j++) {
                const int cchunk = j * 256 + tid;
                const int row = cchunk >> 3, col = (cchunk & 7) * 4;
                float4 v = raw[row * 8 + (cchunk & 7)];
                const int off = row * GPAD + col;
                *(__half2*)&AhP[off]     = __floats2half2_rn(v.x, v.y);
                *(__half2*)&AhP[off + 2] = __floats2half2_rn(v.z, v.w);
            }
        }
        __syncthreads();

        const uint32_t sAh = sm + G1_AH_OFF;
        const uint32_t sBh = sm + G1_BH_OFF + (uint32_t)stage * G1_BSTAGE;
#pragma unroll
        for (int kk = 0; kk < 2; kk++) {
            const int kc = kk * 16;
            const int l16 = lane & 15;
            uint32_t bhf[8][2];
#pragma unroll
            for (int ni = 0; ni < 8; ni++) {
                const uint32_t boff =
                    (uint32_t)((wn * 64 + ni * 8 + (l16 & 7)) * GPAD + kc + (l16 >> 3) * 8) * 2u;
                ldsm_x2(bhf[ni], sBh + boff);
            }
#pragma unroll
            for (int mi = 0; mi < 2; mi++) {
                const uint32_t aoff =
                    (uint32_t)((wm * 32 + mi * 16 + (lane & 15)) * GPAD + kc + (lane >> 4) * 8) * 2u;
                uint32_t ahf[4];
                ldsm_x4(ahf, sAh + aoff);
#pragma unroll
                for (int ni = 0; ni < 8; ni++)
                    mma_fp16(c[mi][ni], ahf, bhf[ni]);
            }
        }
    }

    // epilogue: row-scale by sout, then fp16 store
#pragma unroll
    for (int mi = 0; mi < 2; mi++) {
        const int r0 = bm * 64 + wm * 32 + mi * 16 + (lane >> 2);
        const float s0 = (r0 < M) ? g_sout[r0] : 0.f;
        const float s1 = (r0 + 8 < M) ? g_sout[r0 + 8] : 0.f;
#pragma unroll
        for (int ni = 0; ni < 8; ni++) {
            const int col = wn * 64 + ni * 8 + 2 * (lane & 3);
            if (r0 < M)
                *(__half2*)(g_Hh + (size_t)r0 * H1 + col) =
                    __floats2half2_rn(c[mi][ni][0] * s0, c[mi][ni][1] * s0);
            if (r0 + 8 < M)
                *(__half2*)(g_Hh + (size_t)(r0 + 8) * H1 + col) =
                    __floats2half2_rn(c[mi][ni][2] * s1, c[mi][ni][3] * s1);
        }
    }
}

// ---------------- GEMM2: fp16 A (g_Xh), BM=128 x BN=128, BK=32 ---------------
#define G2_AH_OFF  0u           // 2 x 10240
#define G2_AH_STR  10240u
#define G2_BH_OFF  20480u       // 2 x 10240
#define G2_BSTAGE  10240u
#define G2_SMEM    40960

__global__ __launch_bounds__(256, 2)
void gemm2_fp16(const __half* __restrict__ Bh, int M) {
    extern __shared__ __align__(16) char smem[];
    const uint32_t sm = smem_u32(smem);

    const int tid = threadIdx.x;
    const int lane = tid & 31, warp = tid >> 5;
    const int wm = warp >> 2, wn = warp & 3;
    const int bm = blockIdx.x;

    float c[4][4][4];
#pragma unroll
    for (int mi = 0; mi < 4; mi++)
#pragma unroll
        for (int ni = 0; ni < 4; ni++)
#pragma unroll
            for (int q = 0; q < 4; q++) c[mi][ni][q] = 0.f;

    const int kiters = H1 / 32;   // 8

    auto issue_stage = [&](int kt, int stage) {
        const int k0 = kt * 32;
        const uint32_t ah = sm + G2_AH_OFF + (uint32_t)stage * G2_AH_STR;
#pragma unroll
        for (int j = 0; j < 2; j++) {
            const int cchunk = j * 256 + tid;         // 0..511
            const int row = cchunk >> 2, cc = cchunk & 3;
            const int grow = bm * 128 + row;
            cp_async16(ah + (uint32_t)(row * (GPAD * 2) + cc * 16),
                       g_Xh + (size_t)grow * H1 + k0 + cc * 8,
                       (grow < M) ? 16 : 0);
        }
        const uint32_t bh = sm + G2_BH_OFF + (uint32_t)stage * G2_BSTAGE;
#pragma unroll
        for (int j = 0; j < 2; j++) {
            const int cchunk = j * 256 + tid;
            const int row = cchunk >> 2, cc = (cchunk & 3) * 8;
            cp_async16(bh + (uint32_t)(row * (GPAD * 2) + cc * 2),
                       Bh + (size_t)row * H1 + k0 + cc, 16);
        }
        cp_commit();
    };

    issue_stage(0, 0);

    for (int kt = 0; kt < kiters; kt++) {
        const int stage = kt & 1;
        cp_wait_all();
        __syncthreads();

        if (kt + 1 < kiters) issue_stage(kt + 1, stage ^ 1);

        const uint32_t sAh = sm + G2_AH_OFF + (uint32_t)stage * G2_AH_STR;
        const uint32_t sBh = sm + G2_BH_OFF + (uint32_t)stage * G2_BSTAGE;
#pragma unroll
        for (int kk = 0; kk < 2; kk++) {
            const int kc = kk * 16;
            const int l16 = lane & 15;
            uint32_t bhf[4][2];
#pragma unroll
            for (int ni = 0; ni < 4; ni++) {
                const uint32_t boff =
                    (uint32_t)((wn * 32 + ni * 8 + (l16 & 7)) * GPAD + kc + (l16 >> 3) * 8) * 2u;
                ldsm_x2(bhf[ni], sBh + boff);
            }
#pragma unroll
            for (int mi = 0; mi < 4; mi++) {
                const uint32_t aoff =
                    (uint32_t)((wm * 64 + mi * 16 + (lane & 15)) * GPAD + kc + (lane >> 4) * 8) * 2u;
                uint32_t ahf[4];
                ldsm_x4(ahf, sAh + aoff);
#pragma unroll
                for (int ni = 0; ni < 4; ni++)
                    mma_fp16(c[mi][ni], ahf, bhf[ni]);
            }
        }
    }

#pragma unroll
    for (int mi = 0; mi < 4; mi++) {
        const int r0 = bm * 128 + wm * 64 + mi * 16 + (lane >> 2);
#pragma unroll
        for (int ni = 0; ni < 4; ni++) {
            const int col = wn * 32 + ni * 8 + 2 * (lane & 3);
            if (r0 < M)
                *(__half2*)(g_Hh + (size_t)r0 * H2 + col) =
                    __floats2half2_rn(c[mi][ni][0], c[mi][ni][1]);
            if (r0 + 8 < M)
                *(__half2*)(g_Hh + (size_t)(r0 + 8) * H2 + col) =
                    __floats2half2_rn(c[mi][ni][2], c[mi][ni][3]);
        }
    }
}

// ---------------- head GEMM: out = relu(Xh2 @ Wo1 + bo1) @ Wo2 + bo2 ---------
#define HG_AH_OFF  0u           // 2 x 10240
#define HG_AH_STR  10240u
#define HG_BH_OFF  20480u       // 2 x 5120 (64 x GPAD)
#define HG_BSTAGE  5120u
#define HG_RED_OFF 30720u       // 128 x 4 floats
#define HG_SMEM    32768

__global__ __launch_bounds__(256, 2)
void head_gemm(const __half* __restrict__ Bh, const float* __restrict__ bo1,
               const float* __restrict__ Wo2, const float* __restrict__ bo2,
               float* __restrict__ out, int M) {
    extern __shared__ __align__(16) char smem[];
    const uint32_t sm = smem_u32(smem);

    const int tid = threadIdx.x;
    const int lane = tid & 31, warp = tid >> 5;
    const int wm = warp >> 2, wn = warp & 3;
    const int bm = blockIdx.x;

    float c[4][2][4];
#pragma unroll
    for (int mi = 0; mi < 4; mi++)
#pragma unroll
        for (int ni = 0; ni < 2; ni++)
#pragma unroll
            for (int q = 0; q < 4; q++) c[mi][ni][q] = 0.f;

    const int kiters = H2 / 32;   // 4

    auto issue_stage = [&](int kt, int stage) {
        const int k0 = kt * 32;
        const uint32_t ah = sm + HG_AH_OFF + (uint32_t)stage * HG_AH_STR;
#pragma unroll
        for (int j = 0; j < 2; j++) {
            const int cchunk = j * 256 + tid;         // 0..511
            const int row = cchunk >> 2, cc = cchunk & 3;
            const int grow = bm * 128 + row;
            cp_async16(ah + (uint32_t)(row * (GPAD * 2) + cc * 16),
                       g_Xh2 + (size_t)grow * H2 + k0 + cc * 8,
                       (grow < M) ? 16 : 0);
        }
        const uint32_t bh = sm + HG_BH_OFF + (uint32_t)stage * HG_BSTAGE;
        if (tid < 256) {                              // 64 rows x 4 chunks
            const int row = tid >> 2, cc = (tid & 3) * 8;
            cp_async16(bh + (uint32_t)(row * (GPAD * 2) + cc * 2),
                       Bh + (size_t)row * H2 + k0 + cc, 16);
        }
        cp_commit();
    };

    issue_stage(0, 0);

    for (int kt = 0; kt < kiters; kt++) {
        const int stage = kt & 1;
        cp_wait_all();
        __syncthreads();

        if (kt + 1 < kiters) issue_stage(kt + 1, stage ^ 1);

        const uint32_t sAh = sm + HG_AH_OFF + (uint32_t)stage * HG_AH_STR;
        const uint32_t sBh = sm + HG_BH_OFF + (uint32_t)stage * HG_BSTAGE;
#pragma unroll
        for (int kk = 0; kk < 2; kk++) {
            const int kc = kk * 16;
            const int l16 = lane & 15;
            uint32_t bhf[2][2];
#pragma unroll
            for (int ni = 0; ni < 2; ni++) {
                const uint32_t boff =
                    (uint32_t)((wn * 16 + ni * 8 + (l16 & 7)) * GPAD + kc + (l16 >> 3) * 8) * 2u;
                ldsm_x2(bhf[ni], sBh + boff);
            }
#pragma unroll
            for (int mi = 0; mi < 4; mi++) {
                const uint32_t aoff =
                    (uint32_t)((wm * 64 + mi * 16 + (lane & 15)) * GPAD + kc + (lane >> 4) * 8) * 2u;
                uint32_t ahf[4];
                ldsm_x4(ahf, sAh + aoff);
#pragma unroll
                for (int ni = 0; ni < 2; ni++)
                    mma_fp16(c[mi][ni], ahf, bhf[ni]);
            }
        }
    }

    // ---- fused epilogue: relu(+bo1) dot Wo2, reduce to one float per row ----
    float* sred = (float*)(smem + HG_RED_OFF);    // [128][4]
    __syncthreads();
#pragma unroll
    for (int mi = 0; mi < 4; mi++) {
        float pA = 0.f, pB = 0.f;
#pragma unroll
        for (int ni = 0; ni < 2; ni++) {
            const int cl = wn * 16 + ni * 8 + 2 * (lane & 3);
            const float b0 = __ldg(bo1 + cl), b1 = __ldg(bo1 + cl + 1);
            const float w0 = __ldg(Wo2 + cl), w1 = __ldg(Wo2 + cl + 1);
            pA += fmaxf(c[mi][ni][0] + b0, 0.f) * w0 + fmaxf(c[mi][ni][1] + b1, 0.f) * w1;
            pB += fmaxf(c[mi][ni][2] + b0, 0.f) * w0 + fmaxf(c[mi][ni][3] + b1, 0.f) * w1;
        }
        pA += __shfl_xor_sync(0xffffffffu, pA, 1);
        pA += __shfl_xor_sync(0xffffffffu, pA, 2);
        pB += __shfl_xor_sync(0xffffffffu, pB, 1);
        pB += __shfl_xor_sync(0xffffffffu, pB, 2);
        if ((lane & 3) == 0) {
            const int wr = wm * 64 + mi * 16 + (lane >> 2);
            sred[wr * 4 + wn] = pA;
            sred[(wr + 8) * 4 + wn] = pB;
        }
    }
    __syncthreads();
    if (tid < 128) {
        const int row = bm * 128 + tid;
        if (row < M)
            out[row] = sred[tid * 4] + sred[tid * 4 + 1] + sred[tid * 4 + 2] +
                       sred[tid * 4 + 3] + __ldg(bo2);
    }
}

// ---------------- warp-per-node aggregation (fp16 gather, LDG.128) ----------
// One warp per node. Index prefetch: ONE lane-parallel LDG per 32 edges,
// distributed via shfl — inner loop is a single LDG.128 + cvt/add per edge.
// H rows are pre-scaled by sout (GEMM1 epilogue), so no per-edge weight.
template <int COLS, bool L1MODE>
__global__ __launch_bounds__(256)
void aggregate_warp(const float* __restrict__ bias) {
    const int warp = threadIdx.x >> 5, lane = threadIdx.x & 31;
    const int v = blockIdx.x * 8 + warp;
    if (v >= N_NODES) return;
    constexpr int EPT = COLS / 32;        // 8 (agg1) or 4 (agg2)

    float acc[EPT];
#pragma unroll
    for (int i = 0; i < EPT; i++) acc[i] = 0.f;

    const __half* __restrict__ Hm = g_Hh;

    auto add_row = [&](int s) {
        const __half* r = Hm + (size_t)s * COLS + lane * EPT;
        if constexpr (EPT == 8) {
            const uint4 d = *(const uint4*)r;
            const float2 f0 = __half22float2(*(const __half2*)&d.x);
            const float2 f1 = __half22float2(*(const __half2*)&d.y);
            const float2 f2 = __half22float2(*(const __half2*)&d.z);
            const float2 f3 = __half22float2(*(const __half2*)&d.w);
            acc[0] += f0.x; acc[1] += f0.y; acc[2] += f1.x; acc[3] += f1.y;
            acc[4] += f2.x; acc[5] += f2.y; acc[6] += f3.x; acc[7] += f3.y;
        } else {
            const uint2 d = *(const uint2*)r;
            const float2 f0 = __half22float2(*(const __half2*)&d.x);
            const float2 f1 = __half22float2(*(const __half2*)&d.y);
            acc[0] += f0.x; acc[1] += f0.y; acc[2] += f1.x; acc[3] += f1.y;
        }
    };

    const int beg = g_rowptr[v];
    const int end = g_rowptr[v + 1];
    for (int base = beg; base < end; base += 32) {
        const int cnt = min(32, end - base);
        int idx = 0;
        if (lane < cnt) idx = g_colsrc[base + lane];
        int j = 0;
        for (; j + 4 <= cnt; j += 4) {
            const int s0 = __shfl_sync(0xffffffffu, idx, j);
            const int s1 = __shfl_sync(0xffffffffu, idx, j + 1);
            const int s2 = __shfl_sync(0xffffffffu, idx, j + 2);
            const int s3 = __shfl_sync(0xffffffffu, idx, j + 3);
            add_row(s0); add_row(s1); add_row(s2); add_row(s3);
        }
        for (; j < cnt; j++) add_row(__shfl_sync(0xffffffffu, idx, j));
    }

    const float si = g_sin[v];
    float o[EPT];
#pragma unroll
    for (int i = 0; i < EPT; i += 4) {
        const float4 b = *(const float4*)(bias + lane * EPT + i);
        o[i]     = fmaf(acc[i],     si, b.x);
        o[i + 1] = fmaf(acc[i + 1], si, b.y);
        o[i + 2] = fmaf(acc[i + 2], si, b.z);
        o[i + 3] = fmaf(acc[i + 3], si, b.w);
    }

    __half2 h[EPT / 2];
    if constexpr (L1MODE) {
        const float so = g_sout[v];
#pragma unroll
        for (int i = 0; i < EPT; i++) o[i] = fmaxf(o[i], 0.f) * so;
#pragma unroll
        for (int i = 0; i < EPT / 2; i++) h[i] = __floats2half2_rn(o[2 * i], o[2 * i + 1]);
        if constexpr (EPT == 8)
            *(uint4*)(g_Xh + (size_t)v * COLS + lane * EPT) = *(uint4*)h;
        else
            *(uint2*)(g_Xh + (size_t)v * COLS + lane * EPT) = *(uint2*)h;
    } else {
#pragma unroll
        for (int i = 0; i < EPT / 2; i++) h[i] = __floats2half2_rn(o[2 * i], o[2 * i + 1]);
        if constexpr (EPT == 8)
            *(uint4*)(g_Xh2 + (size_t)v * COLS + lane * EPT) = *(uint4*)h;
        else
            *(uint2*)(g_Xh2 + (size_t)v * COLS + lane * EPT) = *(uint2*)h;
    }
}

// ---------------- launch -----------------------------------------------------
extern "C" void kernel_launch(void* const* d_in, const int* in_sizes, int n_in,
                              void* d_out, int out_size) {
    const float* feat = (const float*)d_in[0];   // [N, 64, 8] -> [N, 512]
    const int*   src  = (const int*)d_in[1];
    const int*   dst  = (const int*)d_in[2];
    const float* W1   = (const float*)d_in[3];
    const float* b1   = (const float*)d_in[4];
    const float* W2   = (const float*)d_in[5];
    const float* b2   = (const float*)d_in[6];
    const float* Wo1  = (const float*)d_in[7];
    const float* bo1  = (const float*)d_in[8];
    const float* Wo2  = (const float*)d_in[9];
    const float* bo2  = (const float*)d_in[10];
    float* out = (float*)d_out;

    const int nb_nodes = (N_NODES + 255) / 256;
    const int mt64  = (N_NODES + 63) / 64;    // 1563
    const int mt128 = (N_NODES + 127) / 128;  // 782
    const int agrid = (N_NODES + 7) / 8;      // 12500

    __half *t1, *t2, *to1;
    cudaGetSymbolAddress((void**)&t1, g_W1t);
    cudaGetSymbolAddress((void**)&t2, g_W2t);
    cudaGetSymbolAddress((void**)&to1, g_Wo1t);

    cudaFuncSetAttribute(gemm1_wide,
                         cudaFuncAttributeMaxDynamicSharedMemorySize, G1_SMEM);
    cudaFuncSetAttribute(gemm2_fp16,
                         cudaFuncAttributeMaxDynamicSharedMemorySize, G2_SMEM);
    cudaFuncSetAttribute(head_gemm,
                         cudaFuncAttributeMaxDynamicSharedMemorySize, HG_SMEM);

    // one-time side stream + fork/join events (reused across calls/capture)
    static cudaStream_t s_pre = nullptr;
    static cudaEvent_t ev_fork = nullptr, ev_scales = nullptr, ev_pre = nullptr;
    if (s_pre == nullptr) {
        cudaStreamCreateWithFlags(&s_pre, cudaStreamNonBlocking);
        cudaEventCreateWithFlags(&ev_fork, cudaEventDisableTiming);
        cudaEventCreateWithFlags(&ev_scales, cudaEventDisableTiming);
        cudaEventCreateWithFlags(&ev_pre, cudaEventDisableTiming);
    }

    // ---- fork: graph preprocessing on side stream ----
    cudaEventRecord(ev_fork, 0);
    cudaStreamWaitEvent(s_pre, ev_fork, 0);
    zero_deg_kernel<<<nb_nodes, 256, 0, s_pre>>>();
    degree_kernel<<<1024, 256, 0, s_pre>>>((const int4*)src, (const int4*)dst);
    scales_kernel<<<nb_nodes, 256, 0, s_pre>>>();
    cudaEventRecord(ev_scales, s_pre);
    scan_block_kernel<<<SCAN_BLOCKS, 1024, 0, s_pre>>>();
    scan_part_kernel<<<1, 128, 0, s_pre>>>();
    scan_finish_kernel<<<nb_nodes, 256, 0, s_pre>>>();
    csr_fill_kernel<<<1024, 256, 0, s_pre>>>((const int4*)src, (const int4*)dst);
    cudaEventRecord(ev_pre, s_pre);

    // ---- main stream: weight transpose; GEMM1 waits only on scales ----
    wconv_kernel<<<(K1 * H1 + 255) / 256, 256>>>(W1, t1, K1, H1);
    wconv_kernel<<<(H1 * H2 + 255) / 256, 256>>>(W2, t2, H1, H2);
    wconv_kernel<<<(H2 * ENDD + 255) / 256, 256>>>(Wo1, to1, H2, ENDD);
    cudaStreamWaitEvent(0, ev_scales, 0);
    gemm1_wide<<<mt64, 256, G1_SMEM>>>(feat, t1, N_NODES);

    // ---- join: aggregation needs CSR + GEMM1 ----
    cudaStreamWaitEvent(0, ev_pre, 0);
    aggregate_warp<H1, true><<<agrid, 256>>>(b1);

    // layer 2 (fp16 A directly from g_Xh; agg2 -> fp16 g_Xh2)
    gemm2_fp16<<<mt128, 256, G2_SMEM>>>(t2, N_NODES);
    aggregate_warp<H2, false><<<agrid, 256>>>(b2);

    // fused head GEMM (relu + Wo2 dot in epilogue)
    head_gemm<<<mt128, 256, HG_SMEM>>>(to1, bo1, Wo2, bo2, out, N_NODES);
}